// round 1
// baseline (speedup 1.0000x reference)
#include <cuda_runtime.h>

#define BB 2
#define SS 2048
#define DM 1024
#define NH 16
#define DK 64
#define MROWS (BB * SS)     // 4096
#define HEADS (BB * NH)     // 32

// Scratch (device globals per harness rules; no allocations anywhere)
__device__ float g_q[HEADS * SS * DK];          // [B,H,S,dk]
__device__ float g_k[HEADS * SS * DK];
__device__ float g_v[HEADS * SS * DK];
__device__ float g_ctx[MROWS * DM];             // [B,S,D] (heads re-merged)
__device__ float g_attn_fallback[134217728];    // used only if harness out lacks attention

// ---------------------------------------------------------------------------
// QKV projection: C[4096,1024] = X @ W + b, epilogue writes head-split [B,H,S,dk]
// 128x128 tile, BK=8, 256 threads, 8x8 microtile
// ---------------------------------------------------------------------------
template <int DST>
__global__ void proj_kernel(const float* __restrict__ X,
                            const float* __restrict__ W,
                            const float* __restrict__ bias) {
    constexpr int BM = 128, BN = 128, BK = 8;
    __shared__ float As[BK][BM];
    __shared__ float Bs[BK][BN];

    const int tid  = threadIdx.x;
    const int trow = tid >> 4;        // 0..15
    const int tcol = tid & 15;        // 0..15
    const int m0 = blockIdx.y * BM;
    const int n0 = blockIdx.x * BN;

    const int aRow = tid >> 1;        // 0..127
    const int aCol = (tid & 1) * 4;   // 0 or 4
    const int bRow = tid >> 5;        // 0..7
    const int bCol = (tid & 31) * 4;  // 0..124

    float acc[8][8];
#pragma unroll
    for (int i = 0; i < 8; i++)
#pragma unroll
        for (int j = 0; j < 8; j++) acc[i][j] = 0.f;

    for (int k0 = 0; k0 < DM; k0 += BK) {
        float4 a4 = *(const float4*)(X + (m0 + aRow) * DM + k0 + aCol);
        As[aCol + 0][aRow] = a4.x;
        As[aCol + 1][aRow] = a4.y;
        As[aCol + 2][aRow] = a4.z;
        As[aCol + 3][aRow] = a4.w;
        float4 b4 = *(const float4*)(W + (k0 + bRow) * DM + n0 + bCol);
        *(float4*)(&Bs[bRow][bCol]) = b4;
        __syncthreads();
#pragma unroll
        for (int kk = 0; kk < BK; kk++) {
            float4 a0 = *(const float4*)(&As[kk][trow * 8]);
            float4 a1 = *(const float4*)(&As[kk][trow * 8 + 4]);
            float4 b0 = *(const float4*)(&Bs[kk][tcol * 8]);
            float4 b1 = *(const float4*)(&Bs[kk][tcol * 8 + 4]);
            float ra[8] = {a0.x, a0.y, a0.z, a0.w, a1.x, a1.y, a1.z, a1.w};
            float rb[8] = {b0.x, b0.y, b0.z, b0.w, b1.x, b1.y, b1.z, b1.w};
#pragma unroll
            for (int i = 0; i < 8; i++)
#pragma unroll
                for (int j = 0; j < 8; j++) acc[i][j] += ra[i] * rb[j];
        }
        __syncthreads();
    }

    float* out = (DST == 0) ? g_q : (DST == 1) ? g_k : g_v;
#pragma unroll
    for (int i = 0; i < 8; i++) {
        const int m = m0 + trow * 8 + i;
        const int b = m >> 11;        // /2048
        const int s = m & 2047;
#pragma unroll
        for (int j = 0; j < 8; j++) {
            const int n = n0 + tcol * 8 + j;
            const int h = n >> 6;     // /64
            const int d = n & 63;
            out[((b * NH + h) * SS + s) * DK + d] = acc[i][j] + bias[n];
        }
    }
}

// ---------------------------------------------------------------------------
// Scores: per (b,h): attn = (q @ k^T) * 0.125   (unnormalized; softmax after)
// ---------------------------------------------------------------------------
__global__ void scores_kernel(float* __restrict__ attn_param) {
    constexpr int BM = 128, BN = 128, BK = 8;
    __shared__ float As[BK][BM];
    __shared__ float Bs[BK][BN];

    float* attn = attn_param ? attn_param : g_attn_fallback;
    const int bh = blockIdx.z;
    const float* A = g_q + bh * SS * DK;
    const float* Kp = g_k + bh * SS * DK;

    const int tid  = threadIdx.x;
    const int trow = tid >> 4, tcol = tid & 15;
    const int m0 = blockIdx.y * BM;
    const int n0 = blockIdx.x * BN;

    const int aRow = tid >> 1;
    const int aCol = (tid & 1) * 4;
    const int bN = tid & 127;         // n index 0..127
    const int bK = (tid >> 7) * 4;    // 0 or 4

    float acc[8][8];
#pragma unroll
    for (int i = 0; i < 8; i++)
#pragma unroll
        for (int j = 0; j < 8; j++) acc[i][j] = 0.f;

    for (int k0 = 0; k0 < DK; k0 += BK) {
        float4 a4 = *(const float4*)(A + (m0 + aRow) * DK + k0 + aCol);
        As[aCol + 0][aRow] = a4.x;
        As[aCol + 1][aRow] = a4.y;
        As[aCol + 2][aRow] = a4.z;
        As[aCol + 3][aRow] = a4.w;
        float4 b4 = *(const float4*)(Kp + (n0 + bN) * DK + k0 + bK);
        Bs[bK + 0][bN] = b4.x;
        Bs[bK + 1][bN] = b4.y;
        Bs[bK + 2][bN] = b4.z;
        Bs[bK + 3][bN] = b4.w;
        __syncthreads();
#pragma unroll
        for (int kk = 0; kk < BK; kk++) {
            float4 a0 = *(const float4*)(&As[kk][trow * 8]);
            float4 a1 = *(const float4*)(&As[kk][trow * 8 + 4]);
            float4 b0 = *(const float4*)(&Bs[kk][tcol * 8]);
            float4 b1 = *(const float4*)(&Bs[kk][tcol * 8 + 4]);
            float ra[8] = {a0.x, a0.y, a0.z, a0.w, a1.x, a1.y, a1.z, a1.w};
            float rb[8] = {b0.x, b0.y, b0.z, b0.w, b1.x, b1.y, b1.z, b1.w};
#pragma unroll
            for (int i = 0; i < 8; i++)
#pragma unroll
                for (int j = 0; j < 8; j++) acc[i][j] += ra[i] * rb[j];
        }
        __syncthreads();
    }

    const long base = (long)bh * SS * SS;
#pragma unroll
    for (int i = 0; i < 8; i++) {
        const long m = m0 + trow * 8 + i;
#pragma unroll
        for (int j = 0; j < 8; j++) {
            const int n = n0 + tcol * 8 + j;
            attn[base + m * SS + n] = acc[i][j] * 0.125f;
        }
    }
}

// ---------------------------------------------------------------------------
// Row softmax in place on the attention buffer. One block per row of 2048.
// ---------------------------------------------------------------------------
__global__ void softmax_kernel(float* __restrict__ attn_param) {
    float* attn = attn_param ? attn_param : g_attn_fallback;
    __shared__ float red[256];
    const long row = blockIdx.x;
    float* p = attn + row * (long)SS;
    const int t = threadIdx.x;

    float vals[8];
    float mx = -1e30f;
#pragma unroll
    for (int i = 0; i < 8; i++) {
        vals[i] = p[t + i * 256];
        mx = fmaxf(mx, vals[i]);
    }
    red[t] = mx;
    __syncthreads();
    for (int s = 128; s > 0; s >>= 1) {
        if (t < s) red[t] = fmaxf(red[t], red[t + s]);
        __syncthreads();
    }
    const float rowmax = red[0];
    __syncthreads();

    float sum = 0.f;
#pragma unroll
    for (int i = 0; i < 8; i++) {
        vals[i] = __expf(vals[i] - rowmax);
        sum += vals[i];
    }
    red[t] = sum;
    __syncthreads();
    for (int s = 128; s > 0; s >>= 1) {
        if (t < s) red[t] += red[t + s];
        __syncthreads();
    }
    const float inv = 1.0f / red[0];
#pragma unroll
    for (int i = 0; i < 8; i++) p[t + i * 256] = vals[i] * inv;
}

// ---------------------------------------------------------------------------
// Context: per (b,h): ctx = attn @ v ; epilogue re-merges heads into [B,S,D]
// BM=128, BN=64 (full d_k), BK=8, 256 threads, 8x4 microtile
// ---------------------------------------------------------------------------
__global__ void ctx_kernel(const float* __restrict__ attn_param) {
    constexpr int BM = 128, BN = 64, BK = 8;
    __shared__ float As[BK][BM];
    __shared__ float Bs[BK][BN];

    const float* attn = attn_param ? attn_param : g_attn_fallback;
    const int bh = blockIdx.z;
    const int b = bh / NH, h = bh % NH;
    const float* A = attn + (long)bh * SS * SS;
    const float* V = g_v + bh * SS * DK;

    const int tid  = threadIdx.x;
    const int trow = tid >> 4;        // 0..15 -> 8 rows each
    const int tcol = tid & 15;        // 0..15 -> 4 cols each
    const int m0 = blockIdx.y * BM;

    const int aRow = tid >> 1;
    const int aCol = (tid & 1) * 4;
    const int bRow = (tid >> 4) & 7;  // 0..7 (tid<128 used)
    const int bCol = (tid & 15) * 4;

    float acc[8][4];
#pragma unroll
    for (int i = 0; i < 8; i++)
#pragma unroll
        for (int j = 0; j < 4; j++) acc[i][j] = 0.f;

    for (int k0 = 0; k0 < SS; k0 += BK) {
        float4 a4 = *(const float4*)(A + (long)(m0 + aRow) * SS + k0 + aCol);
        As[aCol + 0][aRow] = a4.x;
        As[aCol + 1][aRow] = a4.y;
        As[aCol + 2][aRow] = a4.z;
        As[aCol + 3][aRow] = a4.w;
        if (tid < 128) {
            float4 b4 = *(const float4*)(V + (k0 + bRow) * DK + bCol);
            *(float4*)(&Bs[bRow][bCol]) = b4;
        }
        __syncthreads();
#pragma unroll
        for (int kk = 0; kk < BK; kk++) {
            float4 a0 = *(const float4*)(&As[kk][trow * 8]);
            float4 a1 = *(const float4*)(&As[kk][trow * 8 + 4]);
            float4 b0 = *(const float4*)(&Bs[kk][tcol * 4]);
            float ra[8] = {a0.x, a0.y, a0.z, a0.w, a1.x, a1.y, a1.z, a1.w};
            float rb[4] = {b0.x, b0.y, b0.z, b0.w};
#pragma unroll
            for (int i = 0; i < 8; i++)
#pragma unroll
                for (int j = 0; j < 4; j++) acc[i][j] += ra[i] * rb[j];
        }
        __syncthreads();
    }

#pragma unroll
    for (int i = 0; i < 8; i++) {
        const int s = m0 + trow * 8 + i;
#pragma unroll
        for (int j = 0; j < 4; j++) {
            const int d = tcol * 4 + j;
            g_ctx[(long)(b * SS + s) * DM + h * DK + d] = acc[i][j];
        }
    }
}

// ---------------------------------------------------------------------------
// Output projection: out[4096,1024] = ctx @ Wfc + bfc (plain epilogue)
// ---------------------------------------------------------------------------
__global__ void out_kernel(const float* __restrict__ W,
                           const float* __restrict__ bias,
                           float* __restrict__ out) {
    constexpr int BM = 128, BN = 128, BK = 8;
    __shared__ float As[BK][BM];
    __shared__ float Bs[BK][BN];

    const int tid  = threadIdx.x;
    const int trow = tid >> 4, tcol = tid & 15;
    const int m0 = blockIdx.y * BM;
    const int n0 = blockIdx.x * BN;

    const int aRow = tid >> 1;
    const int aCol = (tid & 1) * 4;
    const int bRow = tid >> 5;
    const int bCol = (tid & 31) * 4;

    float acc[8][8];
#pragma unroll
    for (int i = 0; i < 8; i++)
#pragma unroll
        for (int j = 0; j < 8; j++) acc[i][j] = 0.f;

    for (int k0 = 0; k0 < DM; k0 += BK) {
        float4 a4 = *(const float4*)(g_ctx + (m0 + aRow) * DM + k0 + aCol);
        As[aCol + 0][aRow] = a4.x;
        As[aCol + 1][aRow] = a4.y;
        As[aCol + 2][aRow] = a4.z;
        As[aCol + 3][aRow] = a4.w;
        float4 b4 = *(const float4*)(W + (k0 + bRow) * DM + n0 + bCol);
        *(float4*)(&Bs[bRow][bCol]) = b4;
        __syncthreads();
#pragma unroll
        for (int kk = 0; kk < BK; kk++) {
            float4 a0 = *(const float4*)(&As[kk][trow * 8]);
            float4 a1 = *(const float4*)(&As[kk][trow * 8 + 4]);
            float4 b0 = *(const float4*)(&Bs[kk][tcol * 8]);
            float4 b1 = *(const float4*)(&Bs[kk][tcol * 8 + 4]);
            float ra[8] = {a0.x, a0.y, a0.z, a0.w, a1.x, a1.y, a1.z, a1.w};
            float rb[8] = {b0.x, b0.y, b0.z, b0.w, b1.x, b1.y, b1.z, b1.w};
#pragma unroll
            for (int i = 0; i < 8; i++)
#pragma unroll
                for (int j = 0; j < 8; j++) acc[i][j] += ra[i] * rb[j];
        }
        __syncthreads();
    }

#pragma unroll
    for (int i = 0; i < 8; i++) {
        const int m = m0 + trow * 8 + i;
#pragma unroll
        for (int j = 0; j < 8; j++) {
            const int n = n0 + tcol * 8 + j;
            out[m * DM + n] = acc[i][j] + bias[n];
        }
    }
}

extern "C" void kernel_launch(void* const* d_in, const int* in_sizes, int n_in,
                              void* d_out, int out_size) {
    const float* Q   = (const float*)d_in[0];
    const float* K   = (const float*)d_in[1];
    const float* V   = (const float*)d_in[2];
    const float* Wq  = (const float*)d_in[3];
    const float* bq  = (const float*)d_in[4];
    const float* Wk  = (const float*)d_in[5];
    const float* bk  = (const float*)d_in[6];
    const float* Wv  = (const float*)d_in[7];
    const float* bv  = (const float*)d_in[8];
    const float* Wfc = (const float*)d_in[9];
    const float* bfc = (const float*)d_in[10];
    float* out_f = (float*)d_out;

    // The reference returns (output, attention); assume flattened concatenation:
    // output (4,194,304 floats) first, attention (134,217,728 floats) last.
    const long ATTN_ELEMS = (long)HEADS * SS * SS;
    float* attn_param = nullptr;  // nullptr -> kernels use g_attn_fallback
    if ((long)out_size >= ATTN_ELEMS) {
        attn_param = out_f + ((long)out_size - ATTN_ELEMS);
    }

    dim3 blk(256);
    proj_kernel<0><<<dim3(DM / 128, MROWS / 128), blk>>>(Q, Wq, bq);
    proj_kernel<1><<<dim3(DM / 128, MROWS / 128), blk>>>(K, Wk, bk);
    proj_kernel<2><<<dim3(DM / 128, MROWS / 128), blk>>>(V, Wv, bv);
    scores_kernel<<<dim3(SS / 128, SS / 128, HEADS), blk>>>(attn_param);
    softmax_kernel<<<dim3(HEADS * SS), blk>>>(attn_param);
    ctx_kernel<<<dim3(1, SS / 128, HEADS), blk>>>(attn_param);
    out_kernel<<<dim3(DM / 128, MROWS / 128), blk>>>(Wfc, bfc, out_f);
}

// round 2
// speedup vs baseline: 1.0980x; 1.0980x over previous
#include <cuda_runtime.h>
#include <cstdint>

#define BB 2
#define SS 2048
#define DM 1024
#define NH 16
#define DK 64
#define MROWS (BB*SS)       // 4096
#define HEADS (BB*NH)       // 32

// Device-global scratch (no allocations anywhere)
__device__ float g_q[HEADS*SS*DK];
__device__ float g_k[HEADS*SS*DK];
__device__ float g_v[HEADS*SS*DK];
__device__ float g_ctx[MROWS*DM];
__device__ float g_part[HEADS*SS*16];   // per-row, per-nblock partial sums
__device__ float g_inv[HEADS*SS];       // 1/rowsum
__device__ float g_attn_fb[(size_t)HEADS*SS*SS]; // fallback if attn not in d_out

__device__ __forceinline__ float tf32r(float x){
  unsigned u; asm("cvt.rna.tf32.f32 %0, %1;" : "=r"(u) : "f"(x));
  return __uint_as_float(u);
}

__device__ __forceinline__ void mma8(float c[4], const float a[4], const float b[2]){
  asm volatile(
    "mma.sync.aligned.m16n8k8.row.col.f32.tf32.tf32.f32 "
    "{%0,%1,%2,%3}, {%4,%5,%6,%7}, {%8,%9}, {%0,%1,%2,%3};\n"
    : "+f"(c[0]), "+f"(c[1]), "+f"(c[2]), "+f"(c[3])
    : "r"(__float_as_uint(a[0])), "r"(__float_as_uint(a[1])),
      "r"(__float_as_uint(a[2])), "r"(__float_as_uint(a[3])),
      "r"(__float_as_uint(b[0])), "r"(__float_as_uint(b[1])));
}

// ---------------------------------------------------------------------------
// Unified split-tf32 GEMM.
// A row-major [M,Ktot] (lda). B layout:
//   BLAY=0: B row-major [Ktot,N] (ldb)     -> C = A @ B
//   BLAY=1: B row-major [N,Ktot] (ldb)     -> C = A @ B^T
// EPI: 0=proj(head-split+bias), 1=scores(exp+rowsums), 2=ctx(normalize A on
// load + writeback, merge heads), 3=out(bias).
// BM=128 fixed, BK=16, 256 threads, warp tile WMxWN with WN=32 (NF=4).
// ---------------------------------------------------------------------------
template<int BN,int WARPS_M,int WARPS_N,int BLAY,int EPI>
__global__ void __launch_bounds__(256)
gemm_kernel(const float* __restrict__ Abase, int lda,
            const float* __restrict__ Bbase, int ldb,
            const float* __restrict__ bias,
            float* __restrict__ out,
            float* __restrict__ aux,
            float* __restrict__ Amut,
            int Ktot)
{
  constexpr int BM=128, BK=16;
  constexpr int WM=BM/WARPS_M, WN=BN/WARPS_N;
  constexpr int MF=WM/16, NF=WN/8;
  static_assert(NF==4, "NF must be 4");
  constexpr int BR = BLAY ? BN : BK;
  constexpr int BC = BLAY ? (BK+4) : (BN+8);
  constexpr int BV = BLAY ? 2 : (BN/64);   // float4s per thread for B stage

  __shared__ float sAh[BM][BK+4], sAl[BM][BK+4];
  __shared__ float sBh[BR][BC],   sBl[BR][BC];

  const int tid=threadIdx.x, lane=tid&31, wid=tid>>5;
  const int g=lane>>2, tg=lane&3;
  const int warp_m=wid/WARPS_N, warp_n=wid%WARPS_N;
  const int wm=warp_m*WM, wn=warp_n*WN;
  const int m0=blockIdx.y*BM, n0=blockIdx.x*BN, bh=blockIdx.z;

  const float* A=Abase; const float* Bp=Bbase; float* Aw=nullptr; float ainv=1.f;
  if (EPI==1){ A += (size_t)bh*SS*DK; Bp += (size_t)bh*SS*DK; }
  if (EPI==2){ A += (size_t)bh*SS*SS; Bp += (size_t)bh*SS*DK;
               Aw = Amut + (size_t)bh*SS*SS;
               ainv = aux[bh*SS + m0 + (tid>>1)]; }

  const int ar=tid>>1, ac=(tid&1)*8;
  int br, bc;
  if (BLAY)            { br=tid>>1;  bc=(tid&1)*8;  }
  else if (BN==128)    { br=tid>>4;  bc=(tid&15)*8; }
  else                 { br=tid>>4;  bc=(tid&15)*4; }

  float4 pa0=make_float4(0,0,0,0), pa1=make_float4(0,0,0,0);
  float4 pb0=make_float4(0,0,0,0), pb1=make_float4(0,0,0,0);

  auto ldg_tile = [&](int k0){
    const float* pA = A + (size_t)(m0+ar)*lda + k0 + ac;
    pa0 = *(const float4*)pA; pa1 = *(const float4*)(pA+4);
    if (EPI==2){
      pa0.x*=ainv; pa0.y*=ainv; pa0.z*=ainv; pa0.w*=ainv;
      pa1.x*=ainv; pa1.y*=ainv; pa1.z*=ainv; pa1.w*=ainv;
      float* w = Aw + (size_t)(m0+ar)*lda + k0 + ac;
      *(float4*)w = pa0; *(float4*)(w+4) = pa1;     // normalized attn writeback
    }
    if (BLAY){
      const float* pB = Bp + (size_t)(n0+br)*ldb + k0 + bc;
      pb0 = *(const float4*)pB; pb1 = *(const float4*)(pB+4);
    } else {
      const float* pB = Bp + (size_t)(k0+br)*ldb + n0 + bc;
      pb0 = *(const float4*)pB;
      if (BV==2) pb1 = *(const float4*)(pB+4);
    }
  };
  auto sts_tile = [&](){
    float v[8]={pa0.x,pa0.y,pa0.z,pa0.w,pa1.x,pa1.y,pa1.z,pa1.w};
#pragma unroll
    for (int i=0;i<8;i++){ float h=tf32r(v[i]); sAh[ar][ac+i]=h; sAl[ar][ac+i]=v[i]-h; }
    float u[8]={pb0.x,pb0.y,pb0.z,pb0.w,pb1.x,pb1.y,pb1.z,pb1.w};
#pragma unroll
    for (int i=0;i<4*BV;i++){ float h=tf32r(u[i]); sBh[br][bc+i]=h; sBl[br][bc+i]=u[i]-h; }
  };

  float acc[MF][NF][4];
#pragma unroll
  for (int mi=0;mi<MF;mi++)
#pragma unroll
    for (int ni=0;ni<NF;ni++)
#pragma unroll
      for (int q=0;q<4;q++) acc[mi][ni][q]=0.f;

  const int T = Ktot/BK;
  ldg_tile(0);
  for (int t=0;t<T;t++){
    sts_tile();
    __syncthreads();
    if (t+1<T) ldg_tile((t+1)*BK);
#pragma unroll
    for (int k8=0;k8<BK;k8+=8){
      float ah[MF][4], al[MF][4], bhr[NF][2], blr[NF][2];
#pragma unroll
      for (int mi=0;mi<MF;mi++){
        const int r = wm + mi*16 + g;
        ah[mi][0]=sAh[r  ][k8+tg];   al[mi][0]=sAl[r  ][k8+tg];
        ah[mi][1]=sAh[r+8][k8+tg];   al[mi][1]=sAl[r+8][k8+tg];
        ah[mi][2]=sAh[r  ][k8+tg+4]; al[mi][2]=sAl[r  ][k8+tg+4];
        ah[mi][3]=sAh[r+8][k8+tg+4]; al[mi][3]=sAl[r+8][k8+tg+4];
      }
#pragma unroll
      for (int ni=0;ni<NF;ni++){
        const int c = wn + ni*8 + g;
        if (BLAY){
          bhr[ni][0]=sBh[c][k8+tg]; bhr[ni][1]=sBh[c][k8+tg+4];
          blr[ni][0]=sBl[c][k8+tg]; blr[ni][1]=sBl[c][k8+tg+4];
        } else {
          bhr[ni][0]=sBh[k8+tg][c]; bhr[ni][1]=sBh[k8+tg+4][c];
          blr[ni][0]=sBl[k8+tg][c]; blr[ni][1]=sBl[k8+tg+4][c];
        }
      }
#pragma unroll
      for (int mi=0;mi<MF;mi++)
#pragma unroll
        for (int ni=0;ni<NF;ni++){
          mma8(acc[mi][ni], ah[mi], bhr[ni]);
          mma8(acc[mi][ni], al[mi], bhr[ni]);
          mma8(acc[mi][ni], ah[mi], blr[ni]);
        }
    }
    __syncthreads();
  }

  // ---------------- epilogues ----------------
  if constexpr (EPI==0){           // projection: bias + head split
#pragma unroll
    for (int mi=0;mi<MF;mi++)
#pragma unroll
      for (int half=0;half<2;half++){
        const int m = m0 + wm + mi*16 + g + half*8;
        const int b = m >> 11, s = m & (SS-1);
#pragma unroll
        for (int ni=0;ni<NF;ni++)
#pragma unroll
          for (int j=0;j<2;j++){
            const int n = n0 + wn + ni*8 + tg*2 + j;
            const int h = n >> 6, d = n & 63;
            out[(((size_t)b*NH + h)*SS + s)*DK + d] = acc[mi][ni][half*2+j] + bias[n];
          }
      }
  } else if constexpr (EPI==1){    // scores: exp + deterministic row partials
    __shared__ float rp[BM][WARPS_N];
    float* attn = out + (size_t)bh*SS*SS;
    float rs[MF][2];
#pragma unroll
    for (int mi=0;mi<MF;mi++){ rs[mi][0]=0.f; rs[mi][1]=0.f; }
#pragma unroll
    for (int mi=0;mi<MF;mi++)
#pragma unroll
      for (int half=0;half<2;half++){
        const size_t m = (size_t)(m0 + wm + mi*16 + g + half*8);
#pragma unroll
        for (int ni=0;ni<NF;ni++)
#pragma unroll
          for (int j=0;j<2;j++){
            const int n = n0 + wn + ni*8 + tg*2 + j;
            const float e = __expf(acc[mi][ni][half*2+j]*0.125f);
            attn[m*SS + n] = e;
            rs[mi][half] += e;
          }
      }
#pragma unroll
    for (int mi=0;mi<MF;mi++)
#pragma unroll
      for (int half=0;half<2;half++){
        float v = rs[mi][half];
        v += __shfl_xor_sync(0xffffffffu, v, 1);
        v += __shfl_xor_sync(0xffffffffu, v, 2);
        if (tg==0) rp[wm+mi*16+g+half*8][warp_n] = v;
      }
    __syncthreads();
    if (tid < BM){
      float s = 0.f;
#pragma unroll
      for (int w=0;w<WARPS_N;w++) s += rp[tid][w];
      aux[((size_t)bh*SS + m0 + tid)*16 + blockIdx.x] = s;
    }
  } else if constexpr (EPI==2){    // ctx: merge heads
    const int b = bh/NH, h = bh%NH;
#pragma unroll
    for (int mi=0;mi<MF;mi++)
#pragma unroll
      for (int half=0;half<2;half++){
        const int s = m0 + wm + mi*16 + g + half*8;
#pragma unroll
        for (int ni=0;ni<NF;ni++)
#pragma unroll
          for (int j=0;j<2;j++){
            const int d = n0 + wn + ni*8 + tg*2 + j;
            out[((size_t)(b*SS + s))*DM + h*DK + d] = acc[mi][ni][half*2+j];
          }
      }
  } else {                         // out projection: bias
#pragma unroll
    for (int mi=0;mi<MF;mi++)
#pragma unroll
      for (int half=0;half<2;half++){
        const int m = m0 + wm + mi*16 + g + half*8;
#pragma unroll
        for (int ni=0;ni<NF;ni++)
#pragma unroll
          for (int j=0;j<2;j++){
            const int n = n0 + wn + ni*8 + tg*2 + j;
            out[(size_t)m*DM + n] = acc[mi][ni][half*2+j] + bias[n];
          }
      }
  }
}

// Deterministic rowsum inversion: 16 partials per row, fixed order.
__global__ void rowsum_inv_kernel(const float* __restrict__ part, float* __restrict__ inv){
  const int r = blockIdx.x*blockDim.x + threadIdx.x;   // 0..65535
  const float* p = part + (size_t)r*16;
  float s = 0.f;
#pragma unroll
  for (int i=0;i<16;i++) s += p[i];
  inv[r] = 1.0f/s;
}

extern "C" void kernel_launch(void* const* d_in, const int* in_sizes, int n_in,
                              void* d_out, int out_size){
  const float* Q   = (const float*)d_in[0];
  const float* K   = (const float*)d_in[1];
  const float* V   = (const float*)d_in[2];
  const float* Wq  = (const float*)d_in[3];
  const float* bq  = (const float*)d_in[4];
  const float* Wk  = (const float*)d_in[5];
  const float* bk  = (const float*)d_in[6];
  const float* Wv  = (const float*)d_in[7];
  const float* bv  = (const float*)d_in[8];
  const float* Wfc = (const float*)d_in[9];
  const float* bfc = (const float*)d_in[10];
  float* out_f = (float*)d_out;

  float *gq,*gk,*gv,*gctx,*gpart,*ginv,*gafb;
  cudaGetSymbolAddress((void**)&gq,   g_q);
  cudaGetSymbolAddress((void**)&gk,   g_k);
  cudaGetSymbolAddress((void**)&gv,   g_v);
  cudaGetSymbolAddress((void**)&gctx, g_ctx);
  cudaGetSymbolAddress((void**)&gpart,g_part);
  cudaGetSymbolAddress((void**)&ginv, g_inv);
  cudaGetSymbolAddress((void**)&gafb, g_attn_fb);

  const size_t ATTN = (size_t)HEADS*SS*SS;
  float* attn = ((size_t)out_size >= ATTN) ? (out_f + ((size_t)out_size - ATTN)) : gafb;

  dim3 blk(256);
  // Q/K/V projections: C=A@W+b, head-split epilogue
  gemm_kernel<128,2,4,0,0><<<dim3(8,32),blk>>>(Q,DM, Wq,DM, bq, gq, nullptr,nullptr, DM);
  gemm_kernel<128,2,4,0,0><<<dim3(8,32),blk>>>(K,DM, Wk,DM, bk, gk, nullptr,nullptr, DM);
  gemm_kernel<128,2,4,0,0><<<dim3(8,32),blk>>>(V,DM, Wv,DM, bv, gv, nullptr,nullptr, DM);
  // scores: exp(q@k^T/8), row partial sums
  gemm_kernel<128,2,4,1,1><<<dim3(16,16,HEADS),blk>>>(gq,DK, gk,DK, nullptr, attn, gpart, nullptr, DK);
  // invert row sums
  rowsum_inv_kernel<<<HEADS*SS/256,256>>>(gpart, ginv);
  // ctx: normalize attn rows on load (+writeback), attn@v, merge heads
  gemm_kernel<64,4,2,0,2><<<dim3(1,16,HEADS),blk>>>(attn,SS, gv,DK, nullptr, gctx, ginv, attn, SS);
  // output projection
  gemm_kernel<128,2,4,0,3><<<dim3(8,32),blk>>>(gctx,DM, Wfc,DM, bfc, out_f, nullptr,nullptr, DM);
}

// round 3
// speedup vs baseline: 2.0352x; 1.8536x over previous
#include <cuda_runtime.h>
#include <cuda_bf16.h>
#include <cstdint>

using bf16 = __nv_bfloat16;

#define BB 2
#define SS 2048
#define DM 1024
#define NH 16
#define DK 64
#define MROWS (BB*SS)       // 4096
#define HEADS (BB*NH)       // 32

// ---------------- scratch (device globals; no allocations) ----------------
__device__ bf16 g_Xh[3][MROWS*DM];            // converted Q,K,V inputs (hi)
__device__ bf16 g_Xl[3][MROWS*DM];            // (lo)
__device__ bf16 g_Wh[4][DM*DM];               // converted Wq,Wk,Wv,Wfc (hi)
__device__ bf16 g_Wl[4][DM*DM];
__device__ bf16 g_qh[HEADS*SS*DK], g_ql[HEADS*SS*DK];
__device__ bf16 g_kh[HEADS*SS*DK], g_kl[HEADS*SS*DK];
__device__ bf16 g_vh[HEADS*SS*DK], g_vl[HEADS*SS*DK];
__device__ bf16 g_ch[MROWS*DM],   g_cl[MROWS*DM];   // ctx (merged heads)
__device__ float g_part[HEADS*SS*16];
__device__ float g_inv[HEADS*SS];
__device__ float g_attn_fb[(size_t)HEADS*SS*SS];

// ---------------- helpers ----------------
__device__ __forceinline__ unsigned sptr(const void* p){
  return (unsigned)__cvta_generic_to_shared(p);
}
#define CP16(d,s) asm volatile("cp.async.cg.shared.global [%0], [%1], 16;\n" :: "r"(d), "l"(s))
#define CPCOMMIT() asm volatile("cp.async.commit_group;\n")
#define CPWAIT(N)  asm volatile("cp.async.wait_group %0;\n" :: "n"(N))

__device__ __forceinline__ unsigned pack2(bf16 x, bf16 y){
  __nv_bfloat162 t = __halves2bfloat162(x, y);     // x -> low 16 bits
  return *reinterpret_cast<unsigned*>(&t);
}
__device__ __forceinline__ void split_bf16(float v, bf16& h, bf16& l){
  h = __float2bfloat16(v);
  l = __float2bfloat16(v - __bfloat162float(h));
}
__device__ __forceinline__ void mma16(float c[4], const unsigned a[4], const unsigned b[2]){
  asm volatile(
    "mma.sync.aligned.m16n8k16.row.col.f32.bf16.bf16.f32 "
    "{%0,%1,%2,%3},{%4,%5,%6,%7},{%8,%9},{%0,%1,%2,%3};\n"
    : "+f"(c[0]), "+f"(c[1]), "+f"(c[2]), "+f"(c[3])
    : "r"(a[0]), "r"(a[1]), "r"(a[2]), "r"(a[3]), "r"(b[0]), "r"(b[1]));
}

// fp32 -> (hi,lo) bf16 pair converter; n4 = n/4
__global__ void cvt_kernel(const float* __restrict__ in, bf16* __restrict__ hi,
                           bf16* __restrict__ lo, int n4){
  int i = blockIdx.x*blockDim.x + threadIdx.x;
  if (i >= n4) return;
  float4 v = ((const float4*)in)[i];
  bf16 h0,l0,h1,l1,h2,l2,h3,l3;
  split_bf16(v.x,h0,l0); split_bf16(v.y,h1,l1);
  split_bf16(v.z,h2,l2); split_bf16(v.w,h3,l3);
  uint2 uh, ul;
  uh.x = pack2(h0,h1); uh.y = pack2(h2,h3);
  ul.x = pack2(l0,l1); ul.y = pack2(l2,l3);
  ((uint2*)hi)[i] = uh;
  ((uint2*)lo)[i] = ul;
}

// ---------------------------------------------------------------------------
// bf16 split-3 GEMM, BM=128, BK=32, 256 threads.
// ASRC: 1 = bf16 hi/lo pair in gmem (cp.async staging)
//       2 = fp32, normalize-by-aux + writeback (ctx attention path)
// BLAY: 1 = B is bf16 pair [N, ldb] K-contiguous (C = A @ B^T)
//       0 = B is bf16 pair [K, ldb] N-contiguous (C = A @ B)
// EPI : 0 = proj (bias + head-split, bf16-pair out)
//       1 = scores (exp + attn fp32 store + row partial sums)
//       2 = ctx (merge heads, bf16-pair out)
//       3 = out-proj (bias, fp32 out)
// ---------------------------------------------------------------------------
template<int BN,int WARPS_M,int WARPS_N,int ASRC,int BLAY,int EPI>
__global__ void __launch_bounds__(256)
gemm2(const float* __restrict__ Af,
      const bf16* __restrict__ Ahp, const bf16* __restrict__ Alp, int lda,
      const bf16* __restrict__ Bhp, const bf16* __restrict__ Blp, int ldb,
      const float* __restrict__ bias,
      float* __restrict__ outf, bf16* __restrict__ outh, bf16* __restrict__ outl,
      float* __restrict__ aux, float* __restrict__ Amut, int Ktot)
{
  constexpr int BM=128, BK=32;
  constexpr int STAGES = (ASRC==1) ? 3 : 2;
  constexpr int PK  = 40;        // padded K-contig row (bf16 elems)
  constexpr int PBN = BN + 8;    // padded N-contig row
  constexpr int WM=BM/WARPS_M, WN=BN/WARPS_N;
  constexpr int MF=WM/16, NF=WN/8;
  constexpr int BTILE = BLAY ? (BN*PK) : (BK*PBN);

  extern __shared__ bf16 smx[];
  bf16* sAh = smx;
  bf16* sAl = sAh + STAGES*BM*PK;
  bf16* sBh = sAl + STAGES*BM*PK;
  bf16* sBl = sBh + STAGES*BTILE;

  const int tid=threadIdx.x, lane=tid&31, wid=tid>>5;
  const int g=lane>>2, tg=lane&3;
  const int warp_m=wid/WARPS_N, warp_n=wid%WARPS_N;
  const int wm=warp_m*WM, wn=warp_n*WN;
  const int m0=blockIdx.y*BM, n0=blockIdx.x*BN, bh_=blockIdx.z;

  const float* Afp = Af;
  const bf16 *Ah=Ahp, *Al=Alp, *Bh=Bhp, *Bl=Blp;
  float* Aw = Amut;
  if constexpr (EPI==1){
    Ah += (size_t)bh_*SS*DK; Al += (size_t)bh_*SS*DK;
    Bh += (size_t)bh_*SS*DK; Bl += (size_t)bh_*SS*DK;
  }
  if constexpr (EPI==2){
    Afp += (size_t)bh_*SS*SS; Aw += (size_t)bh_*SS*SS;
    Bh  += (size_t)bh_*SS*DK; Bl += (size_t)bh_*SS*DK;
  }

  // staging thread mapping
  const int ar=tid>>1, acA=(tid&1)*16;
  const int brB1=tid>>1, bcB1=(tid&1)*16;                 // BLAY1 (BN=128)
  const int brB0=tid>>3;
  const int bcB0 = (BN==128) ? (tid&7)*16 : (tid&7)*8;    // BLAY0

  float ainv = 1.f;
  if constexpr (ASRC==2) ainv = aux[(size_t)bh_*SS + m0 + ar];

  float acc[MF][NF][4];
#pragma unroll
  for (int mi=0;mi<MF;mi++)
#pragma unroll
    for (int ni=0;ni<NF;ni++)
#pragma unroll
      for (int q=0;q<4;q++) acc[mi][ni][q]=0.f;

  const int T = Ktot/BK;

  auto compute = [&](int st){
#pragma unroll
    for (int s16=0; s16<2; s16++){
      unsigned ah[MF][4], al[MF][4], bh[NF][2], bl[NF][2];
#pragma unroll
      for (int mi=0;mi<MF;mi++){
        const int r = wm + mi*16 + g;
        const unsigned* rh0 = (const unsigned*)(sAh + ((size_t)st*BM + r  )*PK);
        const unsigned* rh1 = (const unsigned*)(sAh + ((size_t)st*BM + r+8)*PK);
        const unsigned* rl0 = (const unsigned*)(sAl + ((size_t)st*BM + r  )*PK);
        const unsigned* rl1 = (const unsigned*)(sAl + ((size_t)st*BM + r+8)*PK);
        const int q0 = s16*8 + tg;
        ah[mi][0]=rh0[q0];   ah[mi][1]=rh1[q0];
        ah[mi][2]=rh0[q0+4]; ah[mi][3]=rh1[q0+4];
        al[mi][0]=rl0[q0];   al[mi][1]=rl1[q0];
        al[mi][2]=rl0[q0+4]; al[mi][3]=rl1[q0+4];
      }
#pragma unroll
      for (int ni=0;ni<NF;ni++){
        const int c = wn + ni*8 + g;
        if constexpr (BLAY==1){
          const unsigned* ch = (const unsigned*)(sBh + ((size_t)st*BN + c)*PK);
          const unsigned* cl = (const unsigned*)(sBl + ((size_t)st*BN + c)*PK);
          const int q0 = s16*8 + tg;
          bh[ni][0]=ch[q0]; bh[ni][1]=ch[q0+4];
          bl[ni][0]=cl[q0]; bl[ni][1]=cl[q0+4];
        } else {
          const int kk = s16*16;
          const bf16* bb = sBh + ((size_t)st*BK)*PBN;
          const bf16* ll = sBl + ((size_t)st*BK)*PBN;
          bh[ni][0]=pack2(bb[(kk+2*tg  )*PBN+c], bb[(kk+2*tg+1)*PBN+c]);
          bh[ni][1]=pack2(bb[(kk+2*tg+8)*PBN+c], bb[(kk+2*tg+9)*PBN+c]);
          bl[ni][0]=pack2(ll[(kk+2*tg  )*PBN+c], ll[(kk+2*tg+1)*PBN+c]);
          bl[ni][1]=pack2(ll[(kk+2*tg+8)*PBN+c], ll[(kk+2*tg+9)*PBN+c]);
        }
      }
#pragma unroll
      for (int mi=0;mi<MF;mi++)
#pragma unroll
        for (int ni=0;ni<NF;ni++){
          mma16(acc[mi][ni], ah[mi], bh[ni]);
          mma16(acc[mi][ni], al[mi], bh[ni]);
          mma16(acc[mi][ni], ah[mi], bl[ni]);
        }
    }
  };

  if constexpr (ASRC==1){
    auto issue = [&](int t){
      const int st = t % STAGES;
      const int k0 = t*BK;
      {
        const bf16* s = Ah + (size_t)(m0+ar)*lda + k0 + acA;
        unsigned d = sptr(sAh + ((size_t)st*BM+ar)*PK + acA);
        CP16(d, s); CP16(d+16, s+8);
        const bf16* s2 = Al + (size_t)(m0+ar)*lda + k0 + acA;
        unsigned d2 = sptr(sAl + ((size_t)st*BM+ar)*PK + acA);
        CP16(d2, s2); CP16(d2+16, s2+8);
      }
      if constexpr (BLAY==1){
        const bf16* s = Bh + (size_t)(n0+brB1)*ldb + k0 + bcB1;
        unsigned d = sptr(sBh + ((size_t)st*BN+brB1)*PK + bcB1);
        CP16(d, s); CP16(d+16, s+8);
        const bf16* s2 = Bl + (size_t)(n0+brB1)*ldb + k0 + bcB1;
        unsigned d2 = sptr(sBl + ((size_t)st*BN+brB1)*PK + bcB1);
        CP16(d2, s2); CP16(d2+16, s2+8);
      } else {
        const bf16* s = Bh + (size_t)(k0+brB0)*ldb + n0 + bcB0;
        unsigned d = sptr(sBh + ((size_t)st*BK+brB0)*PBN + bcB0);
        CP16(d, s); CP16(d+16, s+8);
        const bf16* s2 = Bl + (size_t)(k0+brB0)*ldb + n0 + bcB0;
        unsigned d2 = sptr(sBl + ((size_t)st*BK+brB0)*PBN + bcB0);
        CP16(d2, s2); CP16(d2+16, s2+8);
      }
      CPCOMMIT();
    };
    issue(0);
    if (T > 1) issue(1);
    for (int t=0;t<T;t++){
      if (t < T-1) { CPWAIT(1); } else { CPWAIT(0); }
      __syncthreads();
      if (t+2 < T) issue(t+2);
      compute(t % STAGES);
    }
    __syncthreads();
  } else {
    // register-staged path (ctx): fp32 A normalize + writeback; bf16 B
    float4 a4[4];
    uint4 bvh, bvl;
    auto ldg = [&](int t){
      const int k0 = t*BK;
      const float4* p = (const float4*)(Afp + (size_t)(m0+ar)*lda + k0 + acA);
      float4* w = (float4*)(Aw + (size_t)(m0+ar)*lda + k0 + acA);
#pragma unroll
      for (int i=0;i<4;i++){
        float4 v = __ldcs(p+i);
        v.x*=ainv; v.y*=ainv; v.z*=ainv; v.w*=ainv;
        __stcs(w+i, v);
        a4[i]=v;
      }
      bvh = *(const uint4*)(Bh + (size_t)(k0+brB0)*ldb + n0 + bcB0);
      bvl = *(const uint4*)(Bl + (size_t)(k0+brB0)*ldb + n0 + bcB0);
    };
    auto sts = [&](int st){
      float f[16] = {a4[0].x,a4[0].y,a4[0].z,a4[0].w, a4[1].x,a4[1].y,a4[1].z,a4[1].w,
                     a4[2].x,a4[2].y,a4[2].z,a4[2].w, a4[3].x,a4[3].y,a4[3].z,a4[3].w};
      unsigned* dh = (unsigned*)(sAh + ((size_t)st*BM+ar)*PK) + (acA>>1);
      unsigned* dl = (unsigned*)(sAl + ((size_t)st*BM+ar)*PK) + (acA>>1);
#pragma unroll
      for (int i=0;i<8;i++){
        bf16 h0,l0,h1,l1;
        split_bf16(f[2*i],  h0,l0);
        split_bf16(f[2*i+1],h1,l1);
        dh[i]=pack2(h0,h1); dl[i]=pack2(l0,l1);
      }
      *(uint4*)(sBh + ((size_t)st*BK+brB0)*PBN + bcB0) = bvh;
      *(uint4*)(sBl + ((size_t)st*BK+brB0)*PBN + bcB0) = bvl;
    };
    ldg(0);
    for (int t=0;t<T;t++){
      sts(t & 1);
      __syncthreads();
      if (t+1<T) ldg(t+1);
      compute(t & 1);
      __syncthreads();
    }
  }

  // ---------------- epilogues ----------------
  if constexpr (EPI==0){
#pragma unroll
    for (int mi=0;mi<MF;mi++)
#pragma unroll
      for (int hf=0;hf<2;hf++){
        const int m = m0 + wm + mi*16 + g + hf*8;
        const int b = m >> 11, s = m & (SS-1);
#pragma unroll
        for (int ni=0;ni<NF;ni++){
          const int n = n0 + wn + ni*8 + tg*2;
          const int h = n >> 6, d = n & 63;
          const size_t o = (((size_t)b*NH + h)*SS + s)*DK + d;
          float y0 = acc[mi][ni][hf*2+0] + bias[n];
          float y1 = acc[mi][ni][hf*2+1] + bias[n+1];
          bf16 h0,l0,h1,l1;
          split_bf16(y0,h0,l0); split_bf16(y1,h1,l1);
          *(unsigned*)(outh+o) = pack2(h0,h1);
          *(unsigned*)(outl+o) = pack2(l0,l1);
        }
      }
  } else if constexpr (EPI==1){
    __shared__ float rp[BM][WARPS_N];
    float* attn = outf + (size_t)bh_*SS*SS;
    float rs[MF][2];
#pragma unroll
    for (int mi=0;mi<MF;mi++){ rs[mi][0]=0.f; rs[mi][1]=0.f; }
#pragma unroll
    for (int mi=0;mi<MF;mi++)
#pragma unroll
      for (int hf=0;hf<2;hf++){
        const size_t m = (size_t)(m0 + wm + mi*16 + g + hf*8);
#pragma unroll
        for (int ni=0;ni<NF;ni++){
          const int n = n0 + wn + ni*8 + tg*2;
          float2 e;
          e.x = __expf(acc[mi][ni][hf*2+0]*0.125f);
          e.y = __expf(acc[mi][ni][hf*2+1]*0.125f);
          __stcs((float2*)(attn + m*SS + n), e);
          rs[mi][hf] += e.x + e.y;
        }
      }
#pragma unroll
    for (int mi=0;mi<MF;mi++)
#pragma unroll
      for (int hf=0;hf<2;hf++){
        float v = rs[mi][hf];
        v += __shfl_xor_sync(0xffffffffu, v, 1);
        v += __shfl_xor_sync(0xffffffffu, v, 2);
        if (tg==0) rp[wm+mi*16+g+hf*8][warp_n] = v;
      }
    __syncthreads();
    if (tid < BM){
      float s = 0.f;
#pragma unroll
      for (int w=0;w<WARPS_N;w++) s += rp[tid][w];
      aux[((size_t)bh_*SS + m0 + tid)*16 + blockIdx.x] = s;
    }
  } else if constexpr (EPI==2){
    const int b = bh_/NH, h = bh_%NH;
#pragma unroll
    for (int mi=0;mi<MF;mi++)
#pragma unroll
      for (int hf=0;hf<2;hf++){
        const int s = m0 + wm + mi*16 + g + hf*8;
#pragma unroll
        for (int ni=0;ni<NF;ni++){
          const int c = wn + ni*8 + tg*2;
          const size_t o = ((size_t)(b*SS + s))*DM + h*DK + c;
          float y0 = acc[mi][ni][hf*2+0];
          float y1 = acc[mi][ni][hf*2+1];
          bf16 h0,l0,h1,l1;
          split_bf16(y0,h0,l0); split_bf16(y1,h1,l1);
          *(unsigned*)(outh+o) = pack2(h0,h1);
          *(unsigned*)(outl+o) = pack2(l0,l1);
        }
      }
  } else {
#pragma unroll
    for (int mi=0;mi<MF;mi++)
#pragma unroll
      for (int hf=0;hf<2;hf++){
        const int m = m0 + wm + mi*16 + g + hf*8;
#pragma unroll
        for (int ni=0;ni<NF;ni++){
          const int n = n0 + wn + ni*8 + tg*2;
          float2 y;
          y.x = acc[mi][ni][hf*2+0] + bias[n];
          y.y = acc[mi][ni][hf*2+1] + bias[n+1];
          *(float2*)(outf + (size_t)m*DM + n) = y;
        }
      }
  }
}

// Deterministic rowsum inversion
__global__ void rowsum_inv_kernel(const float* __restrict__ part, float* __restrict__ inv){
  const int r = blockIdx.x*blockDim.x + threadIdx.x;
  const float* p = part + (size_t)r*16;
  float s = 0.f;
#pragma unroll
  for (int i=0;i<16;i++) s += p[i];
  inv[r] = 1.0f/s;
}

extern "C" void kernel_launch(void* const* d_in, const int* in_sizes, int n_in,
                              void* d_out, int out_size){
  const float* Q   = (const float*)d_in[0];
  const float* K   = (const float*)d_in[1];
  const float* V   = (const float*)d_in[2];
  const float* Wq  = (const float*)d_in[3];
  const float* bq  = (const float*)d_in[4];
  const float* Wk  = (const float*)d_in[5];
  const float* bk  = (const float*)d_in[6];
  const float* Wv  = (const float*)d_in[7];
  const float* bv  = (const float*)d_in[8];
  const float* Wfc = (const float*)d_in[9];
  const float* bfc = (const float*)d_in[10];
  float* out_f = (float*)d_out;

  bf16 *Xh,*Xl,*Wh,*Wl,*qh,*ql,*kh,*kl,*vh,*vl,*ch,*cl;
  float *part,*inv,*afb;
  cudaGetSymbolAddress((void**)&Xh, g_Xh); cudaGetSymbolAddress((void**)&Xl, g_Xl);
  cudaGetSymbolAddress((void**)&Wh, g_Wh); cudaGetSymbolAddress((void**)&Wl, g_Wl);
  cudaGetSymbolAddress((void**)&qh, g_qh); cudaGetSymbolAddress((void**)&ql, g_ql);
  cudaGetSymbolAddress((void**)&kh, g_kh); cudaGetSymbolAddress((void**)&kl, g_kl);
  cudaGetSymbolAddress((void**)&vh, g_vh); cudaGetSymbolAddress((void**)&vl, g_vl);
  cudaGetSymbolAddress((void**)&ch, g_ch); cudaGetSymbolAddress((void**)&cl, g_cl);
  cudaGetSymbolAddress((void**)&part, g_part);
  cudaGetSymbolAddress((void**)&inv,  g_inv);
  cudaGetSymbolAddress((void**)&afb,  g_attn_fb);

  const size_t ATTN = (size_t)HEADS*SS*SS;
  float* attn = ((size_t)out_size >= ATTN) ? (out_f + ((size_t)out_size - ATTN)) : afb;

  // dynamic smem sizes (bytes)
  const int SM_PROJ   = (3*128*40*2 + 3*32*136*2) * 2;   // 113664
  const int SM_SCORES = (3*128*40*2 + 3*128*40*2) * 2;   // 122880
  const int SM_CTX    = (2*128*40*2 + 2*32*72*2)  * 2;   //  59392

  cudaFuncSetAttribute(gemm2<128,2,4,1,0,0>, cudaFuncAttributeMaxDynamicSharedMemorySize, SM_PROJ);
  cudaFuncSetAttribute(gemm2<128,2,4,1,1,1>, cudaFuncAttributeMaxDynamicSharedMemorySize, SM_SCORES);
  cudaFuncSetAttribute(gemm2<64,4,2,2,0,2>,  cudaFuncAttributeMaxDynamicSharedMemorySize, SM_CTX);
  cudaFuncSetAttribute(gemm2<128,2,4,1,0,3>, cudaFuncAttributeMaxDynamicSharedMemorySize, SM_PROJ);

  dim3 blk(256);
  const int NW = DM*DM;     // 1048576
  const int NX = MROWS*DM;  // 4194304

  // convert inputs + weights to bf16 hi/lo pairs
  cvt_kernel<<<NX/4/256, blk>>>(Q,   Xh + 0*(size_t)NX, Xl + 0*(size_t)NX, NX/4);
  cvt_kernel<<<NX/4/256, blk>>>(K,   Xh + 1*(size_t)NX, Xl + 1*(size_t)NX, NX/4);
  cvt_kernel<<<NX/4/256, blk>>>(V,   Xh + 2*(size_t)NX, Xl + 2*(size_t)NX, NX/4);
  cvt_kernel<<<NW/4/256, blk>>>(Wq,  Wh + 0*(size_t)NW, Wl + 0*(size_t)NW, NW/4);
  cvt_kernel<<<NW/4/256, blk>>>(Wk,  Wh + 1*(size_t)NW, Wl + 1*(size_t)NW, NW/4);
  cvt_kernel<<<NW/4/256, blk>>>(Wv,  Wh + 2*(size_t)NW, Wl + 2*(size_t)NW, NW/4);
  cvt_kernel<<<NW/4/256, blk>>>(Wfc, Wh + 3*(size_t)NW, Wl + 3*(size_t)NW, NW/4);

  // Q/K/V projections (head-split bf16-pair out)
  gemm2<128,2,4,1,0,0><<<dim3(8,32), blk, SM_PROJ>>>(
      nullptr, Xh+0*(size_t)NX, Xl+0*(size_t)NX, DM, Wh+0*(size_t)NW, Wl+0*(size_t)NW, DM,
      bq, nullptr, qh, ql, nullptr, nullptr, DM);
  gemm2<128,2,4,1,0,0><<<dim3(8,32), blk, SM_PROJ>>>(
      nullptr, Xh+1*(size_t)NX, Xl+1*(size_t)NX, DM, Wh+1*(size_t)NW, Wl+1*(size_t)NW, DM,
      bk, nullptr, kh, kl, nullptr, nullptr, DM);
  gemm2<128,2,4,1,0,0><<<dim3(8,32), blk, SM_PROJ>>>(
      nullptr, Xh+2*(size_t)NX, Xl+2*(size_t)NX, DM, Wh+2*(size_t)NW, Wl+2*(size_t)NW, DM,
      bv, nullptr, vh, vl, nullptr, nullptr, DM);

  // scores: exp(q@k^T/8) -> attn (fp32) + row partial sums
  gemm2<128,2,4,1,1,1><<<dim3(16,16,HEADS), blk, SM_SCORES>>>(
      nullptr, qh, ql, DK, kh, kl, DK,
      nullptr, attn, nullptr, nullptr, part, nullptr, DK);

  rowsum_inv_kernel<<<HEADS*SS/256, blk>>>(part, inv);

  // ctx: normalize attn on load (+writeback), attn@v, merge heads (bf16-pair out)
  gemm2<64,4,2,2,0,2><<<dim3(1,16,HEADS), blk, SM_CTX>>>(
      attn, nullptr, nullptr, SS, vh, vl, DK,
      nullptr, nullptr, ch, cl, inv, attn, SS);

  // output projection (fp32 out + bias)
  gemm2<128,2,4,1,0,3><<<dim3(8,32), blk, SM_PROJ>>>(
      nullptr, ch, cl, DM, Wh+3*(size_t)NW, Wl+3*(size_t)NW, DM,
      bfc, out_f, nullptr, nullptr, nullptr, nullptr, DM);
}

// round 5
// speedup vs baseline: 2.1795x; 1.0709x over previous
#include <cuda_runtime.h>
#include <cuda_bf16.h>
#include <cstdint>

using bf16 = __nv_bfloat16;

#define BB 2
#define SS 2048
#define DM 1024
#define NH 16
#define DK 64
#define MROWS (BB*SS)       // 4096
#define HEADS (BB*NH)       // 32
#define NXE (MROWS*DM)      // 4194304
#define NWE (DM*DM)         // 1048576
#define QKVE (HEADS*SS*DK)  // 4194304

// ---------------- scratch (device globals; no allocations) ----------------
__device__ bf16 g_Xh[3*NXE], g_Xl[3*NXE];          // converted Q,K,V inputs
__device__ bf16 g_Wh[4*NWE], g_Wl[4*NWE];          // converted Wq,Wk,Wv,Wfc
__device__ bf16 g_qkvh[3*QKVE], g_qkvl[3*QKVE];    // projected q,k,v (head-split)
__device__ bf16 g_ch[MROWS*DM], g_cl[MROWS*DM];    // ctx (merged heads)
__device__ float g_bias3[3*DM];
__device__ float g_part[HEADS*SS*16];
__device__ float g_inv[HEADS*SS];
__device__ float g_attn_fb[(size_t)HEADS*SS*SS];

// ---------------- helpers ----------------
__device__ __forceinline__ unsigned sptr(const void* p){
  return (unsigned)__cvta_generic_to_shared(p);
}
#define CP16(d,s) asm volatile("cp.async.cg.shared.global [%0], [%1], 16;\n" :: "r"(d), "l"(s))
#define CPCOMMIT() asm volatile("cp.async.commit_group;\n")
#define CPWAIT(N)  asm volatile("cp.async.wait_group %0;\n" :: "n"(N))

__device__ __forceinline__ unsigned pack2(bf16 x, bf16 y){
  __nv_bfloat162 t = __halves2bfloat162(x, y);
  return *reinterpret_cast<unsigned*>(&t);
}
__device__ __forceinline__ void split_bf16(float v, bf16& h, bf16& l){
  h = __float2bfloat16(v);
  l = __float2bfloat16(v - __bfloat162float(h));
}
__device__ __forceinline__ void mma16(float c[4], const unsigned a[4], const unsigned b[2]){
  asm volatile(
    "mma.sync.aligned.m16n8k16.row.col.f32.bf16.bf16.f32 "
    "{%0,%1,%2,%3},{%4,%5,%6,%7},{%8,%9},{%0,%1,%2,%3};\n"
    : "+f"(c[0]), "+f"(c[1]), "+f"(c[2]), "+f"(c[3])
    : "r"(a[0]), "r"(a[1]), "r"(a[2]), "r"(a[3]), "r"(b[0]), "r"(b[1]));
}

// single merged fp32 -> bf16 hi/lo converter for all 7 tensors (z selects)
__global__ void cvt7(const float* p0, const float* p1, const float* p2,
                     const float* p3, const float* p4, const float* p5,
                     const float* p6,
                     bf16* __restrict__ Xh, bf16* __restrict__ Xl,
                     bf16* __restrict__ Wh, bf16* __restrict__ Wl){
  const int z = blockIdx.z;
  const float* in = (z==0)?p0:(z==1)?p1:(z==2)?p2:(z==3)?p3:(z==4)?p4:(z==5)?p5:p6;
  const int n4 = ((z<3)?NXE:NWE)/4;
  bf16* hi = (z<3) ? Xh + (size_t)z*NXE : Wh + (size_t)(z-3)*NWE;
  bf16* lo = (z<3) ? Xl + (size_t)z*NXE : Wl + (size_t)(z-3)*NWE;
  const int i = blockIdx.x*blockDim.x + threadIdx.x;
  if (i >= n4) return;
  float4 v = ((const float4*)in)[i];
  bf16 h0,l0,h1,l1,h2,l2,h3,l3;
  split_bf16(v.x,h0,l0); split_bf16(v.y,h1,l1);
  split_bf16(v.z,h2,l2); split_bf16(v.w,h3,l3);
  uint2 uh, ul;
  uh.x = pack2(h0,h1); uh.y = pack2(h2,h3);
  ul.x = pack2(l0,l1); ul.y = pack2(l2,l3);
  ((uint2*)hi)[i] = uh;
  ((uint2*)lo)[i] = ul;
}

// ---------------------------------------------------------------------------
// bf16 split-3 GEMM, BM=128, BK=32, 256 threads, 2 CTAs/SM.
// PK=40 (80-byte rows) keeps every cp.async dst 16B-aligned AND conflict-free.
// ASRC: 1 = bf16 hi/lo pair in gmem (cp.async; 3-stage, except scores 2-stage)
//       2 = fp32 A, normalize + writeback (ctx path, register-staged, 2-stage)
// BLAY: 1 = B bf16 pair [N,ldb] K-contig (C=A@B^T); 0 = [K,ldb] N-contig
// EPI : 0 proj (z-indexed, bias+head-split) / 1 scores / 2 ctx / 3 out-proj
// ---------------------------------------------------------------------------
template<int BN,int WARPS_M,int WARPS_N,int ASRC,int BLAY,int EPI>
__global__ void __launch_bounds__(256,2)
gemm2(const float* __restrict__ Af,
      const bf16* __restrict__ Ahp, const bf16* __restrict__ Alp, int lda,
      const bf16* __restrict__ Bhp, const bf16* __restrict__ Blp, int ldb,
      const float* __restrict__ biasp,
      float* __restrict__ outf, bf16* __restrict__ outhp, bf16* __restrict__ outlp,
      float* __restrict__ aux, float* __restrict__ Amut, int Ktot)
{
  constexpr int BM=128, BK=32;
  // scores (EPI==1) has T = 64/32 = 2 k-tiles; 2 stages suffice and fit 2 CTAs/SM.
  constexpr int STAGES = (ASRC==1) ? ((EPI==1) ? 2 : 3) : 2;
  constexpr int PK  = 40;        // padded K-contig row; 80B = 5*16B -> aligned
  constexpr int PBN = BN + 8;    // padded N-contig row; 16B-aligned stride
  constexpr int WM=BM/WARPS_M, WN=BN/WARPS_N;
  constexpr int MF=WM/16, NF=WN/8;
  constexpr int BTILE = BLAY ? (BN*PK) : (BK*PBN);

  extern __shared__ bf16 smx[];
  bf16* sAh = smx;
  bf16* sAl = sAh + STAGES*BM*PK;
  bf16* sBh = sAl + STAGES*BM*PK;
  bf16* sBl = sBh + STAGES*BTILE;

  const int tid=threadIdx.x, lane=tid&31, wid=tid>>5;
  const int g=lane>>2, tg=lane&3;
  const int warp_m=wid/WARPS_N, warp_n=wid%WARPS_N;
  const int wm=warp_m*WM, wn=warp_n*WN;
  const int m0=blockIdx.y*BM, n0=blockIdx.x*BN, bh_=blockIdx.z;

  const float* Afp = Af;
  const bf16 *Ah=Ahp, *Al=Alp, *Bh=Bhp, *Bl=Blp;
  const float* bias = biasp;
  bf16 *outh=outhp, *outl=outlp;
  float* Aw = Amut;
  if constexpr (EPI==0){
    Ah += (size_t)bh_*NXE;  Al += (size_t)bh_*NXE;
    Bh += (size_t)bh_*NWE;  Bl += (size_t)bh_*NWE;
    bias += bh_*DM;
    outh += (size_t)bh_*QKVE; outl += (size_t)bh_*QKVE;
  }
  if constexpr (EPI==1){
    Ah += (size_t)bh_*SS*DK; Al += (size_t)bh_*SS*DK;
    Bh += (size_t)bh_*SS*DK; Bl += (size_t)bh_*SS*DK;
  }
  if constexpr (EPI==2){
    Afp += (size_t)bh_*SS*SS; Aw += (size_t)bh_*SS*SS;
    Bh  += (size_t)bh_*SS*DK; Bl += (size_t)bh_*SS*DK;
  }

  const int ar=tid>>1, acA=(tid&1)*16;
  const int brB1=tid>>1, bcB1=(tid&1)*16;
  const int brB0=tid>>3;
  const int bcB0 = (BN==128) ? (tid&7)*16 : (tid&7)*8;

  float ainv = 1.f;
  if constexpr (ASRC==2) ainv = aux[(size_t)bh_*SS + m0 + ar];

  float acc[MF][NF][4];
#pragma unroll
  for (int mi=0;mi<MF;mi++)
#pragma unroll
    for (int ni=0;ni<NF;ni++)
#pragma unroll
      for (int q=0;q<4;q++) acc[mi][ni][q]=0.f;

  const int T = Ktot/BK;

  auto compute = [&](int st){
#pragma unroll
    for (int s16=0; s16<2; s16++){
      unsigned ah[MF][4], al[MF][4], bh[NF][2], bl[NF][2];
#pragma unroll
      for (int mi=0;mi<MF;mi++){
        const int r = wm + mi*16 + g;
        const unsigned* rh0 = (const unsigned*)(sAh + ((size_t)st*BM + r  )*PK);
        const unsigned* rh1 = (const unsigned*)(sAh + ((size_t)st*BM + r+8)*PK);
        const unsigned* rl0 = (const unsigned*)(sAl + ((size_t)st*BM + r  )*PK);
        const unsigned* rl1 = (const unsigned*)(sAl + ((size_t)st*BM + r+8)*PK);
        const int q0 = s16*8 + tg;
        ah[mi][0]=rh0[q0];   ah[mi][1]=rh1[q0];
        ah[mi][2]=rh0[q0+4]; ah[mi][3]=rh1[q0+4];
        al[mi][0]=rl0[q0];   al[mi][1]=rl1[q0];
        al[mi][2]=rl0[q0+4]; al[mi][3]=rl1[q0+4];
      }
#pragma unroll
      for (int ni=0;ni<NF;ni++){
        const int c = wn + ni*8 + g;
        if constexpr (BLAY==1){
          const unsigned* ch = (const unsigned*)(sBh + ((size_t)st*BN + c)*PK);
          const unsigned* cl = (const unsigned*)(sBl + ((size_t)st*BN + c)*PK);
          const int q0 = s16*8 + tg;
          bh[ni][0]=ch[q0]; bh[ni][1]=ch[q0+4];
          bl[ni][0]=cl[q0]; bl[ni][1]=cl[q0+4];
        } else {
          const int kk = s16*16;
          const bf16* bb = sBh + ((size_t)st*BK)*PBN;
          const bf16* ll = sBl + ((size_t)st*BK)*PBN;
          bh[ni][0]=pack2(bb[(kk+2*tg  )*PBN+c], bb[(kk+2*tg+1)*PBN+c]);
          bh[ni][1]=pack2(bb[(kk+2*tg+8)*PBN+c], bb[(kk+2*tg+9)*PBN+c]);
          bl[ni][0]=pack2(ll[(kk+2*tg  )*PBN+c], ll[(kk+2*tg+1)*PBN+c]);
          bl[ni][1]=pack2(ll[(kk+2*tg+8)*PBN+c], ll[(kk+2*tg+9)*PBN+c]);
        }
      }
#pragma unroll
      for (int mi=0;mi<MF;mi++)
#pragma unroll
        for (int ni=0;ni<NF;ni++){
          mma16(acc[mi][ni], ah[mi], bh[ni]);
          mma16(acc[mi][ni], al[mi], bh[ni]);
          mma16(acc[mi][ni], ah[mi], bl[ni]);
        }
    }
  };

  if constexpr (ASRC==1){
    auto issue = [&](int t){
      const int st = t % STAGES;
      const int k0 = t*BK;
      {
        const bf16* s = Ah + (size_t)(m0+ar)*lda + k0 + acA;
        unsigned d = sptr(sAh + ((size_t)st*BM+ar)*PK + acA);
        CP16(d, s); CP16(d+16, s+8);
        const bf16* s2 = Al + (size_t)(m0+ar)*lda + k0 + acA;
        unsigned d2 = sptr(sAl + ((size_t)st*BM+ar)*PK + acA);
        CP16(d2, s2); CP16(d2+16, s2+8);
      }
      if constexpr (BLAY==1){
        const bf16* s = Bh + (size_t)(n0+brB1)*ldb + k0 + bcB1;
        unsigned d = sptr(sBh + ((size_t)st*BN+brB1)*PK + bcB1);
        CP16(d, s); CP16(d+16, s+8);
        const bf16* s2 = Bl + (size_t)(n0+brB1)*ldb + k0 + bcB1;
        unsigned d2 = sptr(sBl + ((size_t)st*BN+brB1)*PK + bcB1);
        CP16(d2, s2); CP16(d2+16, s2+8);
      } else {
        const bf16* s = Bh + (size_t)(k0+brB0)*ldb + n0 + bcB0;
        unsigned d = sptr(sBh + ((size_t)st*BK+brB0)*PBN + bcB0);
        CP16(d, s); CP16(d+16, s+8);
        const bf16* s2 = Bl + (size_t)(k0+brB0)*ldb + n0 + bcB0;
        unsigned d2 = sptr(sBl + ((size_t)st*BK+brB0)*PBN + bcB0);
        CP16(d2, s2); CP16(d2+16, s2+8);
      }
      CPCOMMIT();
    };
    issue(0);
    if (T > 1) issue(1);
    for (int t=0;t<T;t++){
      if (t < T-1) { CPWAIT(1); } else { CPWAIT(0); }
      __syncthreads();
      if (t+2 < T) issue(t+2);   // requires STAGES==3 when T>2 (scores has T==2)
      compute(t % STAGES);
    }
    __syncthreads();
  } else {
    float4 a4[4];
    uint4 bvh, bvl;
    auto ldg = [&](int t){
      const int k0 = t*BK;
      const float4* p = (const float4*)(Afp + (size_t)(m0+ar)*lda + k0 + acA);
      float4* w = (float4*)(Aw + (size_t)(m0+ar)*lda + k0 + acA);
#pragma unroll
      for (int i=0;i<4;i++){
        float4 v = __ldcs(p+i);
        v.x*=ainv; v.y*=ainv; v.z*=ainv; v.w*=ainv;
        __stcs(w+i, v);
        a4[i]=v;
      }
      bvh = *(const uint4*)(Bh + (size_t)(k0+brB0)*ldb + n0 + bcB0);
      bvl = *(const uint4*)(Bl + (size_t)(k0+brB0)*ldb + n0 + bcB0);
    };
    auto sts = [&](int st){
      float f[16] = {a4[0].x,a4[0].y,a4[0].z,a4[0].w, a4[1].x,a4[1].y,a4[1].z,a4[1].w,
                     a4[2].x,a4[2].y,a4[2].z,a4[2].w, a4[3].x,a4[3].y,a4[3].z,a4[3].w};
      unsigned* dh = (unsigned*)(sAh + ((size_t)st*BM+ar)*PK) + (acA>>1);
      unsigned* dl = (unsigned*)(sAl + ((size_t)st*BM+ar)*PK) + (acA>>1);
#pragma unroll
      for (int i=0;i<8;i++){
        bf16 h0,l0,h1,l1;
        split_bf16(f[2*i],  h0,l0);
        split_bf16(f[2*i+1],h1,l1);
        dh[i]=pack2(h0,h1); dl[i]=pack2(l0,l1);
      }
      *(uint4*)(sBh + ((size_t)st*BK+brB0)*PBN + bcB0) = bvh;
      *(uint4*)(sBl + ((size_t)st*BK+brB0)*PBN + bcB0) = bvl;
    };
    ldg(0);
    for (int t=0;t<T;t++){
      sts(t & 1);
      __syncthreads();
      if (t+1<T) ldg(t+1);
      compute(t & 1);
      __syncthreads();
    }
  }

  // ---------------- epilogues ----------------
  if constexpr (EPI==0){
#pragma unroll
    for (int mi=0;mi<MF;mi++)
#pragma unroll
      for (int hf=0;hf<2;hf++){
        const int m = m0 + wm + mi*16 + g + hf*8;
        const int b = m >> 11, s = m & (SS-1);
#pragma unroll
        for (int ni=0;ni<NF;ni++){
          const int n = n0 + wn + ni*8 + tg*2;
          const int h = n >> 6, d = n & 63;
          const size_t o = (((size_t)b*NH + h)*SS + s)*DK + d;
          float y0 = acc[mi][ni][hf*2+0] + bias[n];
          float y1 = acc[mi][ni][hf*2+1] + bias[n+1];
          bf16 h0,l0,h1,l1;
          split_bf16(y0,h0,l0); split_bf16(y1,h1,l1);
          *(unsigned*)(outh+o) = pack2(h0,h1);
          *(unsigned*)(outl+o) = pack2(l0,l1);
        }
      }
  } else if constexpr (EPI==1){
    __shared__ float rp[BM][WARPS_N];
    float* attn = outf + (size_t)bh_*SS*SS;
    float rs[MF][2];
#pragma unroll
    for (int mi=0;mi<MF;mi++){ rs[mi][0]=0.f; rs[mi][1]=0.f; }
#pragma unroll
    for (int mi=0;mi<MF;mi++)
#pragma unroll
      for (int hf=0;hf<2;hf++){
        const size_t m = (size_t)(m0 + wm + mi*16 + g + hf*8);
#pragma unroll
        for (int ni=0;ni<NF;ni++){
          const int n = n0 + wn + ni*8 + tg*2;
          float2 e;
          e.x = __expf(acc[mi][ni][hf*2+0]*0.125f);
          e.y = __expf(acc[mi][ni][hf*2+1]*0.125f);
          __stcs((float2*)(attn + m*SS + n), e);
          rs[mi][hf] += e.x + e.y;
        }
      }
#pragma unroll
    for (int mi=0;mi<MF;mi++)
#pragma unroll
      for (int hf=0;hf<2;hf++){
        float v = rs[mi][hf];
        v += __shfl_xor_sync(0xffffffffu, v, 1);
        v += __shfl_xor_sync(0xffffffffu, v, 2);
        if (tg==0) rp[wm+mi*16+g+hf*8][warp_n] = v;
      }
    __syncthreads();
    if (tid < BM){
      float s = 0.f;
#pragma unroll
      for (int w=0;w<WARPS_N;w++) s += rp[tid][w];
      aux[((size_t)bh_*SS + m0 + tid)*16 + blockIdx.x] = s;
    }
  } else if constexpr (EPI==2){
    const int b = bh_/NH, h = bh_%NH;
#pragma unroll
    for (int mi=0;mi<MF;mi++)
#pragma unroll
      for (int hf=0;hf<2;hf++){
        const int s = m0 + wm + mi*16 + g + hf*8;
#pragma unroll
        for (int ni=0;ni<NF;ni++){
          const int c = wn + ni*8 + tg*2;
          const size_t o = ((size_t)(b*SS + s))*DM + h*DK + c;
          float y0 = acc[mi][ni][hf*2+0];
          float y1 = acc[mi][ni][hf*2+1];
          bf16 h0,l0,h1,l1;
          split_bf16(y0,h0,l0); split_bf16(y1,h1,l1);
          *(unsigned*)(outh+o) = pack2(h0,h1);
          *(unsigned*)(outl+o) = pack2(l0,l1);
        }
      }
  } else {
#pragma unroll
    for (int mi=0;mi<MF;mi++)
#pragma unroll
      for (int hf=0;hf<2;hf++){
        const int m = m0 + wm + mi*16 + g + hf*8;
#pragma unroll
        for (int ni=0;ni<NF;ni++){
          const int n = n0 + wn + ni*8 + tg*2;
          float2 y;
          y.x = acc[mi][ni][hf*2+0] + bias[n];
          y.y = acc[mi][ni][hf*2+1] + bias[n+1];
          *(float2*)(outf + (size_t)m*DM + n) = y;
        }
      }
  }
}

__global__ void rowsum_inv_kernel(const float* __restrict__ part, float* __restrict__ inv){
  const int r = blockIdx.x*blockDim.x + threadIdx.x;
  const float* p = part + (size_t)r*16;
  float s = 0.f;
#pragma unroll
  for (int i=0;i<16;i++) s += p[i];
  inv[r] = 1.0f/s;
}

extern "C" void kernel_launch(void* const* d_in, const int* in_sizes, int n_in,
                              void* d_out, int out_size){
  const float* Q   = (const float*)d_in[0];
  const float* K   = (const float*)d_in[1];
  const float* V   = (const float*)d_in[2];
  const float* Wq  = (const float*)d_in[3];
  const float* bq  = (const float*)d_in[4];
  const float* Wk  = (const float*)d_in[5];
  const float* bk  = (const float*)d_in[6];
  const float* Wv  = (const float*)d_in[7];
  const float* bv  = (const float*)d_in[8];
  const float* Wfc = (const float*)d_in[9];
  const float* bfc = (const float*)d_in[10];
  float* out_f = (float*)d_out;

  bf16 *Xh,*Xl,*Wh,*Wl,*qkvh,*qkvl,*ch,*cl;
  float *bias3,*part,*inv,*afb;
  cudaGetSymbolAddress((void**)&Xh, g_Xh);   cudaGetSymbolAddress((void**)&Xl, g_Xl);
  cudaGetSymbolAddress((void**)&Wh, g_Wh);   cudaGetSymbolAddress((void**)&Wl, g_Wl);
  cudaGetSymbolAddress((void**)&qkvh, g_qkvh); cudaGetSymbolAddress((void**)&qkvl, g_qkvl);
  cudaGetSymbolAddress((void**)&ch, g_ch);   cudaGetSymbolAddress((void**)&cl, g_cl);
  cudaGetSymbolAddress((void**)&bias3, g_bias3);
  cudaGetSymbolAddress((void**)&part, g_part);
  cudaGetSymbolAddress((void**)&inv,  g_inv);
  cudaGetSymbolAddress((void**)&afb,  g_attn_fb);

  const size_t ATTN = (size_t)HEADS*SS*SS;
  float* attn = ((size_t)out_size >= ATTN) ? (out_f + ((size_t)out_size - ATTN)) : afb;

  // dynamic smem sizes (bytes), PK=40
  const int SM_PROJ   = 3*128*40*2*2 + 3*32*136*2*2;   // 113664 (3-stage)
  const int SM_SCORES = 2*128*40*2*2 + 2*128*40*2*2;   //  81920 (2-stage, T=2)
  const int SM_CTX    = 2*128*40*2*2 + 2*32*72*2*2;    //  59392

  cudaFuncSetAttribute(gemm2<128,2,4,1,0,0>, cudaFuncAttributeMaxDynamicSharedMemorySize, SM_PROJ);
  cudaFuncSetAttribute(gemm2<128,2,4,1,1,1>, cudaFuncAttributeMaxDynamicSharedMemorySize, SM_SCORES);
  cudaFuncSetAttribute(gemm2<64,4,2,2,0,2>,  cudaFuncAttributeMaxDynamicSharedMemorySize, SM_CTX);
  cudaFuncSetAttribute(gemm2<128,2,4,1,0,3>, cudaFuncAttributeMaxDynamicSharedMemorySize, SM_PROJ);

  dim3 blk(256);

  // contiguous biases (graph-capturable D2D copies)
  cudaMemcpyAsync(bias3,        bq, DM*sizeof(float), cudaMemcpyDeviceToDevice);
  cudaMemcpyAsync(bias3 + DM,   bk, DM*sizeof(float), cudaMemcpyDeviceToDevice);
  cudaMemcpyAsync(bias3 + 2*DM, bv, DM*sizeof(float), cudaMemcpyDeviceToDevice);

  // convert all inputs + weights (one launch)
  cvt7<<<dim3(NXE/4/256,1,7), blk>>>(Q,K,V,Wq,Wk,Wv,Wfc, Xh,Xl,Wh,Wl);

  // Q/K/V projections in one launch (z selects input/weight/bias/output)
  gemm2<128,2,4,1,0,0><<<dim3(8,32,3), blk, SM_PROJ>>>(
      nullptr, Xh, Xl, DM, Wh, Wl, DM,
      bias3, nullptr, qkvh, qkvl, nullptr, nullptr, DM);

  // scores: exp(q@k^T/8) -> attn (fp32) + row partial sums
  gemm2<128,2,4,1,1,1><<<dim3(16,16,HEADS), blk, SM_SCORES>>>(
      nullptr, qkvh, qkvl, DK, qkvh + (size_t)QKVE, qkvl + (size_t)QKVE, DK,
      nullptr, attn, nullptr, nullptr, part, nullptr, DK);

  rowsum_inv_kernel<<<HEADS*SS/256, blk>>>(part, inv);

  // ctx: normalize attn on load (+writeback), attn@v, merge heads
  gemm2<64,4,2,2,0,2><<<dim3(1,16,HEADS), blk, SM_CTX>>>(
      attn, nullptr, nullptr, SS, qkvh + 2*(size_t)QKVE, qkvl + 2*(size_t)QKVE, DK,
      nullptr, nullptr, ch, cl, inv, attn, SS);

  // output projection (fp32 out + bias)
  gemm2<128,2,4,1,0,3><<<dim3(8,32), blk, SM_PROJ>>>(
      nullptr, ch, cl, DM, Wh + 3*(size_t)NWE, Wl + 3*(size_t)NWE, DM,
      bfc, out_f, nullptr, nullptr, nullptr, nullptr, DM);
}

// round 6
// speedup vs baseline: 2.6587x; 1.2199x over previous
#include <cuda_runtime.h>
#include <cuda_bf16.h>
#include <cstdint>

using bf16 = __nv_bfloat16;

#define BB 2
#define SS 2048
#define DM 1024
#define NH 16
#define DK 64
#define MROWS (BB*SS)       // 4096
#define HEADS (BB*NH)       // 32
#define NXE (MROWS*DM)      // 4194304
#define NWE (DM*DM)         // 1048576
#define QKVE (HEADS*SS*DK)  // 4194304

// ---------------- scratch (device globals; no allocations) ----------------
__device__ bf16 g_Xh[3*NXE], g_Xl[3*NXE];          // converted Q,K,V inputs
__device__ bf16 g_Wh[4*NWE], g_Wl[4*NWE];          // converted weights
__device__ bf16 g_qkvh[3*QKVE], g_qkvl[3*QKVE];    // q,k head-split; v TRANSPOSED [bh][dk][seq]
__device__ bf16 g_ch[MROWS*DM], g_cl[MROWS*DM];    // ctx (merged heads)
__device__ float g_bias3[3*DM];
__device__ float g_attn_fb[(size_t)HEADS*SS*SS];

// ---------------- helpers ----------------
__device__ __forceinline__ unsigned sptr(const void* p){
  return (unsigned)__cvta_generic_to_shared(p);
}
#define CP16(d,s) asm volatile("cp.async.cg.shared.global [%0], [%1], 16;\n" :: "r"(d), "l"(s))
#define CPCOMMIT() asm volatile("cp.async.commit_group;\n")
#define CPWAIT(N)  asm volatile("cp.async.wait_group %0;\n" :: "n"(N))

__device__ __forceinline__ unsigned pack2(bf16 x, bf16 y){
  __nv_bfloat162 t = __halves2bfloat162(x, y);
  return *reinterpret_cast<unsigned*>(&t);
}
__device__ __forceinline__ void split_bf16(float v, bf16& h, bf16& l){
  h = __float2bfloat16(v);
  l = __float2bfloat16(v - __bfloat162float(h));
}
__device__ __forceinline__ bf16 hi_bf16(float v){ return __float2bfloat16(v); }
__device__ __forceinline__ bf16 lo_bf16(float v){
  bf16 h = __float2bfloat16(v);
  return __float2bfloat16(v - __bfloat162float(h));
}
__device__ __forceinline__ void mma16(float c[4], const unsigned a[4], const unsigned b[2]){
  asm volatile(
    "mma.sync.aligned.m16n8k16.row.col.f32.bf16.bf16.f32 "
    "{%0,%1,%2,%3},{%4,%5,%6,%7},{%8,%9},{%0,%1,%2,%3};\n"
    : "+f"(c[0]), "+f"(c[1]), "+f"(c[2]), "+f"(c[3])
    : "r"(a[0]), "r"(a[1]), "r"(a[2]), "r"(a[3]), "r"(b[0]), "r"(b[1]));
}

// merged fp32 -> bf16 hi/lo converter for all 7 tensors (z selects)
__global__ void cvt7(const float* p0, const float* p1, const float* p2,
                     const float* p3, const float* p4, const float* p5,
                     const float* p6,
                     bf16* __restrict__ Xh, bf16* __restrict__ Xl,
                     bf16* __restrict__ Wh, bf16* __restrict__ Wl){
  const int z = blockIdx.z;
  const float* in = (z==0)?p0:(z==1)?p1:(z==2)?p2:(z==3)?p3:(z==4)?p4:(z==5)?p5:p6;
  const int n4 = ((z<3)?NXE:NWE)/4;
  bf16* hi = (z<3) ? Xh + (size_t)z*NXE : Wh + (size_t)(z-3)*NWE;
  bf16* lo = (z<3) ? Xl + (size_t)z*NXE : Wl + (size_t)(z-3)*NWE;
  const int i = blockIdx.x*blockDim.x + threadIdx.x;
  if (i >= n4) return;
  float4 v = ((const float4*)in)[i];
  bf16 h0,l0,h1,l1,h2,l2,h3,l3;
  split_bf16(v.x,h0,l0); split_bf16(v.y,h1,l1);
  split_bf16(v.z,h2,l2); split_bf16(v.w,h3,l3);
  uint2 uh, ul;
  uh.x = pack2(h0,h1); uh.y = pack2(h2,h3);
  ul.x = pack2(l0,l1); ul.y = pack2(l2,l3);
  ((uint2*)hi)[i] = uh;
  ((uint2*)lo)[i] = ul;
}

// ---------------------------------------------------------------------------
// bf16 split-3 GEMM for projections / out-projection.
// A,B bf16 hi/lo pairs in gmem, cp.async 3-stage, BM=128 BN=128 BK=32.
// EPI 0: proj (z-indexed; q,k head-split; V TRANSPOSED per head)
// EPI 3: out-proj (bias, fp32 out)
// ---------------------------------------------------------------------------
template<int EPI>
__global__ void __launch_bounds__(256,2)
gemm2(const bf16* __restrict__ Ahp, const bf16* __restrict__ Alp,
      const bf16* __restrict__ Bhp, const bf16* __restrict__ Blp,
      const float* __restrict__ biasp,
      float* __restrict__ outf, bf16* __restrict__ outhp, bf16* __restrict__ outlp)
{
  constexpr int BM=128, BN=128, BK=32, STAGES=3;
  constexpr int PK=40, PBN=BN+8;
  constexpr int WM=64, WN=32, MF=4, NF=4;   // 2x4 warps

  extern __shared__ bf16 smx[];
  bf16* sAh = smx;
  bf16* sAl = sAh + STAGES*BM*PK;
  bf16* sBh = sAl + STAGES*BM*PK;
  bf16* sBl = sBh + STAGES*BK*PBN;

  const int tid=threadIdx.x, lane=tid&31, wid=tid>>5;
  const int g=lane>>2, tg=lane&3;
  const int warp_m=wid>>2, warp_n=wid&3;
  const int wm=warp_m*WM, wn=warp_n*WN;
  const int m0=blockIdx.y*BM, n0=blockIdx.x*BN, bh_=blockIdx.z;

  const bf16 *Ah=Ahp, *Al=Alp, *Bh=Bhp, *Bl=Blp;
  const float* bias = biasp;
  bf16 *outh=outhp, *outl=outlp;
  if constexpr (EPI==0){
    Ah += (size_t)bh_*NXE;  Al += (size_t)bh_*NXE;
    Bh += (size_t)bh_*NWE;  Bl += (size_t)bh_*NWE;
    bias += bh_*DM;
    outh += (size_t)bh_*QKVE; outl += (size_t)bh_*QKVE;
  }

  const int ar=tid>>1, acA=(tid&1)*16;
  const int brB=tid>>3, bcB=(tid&7)*16;

  float acc[MF][NF][4];
#pragma unroll
  for (int mi=0;mi<MF;mi++)
#pragma unroll
    for (int ni=0;ni<NF;ni++)
#pragma unroll
      for (int q=0;q<4;q++) acc[mi][ni][q]=0.f;

  const int T = DM/BK;

  auto issue = [&](int t){
    const int st = t % STAGES;
    const int k0 = t*BK;
    const bf16* s = Ah + (size_t)(m0+ar)*DM + k0 + acA;
    unsigned d = sptr(sAh + ((size_t)st*BM+ar)*PK + acA);
    CP16(d, s); CP16(d+16, s+8);
    const bf16* s2 = Al + (size_t)(m0+ar)*DM + k0 + acA;
    unsigned d2 = sptr(sAl + ((size_t)st*BM+ar)*PK + acA);
    CP16(d2, s2); CP16(d2+16, s2+8);
    const bf16* s3 = Bh + (size_t)(k0+brB)*DM + n0 + bcB;
    unsigned d3 = sptr(sBh + ((size_t)st*BK+brB)*PBN + bcB);
    CP16(d3, s3); CP16(d3+16, s3+8);
    const bf16* s4 = Bl + (size_t)(k0+brB)*DM + n0 + bcB;
    unsigned d4 = sptr(sBl + ((size_t)st*BK+brB)*PBN + bcB);
    CP16(d4, s4); CP16(d4+16, s4+8);
    CPCOMMIT();
  };

  auto compute = [&](int st){
#pragma unroll
    for (int s16=0; s16<2; s16++){
      unsigned ah[MF][4], al[MF][4], bh[NF][2], bl[NF][2];
#pragma unroll
      for (int mi=0;mi<MF;mi++){
        const int r = wm + mi*16 + g;
        const unsigned* rh0 = (const unsigned*)(sAh + ((size_t)st*BM + r  )*PK);
        const unsigned* rh1 = (const unsigned*)(sAh + ((size_t)st*BM + r+8)*PK);
        const unsigned* rl0 = (const unsigned*)(sAl + ((size_t)st*BM + r  )*PK);
        const unsigned* rl1 = (const unsigned*)(sAl + ((size_t)st*BM + r+8)*PK);
        const int q0 = s16*8 + tg;
        ah[mi][0]=rh0[q0];   ah[mi][1]=rh1[q0];
        ah[mi][2]=rh0[q0+4]; ah[mi][3]=rh1[q0+4];
        al[mi][0]=rl0[q0];   al[mi][1]=rl1[q0];
        al[mi][2]=rl0[q0+4]; al[mi][3]=rl1[q0+4];
      }
#pragma unroll
      for (int ni=0;ni<NF;ni++){
        const int c = wn + ni*8 + g;
        const int kk = s16*16;
        const bf16* bb = sBh + ((size_t)st*BK)*PBN;
        const bf16* ll = sBl + ((size_t)st*BK)*PBN;
        bh[ni][0]=pack2(bb[(kk+2*tg  )*PBN+c], bb[(kk+2*tg+1)*PBN+c]);
        bh[ni][1]=pack2(bb[(kk+2*tg+8)*PBN+c], bb[(kk+2*tg+9)*PBN+c]);
        bl[ni][0]=pack2(ll[(kk+2*tg  )*PBN+c], ll[(kk+2*tg+1)*PBN+c]);
        bl[ni][1]=pack2(ll[(kk+2*tg+8)*PBN+c], ll[(kk+2*tg+9)*PBN+c]);
      }
#pragma unroll
      for (int mi=0;mi<MF;mi++)
#pragma unroll
        for (int ni=0;ni<NF;ni++){
          mma16(acc[mi][ni], ah[mi], bh[ni]);
          mma16(acc[mi][ni], al[mi], bh[ni]);
          mma16(acc[mi][ni], ah[mi], bl[ni]);
        }
    }
  };

  issue(0); issue(1);
  for (int t=0;t<T;t++){
    if (t < T-1) { CPWAIT(1); } else { CPWAIT(0); }
    __syncthreads();
    if (t+2 < T) issue(t+2);
    compute(t % STAGES);
  }
  __syncthreads();

  if constexpr (EPI==0){
    const bool vdst = (bh_==2);
#pragma unroll
    for (int mi=0;mi<MF;mi++)
#pragma unroll
      for (int hf=0;hf<2;hf++){
        const int m = m0 + wm + mi*16 + g + hf*8;
        const int b = m >> 11, s = m & (SS-1);
#pragma unroll
        for (int ni=0;ni<NF;ni++){
          const int n = n0 + wn + ni*8 + tg*2;
          const int h = n >> 6, d = n & 63;
          float y0 = acc[mi][ni][hf*2+0] + bias[n];
          float y1 = acc[mi][ni][hf*2+1] + bias[n+1];
          if (!vdst){
            const size_t o = (((size_t)b*NH + h)*SS + s)*DK + d;
            *(unsigned*)(outh+o) = pack2(hi_bf16(y0), hi_bf16(y1));
            *(unsigned*)(outl+o) = pack2(lo_bf16(y0), lo_bf16(y1));
          } else {
            // V transposed: [bh][dk][seq]
            const size_t o0 = (((size_t)b*NH + h)*DK + d)*SS + s;
            const size_t o1 = o0 + SS;
            outh[o0]=hi_bf16(y0); outl[o0]=lo_bf16(y0);
            outh[o1]=hi_bf16(y1); outl[o1]=lo_bf16(y1);
          }
        }
      }
  } else {
#pragma unroll
    for (int mi=0;mi<MF;mi++)
#pragma unroll
      for (int hf=0;hf<2;hf++){
        const int m = m0 + wm + mi*16 + g + hf*8;
#pragma unroll
        for (int ni=0;ni<NF;ni++){
          const int n = n0 + wn + ni*8 + tg*2;
          float2 y;
          y.x = acc[mi][ni][hf*2+0] + bias[n];
          y.y = acc[mi][ni][hf*2+1] + bias[n+1];
          *(float2*)(outf + (size_t)m*DM + n) = y;
        }
      }
  }
}

// ---------------------------------------------------------------------------
// Fused attention: two sweeps over the KV sequence per (head, 128-row block).
// Sweep 1: S=qK^T, exp, in-warp row sums -> sInv.
// Sweep 2: recompute S, normalize, write final attn once, P@V in registers.
// 8 warps all in M (WM=16); each warp owns its 16 rows across full N.
// ---------------------------------------------------------------------------
__global__ void __launch_bounds__(256,2)
fused_attn(const bf16* __restrict__ qh_, const bf16* __restrict__ ql_,
           const bf16* __restrict__ kh_, const bf16* __restrict__ kl_,
           const bf16* __restrict__ vh_, const bf16* __restrict__ vl_,
           float* __restrict__ attn_, bf16* __restrict__ ch, bf16* __restrict__ cl)
{
  constexpr int PK=72, NBT=64, NB=SS/NBT;   // 32 kv-blocks
  extern __shared__ bf16 sm[];
  bf16* sQh = sm;                   // 128*72
  bf16* sQl = sQh + 128*PK;
  bf16* sKh = sQl + 128*PK;         // 2 stages * 64*72
  bf16* sKl = sKh + 2*64*PK;
  bf16* sVh = sKl + 2*64*PK;
  bf16* sVl = sVh + 2*64*PK;
  float* sInv = (float*)(sVl + 2*64*PK);   // 128 floats

  const int tid=threadIdx.x, lane=tid&31;
  const int g=lane>>2, tg=lane&3;
  const int wm = (tid>>5)*16;
  const int m0 = blockIdx.x*128;
  const int bh = blockIdx.y;

  const bf16* qh = qh_ + (size_t)(bh*SS+m0)*DK;
  const bf16* ql = ql_ + (size_t)(bh*SS+m0)*DK;
  const bf16* kh = kh_ + (size_t)bh*SS*DK;
  const bf16* kl = kl_ + (size_t)bh*SS*DK;
  const bf16* vh = vh_ + (size_t)bh*DK*SS;   // transposed [dk][seq]
  const bf16* vl = vl_ + (size_t)bh*DK*SS;
  float* attn = attn_ + (size_t)bh*SS*SS;

  // ---- async staging ----
  auto issueQ = [&](){
    const int row=tid>>1, s0=(tid&1)*4;
    const bf16* sh = qh + (size_t)row*DK;
    const bf16* sl = ql + (size_t)row*DK;
    unsigned dh = sptr(sQh + row*PK);
    unsigned dl = sptr(sQl + row*PK);
#pragma unroll
    for (int s=s0;s<s0+4;s++){ CP16(dh+s*16, sh+s*8); CP16(dl+s*16, sl+s*8); }
  };
  auto issueK = [&](int nb,int st){
    const int row=tid>>2, s=tid&3;
    const bf16* sh = kh + (size_t)(nb*NBT+row)*DK;
    const bf16* sl = kl + (size_t)(nb*NBT+row)*DK;
    unsigned dh = sptr(sKh + (st*64+row)*PK);
    unsigned dl = sptr(sKl + (st*64+row)*PK);
    CP16(dh+s*16, sh+s*8);  CP16(dh+(s+4)*16, sh+(s+4)*8);
    CP16(dl+s*16, sl+s*8);  CP16(dl+(s+4)*16, sl+(s+4)*8);
  };
  auto issueV = [&](int nb,int st){
    const int row=tid>>2, s=tid&3;   // row = dk index
    const bf16* sh = vh + (size_t)row*SS + nb*NBT;
    const bf16* sl = vl + (size_t)row*SS + nb*NBT;
    unsigned dh = sptr(sVh + (st*64+row)*PK);
    unsigned dl = sptr(sVl + (st*64+row)*PK);
    CP16(dh+s*16, sh+s*8);  CP16(dh+(s+4)*16, sh+(s+4)*8);
    CP16(dl+s*16, sl+s*8);  CP16(dl+(s+4)*16, sl+(s+4)*8);
  };

  // ---- S = q @ k^T for one kv-block (sacc[ni][4], ni over 8 n8-groups) ----
  auto computeS = [&](int st, float sacc[8][4]){
#pragma unroll
    for (int ni=0;ni<8;ni++)
#pragma unroll
      for (int q=0;q<4;q++) sacc[ni][q]=0.f;
    const unsigned* q0h = (const unsigned*)(sQh + (wm+g)*PK);
    const unsigned* q1h = (const unsigned*)(sQh + (wm+g+8)*PK);
    const unsigned* q0l = (const unsigned*)(sQl + (wm+g)*PK);
    const unsigned* q1l = (const unsigned*)(sQl + (wm+g+8)*PK);
#pragma unroll
    for (int kk=0;kk<4;kk++){
      unsigned ah[4], al[4];
      ah[0]=q0h[kk*8+tg];   ah[1]=q1h[kk*8+tg];
      ah[2]=q0h[kk*8+tg+4]; ah[3]=q1h[kk*8+tg+4];
      al[0]=q0l[kk*8+tg];   al[1]=q1l[kk*8+tg];
      al[2]=q0l[kk*8+tg+4]; al[3]=q1l[kk*8+tg+4];
#pragma unroll
      for (int ni=0;ni<8;ni++){
        const unsigned* kp  = (const unsigned*)(sKh + (st*64 + 8*ni + g)*PK);
        const unsigned* kpl = (const unsigned*)(sKl + (st*64 + 8*ni + g)*PK);
        unsigned bh2[2], bl2[2];
        bh2[0]=kp[kk*8+tg];  bh2[1]=kp[kk*8+tg+4];
        bl2[0]=kpl[kk*8+tg]; bl2[1]=kpl[kk*8+tg+4];
        mma16(sacc[ni], ah, bh2);
        mma16(sacc[ni], al, bh2);
        mma16(sacc[ni], ah, bl2);
      }
    }
  };

  // ================= Sweep 1: row sums =================
  issueQ(); CPCOMMIT();
  issueK(0,0); CPCOMMIT();
  float rs0=0.f, rs1=0.f;
  for (int nb=0;nb<NB;nb++){
    if (nb+1<NB){ issueK(nb+1,(nb+1)&1); CPCOMMIT(); CPWAIT(1); }
    else        { CPWAIT(0); }
    __syncthreads();
    float sacc[8][4];
    computeS(nb&1, sacc);
#pragma unroll
    for (int ni=0;ni<8;ni++){
      rs0 += __expf(sacc[ni][0]*0.125f) + __expf(sacc[ni][1]*0.125f);
      rs1 += __expf(sacc[ni][2]*0.125f) + __expf(sacc[ni][3]*0.125f);
    }
    __syncthreads();
  }
  rs0 += __shfl_xor_sync(0xffffffffu, rs0, 1);
  rs0 += __shfl_xor_sync(0xffffffffu, rs0, 2);
  rs1 += __shfl_xor_sync(0xffffffffu, rs1, 1);
  rs1 += __shfl_xor_sync(0xffffffffu, rs1, 2);
  if (tg==0){ sInv[wm+g] = 1.0f/rs0; sInv[wm+g+8] = 1.0f/rs1; }
  __syncthreads();
  const float inv0 = sInv[wm+g];
  const float inv1 = sInv[wm+g+8];

  // ================= Sweep 2: normalized attn + P@V =================
  float cacc[8][4];
#pragma unroll
  for (int ci=0;ci<8;ci++)
#pragma unroll
    for (int q=0;q<4;q++) cacc[ci][q]=0.f;

  issueK(0,0); issueV(0,0); CPCOMMIT();
  for (int nb=0;nb<NB;nb++){
    if (nb+1<NB){ issueK(nb+1,(nb+1)&1); issueV(nb+1,(nb+1)&1); CPCOMMIT(); CPWAIT(1); }
    else        { CPWAIT(0); }
    __syncthreads();
    const int st = nb&1;
    float sacc[8][4];
    computeS(st, sacc);

    // normalize + write final attention (single store of 537MB total)
    float* arow0 = attn + (size_t)(m0+wm+g)*SS + nb*NBT;
    float* arow1 = arow0 + 8*SS;
#pragma unroll
    for (int ni=0;ni<8;ni++){
      float e0 = __expf(sacc[ni][0]*0.125f)*inv0;
      float e1 = __expf(sacc[ni][1]*0.125f)*inv0;
      float e2 = __expf(sacc[ni][2]*0.125f)*inv1;
      float e3 = __expf(sacc[ni][3]*0.125f)*inv1;
      sacc[ni][0]=e0; sacc[ni][1]=e1; sacc[ni][2]=e2; sacc[ni][3]=e3;
      float2 lo2; lo2.x=e0; lo2.y=e1;
      float2 hi2; hi2.x=e2; hi2.y=e3;
      __stcs((float2*)(arow0 + ni*8 + tg*2), lo2);
      __stcs((float2*)(arow1 + ni*8 + tg*2), hi2);
    }

    // P@V: A-fragments built directly from sacc (C-frag == A-frag identity)
#pragma unroll
    for (int kk=0;kk<4;kk++){
      const int f0=2*kk, f1=2*kk+1;
      unsigned pah[4], pal[4];
      pah[0]=pack2(hi_bf16(sacc[f0][0]), hi_bf16(sacc[f0][1]));
      pah[1]=pack2(hi_bf16(sacc[f0][2]), hi_bf16(sacc[f0][3]));
      pah[2]=pack2(hi_bf16(sacc[f1][0]), hi_bf16(sacc[f1][1]));
      pah[3]=pack2(hi_bf16(sacc[f1][2]), hi_bf16(sacc[f1][3]));
      pal[0]=pack2(lo_bf16(sacc[f0][0]), lo_bf16(sacc[f0][1]));
      pal[1]=pack2(lo_bf16(sacc[f0][2]), lo_bf16(sacc[f0][3]));
      pal[2]=pack2(lo_bf16(sacc[f1][0]), lo_bf16(sacc[f1][1]));
      pal[3]=pack2(lo_bf16(sacc[f1][2]), lo_bf16(sacc[f1][3]));
#pragma unroll
      for (int ci=0;ci<8;ci++){
        const unsigned* vp  = (const unsigned*)(sVh + (st*64 + 8*ci + g)*PK);
        const unsigned* vpl = (const unsigned*)(sVl + (st*64 + 8*ci + g)*PK);
        unsigned vbh[2], vbl[2];
        vbh[0]=vp[kk*8+tg];  vbh[1]=vp[kk*8+tg+4];
        vbl[0]=vpl[kk*8+tg]; vbl[1]=vpl[kk*8+tg+4];
        mma16(cacc[ci], pah, vbh);
        mma16(cacc[ci], pal, vbh);
        mma16(cacc[ci], pah, vbl);
      }
    }
    __syncthreads();
  }

  // ---- ctx epilogue: merge heads, bf16 hi/lo pairs ----
  const int b = bh>>4, h = bh&(NH-1);
#pragma unroll
  for (int ci=0;ci<8;ci++){
    const int d = h*DK + ci*8 + tg*2;
    const size_t o0 = ((size_t)(b*SS + m0+wm+g))*DM + d;
    const size_t o1 = o0 + (size_t)8*DM;
    *(unsigned*)(ch+o0) = pack2(hi_bf16(cacc[ci][0]), hi_bf16(cacc[ci][1]));
    *(unsigned*)(cl+o0) = pack2(lo_bf16(cacc[ci][0]), lo_bf16(cacc[ci][1]));
    *(unsigned*)(ch+o1) = pack2(hi_bf16(cacc[ci][2]), hi_bf16(cacc[ci][3]));
    *(unsigned*)(cl+o1) = pack2(lo_bf16(cacc[ci][2]), lo_bf16(cacc[ci][3]));
  }
}

extern "C" void kernel_launch(void* const* d_in, const int* in_sizes, int n_in,
                              void* d_out, int out_size){
  const float* Q   = (const float*)d_in[0];
  const float* K   = (const float*)d_in[1];
  const float* V   = (const float*)d_in[2];
  const float* Wq  = (const float*)d_in[3];
  const float* bq  = (const float*)d_in[4];
  const float* Wk  = (const float*)d_in[5];
  const float* bk  = (const float*)d_in[6];
  const float* Wv  = (const float*)d_in[7];
  const float* bv  = (const float*)d_in[8];
  const float* Wfc = (const float*)d_in[9];
  const float* bfc = (const float*)d_in[10];
  float* out_f = (float*)d_out;

  bf16 *Xh,*Xl,*Wh,*Wl,*qkvh,*qkvl,*ch,*cl;
  float *bias3,*afb;
  cudaGetSymbolAddress((void**)&Xh, g_Xh);   cudaGetSymbolAddress((void**)&Xl, g_Xl);
  cudaGetSymbolAddress((void**)&Wh, g_Wh);   cudaGetSymbolAddress((void**)&Wl, g_Wl);
  cudaGetSymbolAddress((void**)&qkvh, g_qkvh); cudaGetSymbolAddress((void**)&qkvl, g_qkvl);
  cudaGetSymbolAddress((void**)&ch, g_ch);   cudaGetSymbolAddress((void**)&cl, g_cl);
  cudaGetSymbolAddress((void**)&bias3, g_bias3);
  cudaGetSymbolAddress((void**)&afb,  g_attn_fb);

  const size_t ATTN = (size_t)HEADS*SS*SS;
  float* attn = ((size_t)out_size >= ATTN) ? (out_f + ((size_t)out_size - ATTN)) : afb;

  // smem sizes (bytes)
  const int SM_PROJ  = 3*128*40*2*2 + 3*32*136*2*2;                 // 113664
  const int SM_FUSED = (2*128*72 + 4*64*72 + 4*64*72)*2 + 128*4;    // 111104

  cudaFuncSetAttribute(gemm2<0>, cudaFuncAttributeMaxDynamicSharedMemorySize, SM_PROJ);
  cudaFuncSetAttribute(gemm2<3>, cudaFuncAttributeMaxDynamicSharedMemorySize, SM_PROJ);
  cudaFuncSetAttribute(fused_attn, cudaFuncAttributeMaxDynamicSharedMemorySize, SM_FUSED);

  dim3 blk(256);

  cudaMemcpyAsync(bias3,        bq, DM*sizeof(float), cudaMemcpyDeviceToDevice);
  cudaMemcpyAsync(bias3 + DM,   bk, DM*sizeof(float), cudaMemcpyDeviceToDevice);
  cudaMemcpyAsync(bias3 + 2*DM, bv, DM*sizeof(float), cudaMemcpyDeviceToDevice);

  cvt7<<<dim3(NXE/4/256,1,7), blk>>>(Q,K,V,Wq,Wk,Wv,Wfc, Xh,Xl,Wh,Wl);

  // Q/K/V projections (z: 0=q head-split, 1=k head-split, 2=v transposed)
  gemm2<0><<<dim3(8,32,3), blk, SM_PROJ>>>(
      Xh, Xl, Wh, Wl, bias3, nullptr, qkvh, qkvl);

  // fused attention: rowsums sweep + normalized-attn + P@V sweep
  fused_attn<<<dim3(SS/128, HEADS), blk, SM_FUSED>>>(
      qkvh, qkvl,
      qkvh + (size_t)QKVE, qkvl + (size_t)QKVE,
      qkvh + 2*(size_t)QKVE, qkvl + 2*(size_t)QKVE,
      attn, ch, cl);

  // output projection
  gemm2<3><<<dim3(8,32), blk, SM_PROJ>>>(
      ch, cl, Wh + 3*(size_t)NWE, Wl + 3*(size_t)NWE, bfc, out_f, nullptr, nullptr);
}

// round 7
// speedup vs baseline: 2.7648x; 1.0399x over previous
#include <cuda_runtime.h>
#include <cuda_bf16.h>
#include <cstdint>

using bf16 = __nv_bfloat16;

#define BB 2
#define SS 2048
#define DM 1024
#define NH 16
#define DK 64
#define MROWS (BB*SS)       // 4096
#define HEADS (BB*NH)       // 32
#define NXE (MROWS*DM)      // 4194304
#define NWE (DM*DM)         // 1048576
#define QKVE (HEADS*SS*DK)  // 4194304

// ---------------- scratch (device globals; no allocations) ----------------
__device__ bf16 g_Xh[3*NXE], g_Xl[3*NXE];          // converted Q,K,V inputs
__device__ bf16 g_Wth[4*NWE], g_Wtl[4*NWE];        // TRANSPOSED weights [N][K]
__device__ bf16 g_qkvh[3*QKVE], g_qkvl[3*QKVE];    // q,k head-split; v TRANSPOSED [bh][dk][seq]
__device__ bf16 g_ch[MROWS*DM], g_cl[MROWS*DM];    // ctx (merged heads)
__device__ float g_bias3[3*DM];
__device__ float g_attn_fb[(size_t)HEADS*SS*SS];

// ---------------- helpers ----------------
__device__ __forceinline__ unsigned sptr(const void* p){
  return (unsigned)__cvta_generic_to_shared(p);
}
#define CP16(d,s) asm volatile("cp.async.cg.shared.global [%0], [%1], 16;\n" :: "r"(d), "l"(s))
#define CPCOMMIT() asm volatile("cp.async.commit_group;\n")
#define CPWAIT(N)  asm volatile("cp.async.wait_group %0;\n" :: "n"(N))

__device__ __forceinline__ unsigned pack2(bf16 x, bf16 y){
  __nv_bfloat162 t = __halves2bfloat162(x, y);
  return *reinterpret_cast<unsigned*>(&t);
}
__device__ __forceinline__ void split_bf16(float v, bf16& h, bf16& l){
  h = __float2bfloat16(v);
  l = __float2bfloat16(v - __bfloat162float(h));
}
__device__ __forceinline__ bf16 hi_bf16(float v){ return __float2bfloat16(v); }
__device__ __forceinline__ bf16 lo_bf16(float v){
  bf16 h = __float2bfloat16(v);
  return __float2bfloat16(v - __bfloat162float(h));
}
__device__ __forceinline__ void mma16(float c[4], const unsigned a[4], const unsigned b[2]){
  asm volatile(
    "mma.sync.aligned.m16n8k16.row.col.f32.bf16.bf16.f32 "
    "{%0,%1,%2,%3},{%4,%5,%6,%7},{%8,%9},{%0,%1,%2,%3};\n"
    : "+f"(c[0]), "+f"(c[1]), "+f"(c[2]), "+f"(c[3])
    : "r"(a[0]), "r"(a[1]), "r"(a[2]), "r"(a[3]), "r"(b[0]), "r"(b[1]));
}

// fp32 -> bf16 hi/lo for the 3 input tensors (z selects)
__global__ void cvtX(const float* p0, const float* p1, const float* p2,
                     bf16* __restrict__ Xh, bf16* __restrict__ Xl){
  const int z = blockIdx.z;
  const float* in = (z==0)?p0:(z==1)?p1:p2;
  bf16* hi = Xh + (size_t)z*NXE;
  bf16* lo = Xl + (size_t)z*NXE;
  const int i = blockIdx.x*blockDim.x + threadIdx.x;
  float4 v = ((const float4*)in)[i];
  bf16 h0,l0,h1,l1,h2,l2,h3,l3;
  split_bf16(v.x,h0,l0); split_bf16(v.y,h1,l1);
  split_bf16(v.z,h2,l2); split_bf16(v.w,h3,l3);
  uint2 uh, ul;
  uh.x = pack2(h0,h1); uh.y = pack2(h2,h3);
  ul.x = pack2(l0,l1); ul.y = pack2(l2,l3);
  ((uint2*)hi)[i] = uh;
  ((uint2*)lo)[i] = ul;
}

// fp32 W[K][N] -> TRANSPOSED bf16 hi/lo Wt[N][K] (smem tile transpose)
__global__ void cvtWt(const float* p0, const float* p1, const float* p2, const float* p3,
                      bf16* __restrict__ Wth, bf16* __restrict__ Wtl){
  __shared__ float t[32][33];
  const int z = blockIdx.z;
  const float* in = (z==0)?p0:(z==1)?p1:(z==2)?p2:p3;
  bf16* hi = Wth + (size_t)z*NWE;
  bf16* lo = Wtl + (size_t)z*NWE;
  const int tx = threadIdx.x, ty = threadIdx.y;
  const int n0 = blockIdx.x*32, k0 = blockIdx.y*32;
#pragma unroll
  for (int i=0;i<4;i++){
    const int k = ty + 8*i;
    t[k][tx] = in[(size_t)(k0+k)*DM + n0 + tx];   // t[k_local][n_local]
  }
  __syncthreads();
#pragma unroll
  for (int i=0;i<4;i++){
    const int n = ty + 8*i;
    const float v = t[tx][n];                      // Wt[n][k] = W[k][n]
    const size_t o = (size_t)(n0+n)*DM + k0 + tx;
    hi[o] = hi_bf16(v);
    lo[o] = lo_bf16(v);
  }
}

// ---------------------------------------------------------------------------
// bf16 split-3 GEMM: C = A @ Wt^T. A [M,1024] K-contig, Wt [1024,1024] K-contig.
// BM=BN=128, BK=32, 2-stage cp.async, 256 threads, 2 CTAs/SM.
// EPI 0: proj (z-indexed; q,k head-split; V transposed). EPI 3: out-proj.
// ---------------------------------------------------------------------------
template<int EPI>
__global__ void __launch_bounds__(256,2)
gemmW(const bf16* __restrict__ Ahp, const bf16* __restrict__ Alp,
      const bf16* __restrict__ Bhp, const bf16* __restrict__ Blp,
      const float* __restrict__ biasp,
      float* __restrict__ outf, bf16* __restrict__ outhp, bf16* __restrict__ outlp)
{
  constexpr int BM=128, BN=128, BK=32, STAGES=2, PK=40;
  constexpr int WM=64, WN=32, MF=4, NF=4;   // 2x4 warps

  extern __shared__ bf16 smx[];
  bf16* sAh = smx;
  bf16* sAl = sAh + STAGES*BM*PK;
  bf16* sBh = sAl + STAGES*BM*PK;
  bf16* sBl = sBh + STAGES*BN*PK;

  const int tid=threadIdx.x, lane=tid&31, wid=tid>>5;
  const int g=lane>>2, tg=lane&3;
  const int warp_m=wid>>2, warp_n=wid&3;
  const int wm=warp_m*WM, wn=warp_n*WN;
  const int m0=blockIdx.y*BM, n0=blockIdx.x*BN, bh_=blockIdx.z;

  const bf16 *Ah=Ahp, *Al=Alp, *Bh=Bhp, *Bl=Blp;
  const float* bias = biasp;
  bf16 *outh=outhp, *outl=outlp;
  if constexpr (EPI==0){
    Ah += (size_t)bh_*NXE;  Al += (size_t)bh_*NXE;
    Bh += (size_t)bh_*NWE;  Bl += (size_t)bh_*NWE;
    bias += bh_*DM;
    outh += (size_t)bh_*QKVE; outl += (size_t)bh_*QKVE;
  }

  const int ar=tid>>1, ac=(tid&1)*16;   // A: 128 rows x 32 k
  // B identical mapping (128 rows x 32 k)

  float acc[MF][NF][4];
#pragma unroll
  for (int mi=0;mi<MF;mi++)
#pragma unroll
    for (int ni=0;ni<NF;ni++)
#pragma unroll
      for (int q=0;q<4;q++) acc[mi][ni][q]=0.f;

  const int T = DM/BK;   // 32

  auto issue = [&](int t){
    const int st = t & 1;
    const int k0 = t*BK;
    const bf16* s = Ah + (size_t)(m0+ar)*DM + k0 + ac;
    unsigned d = sptr(sAh + ((size_t)st*BM+ar)*PK + ac);
    CP16(d, s); CP16(d+16, s+8);
    const bf16* s2 = Al + (size_t)(m0+ar)*DM + k0 + ac;
    unsigned d2 = sptr(sAl + ((size_t)st*BM+ar)*PK + ac);
    CP16(d2, s2); CP16(d2+16, s2+8);
    const bf16* s3 = Bh + (size_t)(n0+ar)*DM + k0 + ac;
    unsigned d3 = sptr(sBh + ((size_t)st*BN+ar)*PK + ac);
    CP16(d3, s3); CP16(d3+16, s3+8);
    const bf16* s4 = Bl + (size_t)(n0+ar)*DM + k0 + ac;
    unsigned d4 = sptr(sBl + ((size_t)st*BN+ar)*PK + ac);
    CP16(d4, s4); CP16(d4+16, s4+8);
    CPCOMMIT();
  };

  auto compute = [&](int st){
#pragma unroll
    for (int s16=0; s16<2; s16++){
      const int q0 = s16*8 + tg;
      unsigned ah[MF][4], al[MF][4], bh[NF][2], bl[NF][2];
#pragma unroll
      for (int mi=0;mi<MF;mi++){
        const int r = wm + mi*16 + g;
        const unsigned* rh0 = (const unsigned*)(sAh + ((size_t)st*BM + r  )*PK);
        const unsigned* rh1 = (const unsigned*)(sAh + ((size_t)st*BM + r+8)*PK);
        const unsigned* rl0 = (const unsigned*)(sAl + ((size_t)st*BM + r  )*PK);
        const unsigned* rl1 = (const unsigned*)(sAl + ((size_t)st*BM + r+8)*PK);
        ah[mi][0]=rh0[q0];   ah[mi][1]=rh1[q0];
        ah[mi][2]=rh0[q0+4]; ah[mi][3]=rh1[q0+4];
        al[mi][0]=rl0[q0];   al[mi][1]=rl1[q0];
        al[mi][2]=rl0[q0+4]; al[mi][3]=rl1[q0+4];
      }
#pragma unroll
      for (int ni=0;ni<NF;ni++){
        const int c = wn + ni*8 + g;
        const unsigned* ch = (const unsigned*)(sBh + ((size_t)st*BN + c)*PK);
        const unsigned* cl = (const unsigned*)(sBl + ((size_t)st*BN + c)*PK);
        bh[ni][0]=ch[q0]; bh[ni][1]=ch[q0+4];
        bl[ni][0]=cl[q0]; bl[ni][1]=cl[q0+4];
      }
#pragma unroll
      for (int mi=0;mi<MF;mi++)
#pragma unroll
        for (int ni=0;ni<NF;ni++){
          mma16(acc[mi][ni], ah[mi], bh[ni]);
          mma16(acc[mi][ni], al[mi], bh[ni]);
          mma16(acc[mi][ni], ah[mi], bl[ni]);
        }
    }
  };

  issue(0);
  for (int t=0;t<T;t++){
    if (t+1<T){ issue(t+1); CPWAIT(1); } else { CPWAIT(0); }
    __syncthreads();
    compute(t & 1);
    __syncthreads();
  }

  if constexpr (EPI==0){
    const bool vdst = (bh_==2);
#pragma unroll
    for (int mi=0;mi<MF;mi++)
#pragma unroll
      for (int hf=0;hf<2;hf++){
        const int m = m0 + wm + mi*16 + g + hf*8;
        const int b = m >> 11, s = m & (SS-1);
#pragma unroll
        for (int ni=0;ni<NF;ni++){
          const int n = n0 + wn + ni*8 + tg*2;
          const int h = n >> 6, d = n & 63;
          float y0 = acc[mi][ni][hf*2+0] + bias[n];
          float y1 = acc[mi][ni][hf*2+1] + bias[n+1];
          if (!vdst){
            const size_t o = (((size_t)b*NH + h)*SS + s)*DK + d;
            *(unsigned*)(outh+o) = pack2(hi_bf16(y0), hi_bf16(y1));
            *(unsigned*)(outl+o) = pack2(lo_bf16(y0), lo_bf16(y1));
          } else {
            const size_t o0 = (((size_t)b*NH + h)*DK + d)*SS + s;
            const size_t o1 = o0 + SS;
            outh[o0]=hi_bf16(y0); outl[o0]=lo_bf16(y0);
            outh[o1]=hi_bf16(y1); outl[o1]=lo_bf16(y1);
          }
        }
      }
  } else {
#pragma unroll
    for (int mi=0;mi<MF;mi++)
#pragma unroll
      for (int hf=0;hf<2;hf++){
        const int m = m0 + wm + mi*16 + g + hf*8;
#pragma unroll
        for (int ni=0;ni<NF;ni++){
          const int n = n0 + wn + ni*8 + tg*2;
          float2 y;
          y.x = acc[mi][ni][hf*2+0] + bias[n];
          y.y = acc[mi][ni][hf*2+1] + bias[n+1];
          *(float2*)(outf + (size_t)m*DM + n) = y;
        }
      }
  }
}

// ---------------------------------------------------------------------------
// Fused attention. Sweep 1: hi-only single-MMA S -> exp -> row sums (normalizer
// needs only ~1e-4 accuracy). Sweep 2: split-3 S, normalize, single attn write,
// P@V in registers. 8 warps all-M (WM=16).
// ---------------------------------------------------------------------------
__global__ void __launch_bounds__(256,2)
fused_attn(const bf16* __restrict__ qh_, const bf16* __restrict__ ql_,
           const bf16* __restrict__ kh_, const bf16* __restrict__ kl_,
           const bf16* __restrict__ vh_, const bf16* __restrict__ vl_,
           float* __restrict__ attn_, bf16* __restrict__ ch, bf16* __restrict__ cl)
{
  constexpr int PK=72, NBT=64, NB=SS/NBT;
  extern __shared__ bf16 sm[];
  bf16* sQh = sm;
  bf16* sQl = sQh + 128*PK;
  bf16* sKh = sQl + 128*PK;
  bf16* sKl = sKh + 2*64*PK;
  bf16* sVh = sKl + 2*64*PK;
  bf16* sVl = sVh + 2*64*PK;
  float* sInv = (float*)(sVl + 2*64*PK);

  const int tid=threadIdx.x, lane=tid&31;
  const int g=lane>>2, tg=lane&3;
  const int wm = (tid>>5)*16;
  const int m0 = blockIdx.x*128;
  const int bh = blockIdx.y;

  const bf16* qh = qh_ + (size_t)(bh*SS+m0)*DK;
  const bf16* ql = ql_ + (size_t)(bh*SS+m0)*DK;
  const bf16* kh = kh_ + (size_t)bh*SS*DK;
  const bf16* kl = kl_ + (size_t)bh*SS*DK;
  const bf16* vh = vh_ + (size_t)bh*DK*SS;
  const bf16* vl = vl_ + (size_t)bh*DK*SS;
  float* attn = attn_ + (size_t)bh*SS*SS;

  auto issueQ = [&](){
    const int row=tid>>1, s0=(tid&1)*4;
    const bf16* sh = qh + (size_t)row*DK;
    const bf16* sl = ql + (size_t)row*DK;
    unsigned dh = sptr(sQh + row*PK);
    unsigned dl = sptr(sQl + row*PK);
#pragma unroll
    for (int s=s0;s<s0+4;s++){ CP16(dh+s*16, sh+s*8); CP16(dl+s*16, sl+s*8); }
  };
  auto issueK1 = [&](int nb,int st){    // hi only (sweep 1)
    const int row=tid>>2, s=tid&3;
    const bf16* sh = kh + (size_t)(nb*NBT+row)*DK;
    unsigned dh = sptr(sKh + (st*64+row)*PK);
    CP16(dh+s*16, sh+s*8);  CP16(dh+(s+4)*16, sh+(s+4)*8);
  };
  auto issueK = [&](int nb,int st){
    const int row=tid>>2, s=tid&3;
    const bf16* sh = kh + (size_t)(nb*NBT+row)*DK;
    const bf16* sl = kl + (size_t)(nb*NBT+row)*DK;
    unsigned dh = sptr(sKh + (st*64+row)*PK);
    unsigned dl = sptr(sKl + (st*64+row)*PK);
    CP16(dh+s*16, sh+s*8);  CP16(dh+(s+4)*16, sh+(s+4)*8);
    CP16(dl+s*16, sl+s*8);  CP16(dl+(s+4)*16, sl+(s+4)*8);
  };
  auto issueV = [&](int nb,int st){
    const int row=tid>>2, s=tid&3;
    const bf16* sh = vh + (size_t)row*SS + nb*NBT;
    const bf16* sl = vl + (size_t)row*SS + nb*NBT;
    unsigned dh = sptr(sVh + (st*64+row)*PK);
    unsigned dl = sptr(sVl + (st*64+row)*PK);
    CP16(dh+s*16, sh+s*8);  CP16(dh+(s+4)*16, sh+(s+4)*8);
    CP16(dl+s*16, sl+s*8);  CP16(dl+(s+4)*16, sl+(s+4)*8);
  };

  // split-3 S (sweep 2)
  auto computeS = [&](int st, float sacc[8][4]){
#pragma unroll
    for (int ni=0;ni<8;ni++)
#pragma unroll
      for (int q=0;q<4;q++) sacc[ni][q]=0.f;
    const unsigned* q0h = (const unsigned*)(sQh + (wm+g)*PK);
    const unsigned* q1h = (const unsigned*)(sQh + (wm+g+8)*PK);
    const unsigned* q0l = (const unsigned*)(sQl + (wm+g)*PK);
    const unsigned* q1l = (const unsigned*)(sQl + (wm+g+8)*PK);
#pragma unroll
    for (int kk=0;kk<4;kk++){
      unsigned ah[4], al[4];
      ah[0]=q0h[kk*8+tg];   ah[1]=q1h[kk*8+tg];
      ah[2]=q0h[kk*8+tg+4]; ah[3]=q1h[kk*8+tg+4];
      al[0]=q0l[kk*8+tg];   al[1]=q1l[kk*8+tg];
      al[2]=q0l[kk*8+tg+4]; al[3]=q1l[kk*8+tg+4];
#pragma unroll
      for (int ni=0;ni<8;ni++){
        const unsigned* kp  = (const unsigned*)(sKh + (st*64 + 8*ni + g)*PK);
        const unsigned* kpl = (const unsigned*)(sKl + (st*64 + 8*ni + g)*PK);
        unsigned bh2[2], bl2[2];
        bh2[0]=kp[kk*8+tg];  bh2[1]=kp[kk*8+tg+4];
        bl2[0]=kpl[kk*8+tg]; bl2[1]=kpl[kk*8+tg+4];
        mma16(sacc[ni], ah, bh2);
        mma16(sacc[ni], al, bh2);
        mma16(sacc[ni], ah, bl2);
      }
    }
  };
  // hi-only S (sweep 1: rowsums)
  auto computeS1 = [&](int st, float sacc[8][4]){
#pragma unroll
    for (int ni=0;ni<8;ni++)
#pragma unroll
      for (int q=0;q<4;q++) sacc[ni][q]=0.f;
    const unsigned* q0h = (const unsigned*)(sQh + (wm+g)*PK);
    const unsigned* q1h = (const unsigned*)(sQh + (wm+g+8)*PK);
#pragma unroll
    for (int kk=0;kk<4;kk++){
      unsigned ah[4];
      ah[0]=q0h[kk*8+tg];   ah[1]=q1h[kk*8+tg];
      ah[2]=q0h[kk*8+tg+4]; ah[3]=q1h[kk*8+tg+4];
#pragma unroll
      for (int ni=0;ni<8;ni++){
        const unsigned* kp = (const unsigned*)(sKh + (st*64 + 8*ni + g)*PK);
        unsigned bh2[2];
        bh2[0]=kp[kk*8+tg]; bh2[1]=kp[kk*8+tg+4];
        mma16(sacc[ni], ah, bh2);
      }
    }
  };

  // ================= Sweep 1: row sums (hi-only) =================
  issueQ(); CPCOMMIT();
  issueK1(0,0); CPCOMMIT();
  float rs0=0.f, rs1=0.f;
  for (int nb=0;nb<NB;nb++){
    if (nb+1<NB){ issueK1(nb+1,(nb+1)&1); CPCOMMIT(); CPWAIT(1); }
    else        { CPWAIT(0); }
    __syncthreads();
    float sacc[8][4];
    computeS1(nb&1, sacc);
#pragma unroll
    for (int ni=0;ni<8;ni++){
      rs0 += __expf(sacc[ni][0]*0.125f) + __expf(sacc[ni][1]*0.125f);
      rs1 += __expf(sacc[ni][2]*0.125f) + __expf(sacc[ni][3]*0.125f);
    }
    __syncthreads();
  }
  rs0 += __shfl_xor_sync(0xffffffffu, rs0, 1);
  rs0 += __shfl_xor_sync(0xffffffffu, rs0, 2);
  rs1 += __shfl_xor_sync(0xffffffffu, rs1, 1);
  rs1 += __shfl_xor_sync(0xffffffffu, rs1, 2);
  if (tg==0){ sInv[wm+g] = 1.0f/rs0; sInv[wm+g+8] = 1.0f/rs1; }
  __syncthreads();
  const float inv0 = sInv[wm+g];
  const float inv1 = sInv[wm+g+8];

  // ================= Sweep 2: normalized attn + P@V =================
  float cacc[8][4];
#pragma unroll
  for (int ci=0;ci<8;ci++)
#pragma unroll
    for (int q=0;q<4;q++) cacc[ci][q]=0.f;

  issueK(0,0); issueV(0,0); CPCOMMIT();
  for (int nb=0;nb<NB;nb++){
    if (nb+1<NB){ issueK(nb+1,(nb+1)&1); issueV(nb+1,(nb+1)&1); CPCOMMIT(); CPWAIT(1); }
    else        { CPWAIT(0); }
    __syncthreads();
    const int st = nb&1;
    float sacc[8][4];
    computeS(st, sacc);

    float* arow0 = attn + (size_t)(m0+wm+g)*SS + nb*NBT;
    float* arow1 = arow0 + 8*SS;
#pragma unroll
    for (int ni=0;ni<8;ni++){
      float e0 = __expf(sacc[ni][0]*0.125f)*inv0;
      float e1 = __expf(sacc[ni][1]*0.125f)*inv0;
      float e2 = __expf(sacc[ni][2]*0.125f)*inv1;
      float e3 = __expf(sacc[ni][3]*0.125f)*inv1;
      sacc[ni][0]=e0; sacc[ni][1]=e1; sacc[ni][2]=e2; sacc[ni][3]=e3;
      float2 lo2; lo2.x=e0; lo2.y=e1;
      float2 hi2; hi2.x=e2; hi2.y=e3;
      __stcs((float2*)(arow0 + ni*8 + tg*2), lo2);
      __stcs((float2*)(arow1 + ni*8 + tg*2), hi2);
    }

#pragma unroll
    for (int kk=0;kk<4;kk++){
      const int f0=2*kk, f1=2*kk+1;
      unsigned pah[4], pal[4];
      pah[0]=pack2(hi_bf16(sacc[f0][0]), hi_bf16(sacc[f0][1]));
      pah[1]=pack2(hi_bf16(sacc[f0][2]), hi_bf16(sacc[f0][3]));
      pah[2]=pack2(hi_bf16(sacc[f1][0]), hi_bf16(sacc[f1][1]));
      pah[3]=pack2(hi_bf16(sacc[f1][2]), hi_bf16(sacc[f1][3]));
      pal[0]=pack2(lo_bf16(sacc[f0][0]), lo_bf16(sacc[f0][1]));
      pal[1]=pack2(lo_bf16(sacc[f0][2]), lo_bf16(sacc[f0][3]));
      pal[2]=pack2(lo_bf16(sacc[f1][0]), lo_bf16(sacc[f1][1]));
      pal[3]=pack2(lo_bf16(sacc[f1][2]), lo_bf16(sacc[f1][3]));
#pragma unroll
      for (int ci=0;ci<8;ci++){
        const unsigned* vp  = (const unsigned*)(sVh + (st*64 + 8*ci + g)*PK);
        const unsigned* vpl = (const unsigned*)(sVl + (st*64 + 8*ci + g)*PK);
        unsigned vbh[2], vbl[2];
        vbh[0]=vp[kk*8+tg];  vbh[1]=vp[kk*8+tg+4];
        vbl[0]=vpl[kk*8+tg]; vbl[1]=vpl[kk*8+tg+4];
        mma16(cacc[ci], pah, vbh);
        mma16(cacc[ci], pal, vbh);
        mma16(cacc[ci], pah, vbl);
      }
    }
    __syncthreads();
  }

  const int b = bh>>4, h = bh&(NH-1);
#pragma unroll
  for (int ci=0;ci<8;ci++){
    const int d = h*DK + ci*8 + tg*2;
    const size_t o0 = ((size_t)(b*SS + m0+wm+g))*DM + d;
    const size_t o1 = o0 + (size_t)8*DM;
    *(unsigned*)(ch+o0) = pack2(hi_bf16(cacc[ci][0]), hi_bf16(cacc[ci][1]));
    *(unsigned*)(cl+o0) = pack2(lo_bf16(cacc[ci][0]), lo_bf16(cacc[ci][1]));
    *(unsigned*)(ch+o1) = pack2(hi_bf16(cacc[ci][2]), hi_bf16(cacc[ci][3]));
    *(unsigned*)(cl+o1) = pack2(lo_bf16(cacc[ci][2]), lo_bf16(cacc[ci][3]));
  }
}

extern "C" void kernel_launch(void* const* d_in, const int* in_sizes, int n_in,
                              void* d_out, int out_size){
  const float* Q   = (const float*)d_in[0];
  const float* K   = (const float*)d_in[1];
  const float* V   = (const float*)d_in[2];
  const float* Wq  = (const float*)d_in[3];
  const float* bq  = (const float*)d_in[4];
  const float* Wk  = (const float*)d_in[5];
  const float* bk  = (const float*)d_in[6];
  const float* Wv  = (const float*)d_in[7];
  const float* bv  = (const float*)d_in[8];
  const float* Wfc = (const float*)d_in[9];
  const float* bfc = (const float*)d_in[10];
  float* out_f = (float*)d_out;

  bf16 *Xh,*Xl,*Wth,*Wtl,*qkvh,*qkvl,*ch,*cl;
  float *bias3,*afb;
  cudaGetSymbolAddress((void**)&Xh, g_Xh);     cudaGetSymbolAddress((void**)&Xl, g_Xl);
  cudaGetSymbolAddress((void**)&Wth, g_Wth);   cudaGetSymbolAddress((void**)&Wtl, g_Wtl);
  cudaGetSymbolAddress((void**)&qkvh, g_qkvh); cudaGetSymbolAddress((void**)&qkvl, g_qkvl);
  cudaGetSymbolAddress((void**)&ch, g_ch);     cudaGetSymbolAddress((void**)&cl, g_cl);
  cudaGetSymbolAddress((void**)&bias3, g_bias3);
  cudaGetSymbolAddress((void**)&afb,  g_attn_fb);

  const size_t ATTN = (size_t)HEADS*SS*SS;
  float* attn = ((size_t)out_size >= ATTN) ? (out_f + ((size_t)out_size - ATTN)) : afb;

  const int SM_GEMMW = 2*(128*40 + 128*40)*2*2;                   // 81920
  const int SM_FUSED = (2*128*72 + 4*64*72 + 4*64*72)*2 + 128*4;  // 111104

  cudaFuncSetAttribute(gemmW<0>, cudaFuncAttributeMaxDynamicSharedMemorySize, SM_GEMMW);
  cudaFuncSetAttribute(gemmW<3>, cudaFuncAttributeMaxDynamicSharedMemorySize, SM_GEMMW);
  cudaFuncSetAttribute(fused_attn, cudaFuncAttributeMaxDynamicSharedMemorySize, SM_FUSED);

  dim3 blk(256);

  cudaMemcpyAsync(bias3,        bq, DM*sizeof(float), cudaMemcpyDeviceToDevice);
  cudaMemcpyAsync(bias3 + DM,   bk, DM*sizeof(float), cudaMemcpyDeviceToDevice);
  cudaMemcpyAsync(bias3 + 2*DM, bv, DM*sizeof(float), cudaMemcpyDeviceToDevice);

  cvtX<<<dim3(NXE/4/256,1,3), blk>>>(Q,K,V, Xh,Xl);
  cvtWt<<<dim3(32,32,4), dim3(32,8)>>>(Wq,Wk,Wv,Wfc, Wth,Wtl);

  // Q/K/V projections (z: 0=q, 1=k head-split, 2=v transposed)
  gemmW<0><<<dim3(8,32,3), blk, SM_GEMMW>>>(
      Xh, Xl, Wth, Wtl, bias3, nullptr, qkvh, qkvl);

  fused_attn<<<dim3(SS/128, HEADS), blk, SM_FUSED>>>(
      qkvh, qkvl,
      qkvh + (size_t)QKVE, qkvl + (size_t)QKVE,
      qkvh + 2*(size_t)QKVE, qkvl + 2*(size_t)QKVE,
      attn, ch, cl);

  gemmW<3><<<dim3(8,32), blk, SM_GEMMW>>>(
      ch, cl, Wth + 3*(size_t)NWE, Wtl + 3*(size_t)NWE, bfc, out_f, nullptr, nullptr);
}

// round 8
// speedup vs baseline: 2.9713x; 1.0747x over previous
#include <cuda_runtime.h>
#include <cuda_bf16.h>
#include <cstdint>

using bf16 = __nv_bfloat16;

#define BB 2
#define SS 2048
#define DM 1024
#define NH 16
#define DK 64
#define MROWS (BB*SS)       // 4096
#define HEADS (BB*NH)       // 32
#define NXE (MROWS*DM)      // 4194304
#define NWE (DM*DM)         // 1048576
#define QKVE (HEADS*SS*DK)  // 4194304

// ---------------- scratch ----------------
__device__ bf16 g_Xh[3*NXE], g_Xl[3*NXE];
__device__ bf16 g_Wth[4*NWE], g_Wtl[4*NWE];        // transposed weights [N][K]
__device__ bf16 g_qkvh[3*QKVE], g_qkvl[3*QKVE];    // q,k head-split; v transposed [bh][dk][seq]
__device__ bf16 g_ch[MROWS*DM], g_cl[MROWS*DM];
__device__ float g_bias3[3*DM];
__device__ float g_attn_fb[(size_t)HEADS*SS*SS];

// ---------------- helpers ----------------
__device__ __forceinline__ unsigned sptr(const void* p){
  return (unsigned)__cvta_generic_to_shared(p);
}
#define CP16(d,s) asm volatile("cp.async.cg.shared.global [%0], [%1], 16;\n" :: "r"(d), "l"(s))
#define CPCOMMIT() asm volatile("cp.async.commit_group;\n")
#define CPWAIT(N)  asm volatile("cp.async.wait_group %0;\n" :: "n"(N))

__device__ __forceinline__ void ldsm4(unsigned& r0, unsigned& r1, unsigned& r2, unsigned& r3,
                                      unsigned saddr){
  asm volatile("ldmatrix.sync.aligned.m8n8.x4.shared.b16 {%0,%1,%2,%3}, [%4];"
    : "=r"(r0), "=r"(r1), "=r"(r2), "=r"(r3) : "r"(saddr));
}

__device__ __forceinline__ unsigned pack2(bf16 x, bf16 y){
  __nv_bfloat162 t = __halves2bfloat162(x, y);
  return *reinterpret_cast<unsigned*>(&t);
}
__device__ __forceinline__ void split_bf16(float v, bf16& h, bf16& l){
  h = __float2bfloat16(v);
  l = __float2bfloat16(v - __bfloat162float(h));
}
__device__ __forceinline__ bf16 hi_bf16(float v){ return __float2bfloat16(v); }
__device__ __forceinline__ bf16 lo_bf16(float v){
  bf16 h = __float2bfloat16(v);
  return __float2bfloat16(v - __bfloat162float(h));
}
__device__ __forceinline__ void mma16(float c[4], const unsigned a[4], const unsigned b[2]){
  asm volatile(
    "mma.sync.aligned.m16n8k16.row.col.f32.bf16.bf16.f32 "
    "{%0,%1,%2,%3},{%4,%5,%6,%7},{%8,%9},{%0,%1,%2,%3};\n"
    : "+f"(c[0]), "+f"(c[1]), "+f"(c[2]), "+f"(c[3])
    : "r"(a[0]), "r"(a[1]), "r"(a[2]), "r"(a[3]), "r"(b[0]), "r"(b[1]));
}

// fp32 -> bf16 hi/lo for the 3 input tensors (z selects)
__global__ void cvtX(const float* p0, const float* p1, const float* p2,
                     bf16* __restrict__ Xh, bf16* __restrict__ Xl){
  const int z = blockIdx.z;
  const float* in = (z==0)?p0:(z==1)?p1:p2;
  bf16* hi = Xh + (size_t)z*NXE;
  bf16* lo = Xl + (size_t)z*NXE;
  const int i = blockIdx.x*blockDim.x + threadIdx.x;
  float4 v = ((const float4*)in)[i];
  bf16 h0,l0,h1,l1,h2,l2,h3,l3;
  split_bf16(v.x,h0,l0); split_bf16(v.y,h1,l1);
  split_bf16(v.z,h2,l2); split_bf16(v.w,h3,l3);
  uint2 uh, ul;
  uh.x = pack2(h0,h1); uh.y = pack2(h2,h3);
  ul.x = pack2(l0,l1); ul.y = pack2(l2,l3);
  ((uint2*)hi)[i] = uh;
  ((uint2*)lo)[i] = ul;
}

// fp32 W[K][N] -> transposed bf16 hi/lo Wt[N][K]
__global__ void cvtWt(const float* p0, const float* p1, const float* p2, const float* p3,
                      bf16* __restrict__ Wth, bf16* __restrict__ Wtl){
  __shared__ float t[32][33];
  const int z = blockIdx.z;
  const float* in = (z==0)?p0:(z==1)?p1:(z==2)?p2:p3;
  bf16* hi = Wth + (size_t)z*NWE;
  bf16* lo = Wtl + (size_t)z*NWE;
  const int tx = threadIdx.x, ty = threadIdx.y;
  const int n0 = blockIdx.x*32, k0 = blockIdx.y*32;
#pragma unroll
  for (int i=0;i<4;i++){
    const int k = ty + 8*i;
    t[k][tx] = in[(size_t)(k0+k)*DM + n0 + tx];
  }
  __syncthreads();
#pragma unroll
  for (int i=0;i<4;i++){
    const int n = ty + 8*i;
    const float v = t[tx][n];
    const size_t o = (size_t)(n0+n)*DM + k0 + tx;
    hi[o] = hi_bf16(v);
    lo[o] = lo_bf16(v);
  }
}

// ---------------------------------------------------------------------------
// bf16 split-3 GEMM: C = A @ Wt^T, both K-contiguous, LDSM fragments.
// ---------------------------------------------------------------------------
template<int EPI>
__global__ void __launch_bounds__(256,2)
gemmW(const bf16* __restrict__ Ahp, const bf16* __restrict__ Alp,
      const bf16* __restrict__ Bhp, const bf16* __restrict__ Blp,
      const float* __restrict__ biasp,
      float* __restrict__ outf, bf16* __restrict__ outhp, bf16* __restrict__ outlp)
{
  constexpr int BM=128, BN=128, BK=32, STAGES=2, PK=40;
  constexpr int WM=64, WN=32, MF=4, NF=4;

  extern __shared__ bf16 smx[];
  bf16* sAh = smx;
  bf16* sAl = sAh + STAGES*BM*PK;
  bf16* sBh = sAl + STAGES*BM*PK;
  bf16* sBl = sBh + STAGES*BN*PK;

  const int tid=threadIdx.x, lane=tid&31, wid=tid>>5;
  const int g=lane>>2, tg=lane&3;
  const int warp_m=wid>>2, warp_n=wid&3;
  const int wm=warp_m*WM, wn=warp_n*WN;
  const int m0=blockIdx.y*BM, n0=blockIdx.x*BN, bh_=blockIdx.z;

  // ldmatrix per-lane offsets
  const int aRowF = (lane&7) + ((lane>>3)&1)*8;
  const int aColF = ((lane>>4)&1)*8;
  const int bRowF = (lane&7) + ((lane>>4)&1)*8;
  const int bColF = ((lane>>3)&1)*8;

  const bf16 *Ah=Ahp, *Al=Alp, *Bh=Bhp, *Bl=Blp;
  const float* bias = biasp;
  bf16 *outh=outhp, *outl=outlp;
  if constexpr (EPI==0){
    Ah += (size_t)bh_*NXE;  Al += (size_t)bh_*NXE;
    Bh += (size_t)bh_*NWE;  Bl += (size_t)bh_*NWE;
    bias += bh_*DM;
    outh += (size_t)bh_*QKVE; outl += (size_t)bh_*QKVE;
  }

  const int ar=tid>>1, ac=(tid&1)*16;

  float acc[MF][NF][4];
#pragma unroll
  for (int mi=0;mi<MF;mi++)
#pragma unroll
    for (int ni=0;ni<NF;ni++)
#pragma unroll
      for (int q=0;q<4;q++) acc[mi][ni][q]=0.f;

  const int T = DM/BK;

  auto issue = [&](int t){
    const int st = t & 1;
    const int k0 = t*BK;
    const bf16* s = Ah + (size_t)(m0+ar)*DM + k0 + ac;
    unsigned d = sptr(sAh + ((size_t)st*BM+ar)*PK + ac);
    CP16(d, s); CP16(d+16, s+8);
    const bf16* s2 = Al + (size_t)(m0+ar)*DM + k0 + ac;
    unsigned d2 = sptr(sAl + ((size_t)st*BM+ar)*PK + ac);
    CP16(d2, s2); CP16(d2+16, s2+8);
    const bf16* s3 = Bh + (size_t)(n0+ar)*DM + k0 + ac;
    unsigned d3 = sptr(sBh + ((size_t)st*BN+ar)*PK + ac);
    CP16(d3, s3); CP16(d3+16, s3+8);
    const bf16* s4 = Bl + (size_t)(n0+ar)*DM + k0 + ac;
    unsigned d4 = sptr(sBl + ((size_t)st*BN+ar)*PK + ac);
    CP16(d4, s4); CP16(d4+16, s4+8);
    CPCOMMIT();
  };

  auto compute = [&](int st){
#pragma unroll
    for (int s16=0; s16<2; s16++){
      const int kc = s16*16;
      unsigned ah[MF][4], al[MF][4], bh[NF][2], bl[NF][2];
#pragma unroll
      for (int mi=0;mi<MF;mi++){
        unsigned ad = sptr(sAh + ((size_t)st*BM + wm + mi*16 + aRowF)*PK + kc + aColF);
        ldsm4(ah[mi][0],ah[mi][1],ah[mi][2],ah[mi][3], ad);
        unsigned ad2 = sptr(sAl + ((size_t)st*BM + wm + mi*16 + aRowF)*PK + kc + aColF);
        ldsm4(al[mi][0],al[mi][1],al[mi][2],al[mi][3], ad2);
      }
#pragma unroll
      for (int np=0;np<2;np++){
        unsigned bd = sptr(sBh + ((size_t)st*BN + wn + np*16 + bRowF)*PK + kc + bColF);
        ldsm4(bh[2*np][0], bh[2*np][1], bh[2*np+1][0], bh[2*np+1][1], bd);
        unsigned bd2 = sptr(sBl + ((size_t)st*BN + wn + np*16 + bRowF)*PK + kc + bColF);
        ldsm4(bl[2*np][0], bl[2*np][1], bl[2*np+1][0], bl[2*np+1][1], bd2);
      }
#pragma unroll
      for (int mi=0;mi<MF;mi++)
#pragma unroll
        for (int ni=0;ni<NF;ni++){
          mma16(acc[mi][ni], ah[mi], bh[ni]);
          mma16(acc[mi][ni], al[mi], bh[ni]);
          mma16(acc[mi][ni], ah[mi], bl[ni]);
        }
    }
  };

  issue(0);
  for (int t=0;t<T;t++){
    if (t+1<T){ issue(t+1); CPWAIT(1); } else { CPWAIT(0); }
    __syncthreads();
    compute(t & 1);
    __syncthreads();
  }

  if constexpr (EPI==0){
    const bool vdst = (bh_==2);
#pragma unroll
    for (int mi=0;mi<MF;mi++)
#pragma unroll
      for (int hf=0;hf<2;hf++){
        const int m = m0 + wm + mi*16 + g + hf*8;
        const int b = m >> 11, s = m & (SS-1);
#pragma unroll
        for (int ni=0;ni<NF;ni++){
          const int n = n0 + wn + ni*8 + tg*2;
          const int h = n >> 6, d = n & 63;
          float y0 = acc[mi][ni][hf*2+0] + bias[n];
          float y1 = acc[mi][ni][hf*2+1] + bias[n+1];
          if (!vdst){
            const size_t o = (((size_t)b*NH + h)*SS + s)*DK + d;
            *(unsigned*)(outh+o) = pack2(hi_bf16(y0), hi_bf16(y1));
            *(unsigned*)(outl+o) = pack2(lo_bf16(y0), lo_bf16(y1));
          } else {
            const size_t o0 = (((size_t)b*NH + h)*DK + d)*SS + s;
            const size_t o1 = o0 + SS;
            outh[o0]=hi_bf16(y0); outl[o0]=lo_bf16(y0);
            outh[o1]=hi_bf16(y1); outl[o1]=lo_bf16(y1);
          }
        }
      }
  } else {
#pragma unroll
    for (int mi=0;mi<MF;mi++)
#pragma unroll
      for (int hf=0;hf<2;hf++){
        const int m = m0 + wm + mi*16 + g + hf*8;
#pragma unroll
        for (int ni=0;ni<NF;ni++){
          const int n = n0 + wn + ni*8 + tg*2;
          float2 y;
          y.x = acc[mi][ni][hf*2+0] + bias[n];
          y.y = acc[mi][ni][hf*2+1] + bias[n+1];
          *(float2*)(outf + (size_t)m*DM + n) = y;
        }
      }
  }
}

// ---------------------------------------------------------------------------
// Fused attention (two sweeps), LDSM fragments, Q cached in registers.
// ---------------------------------------------------------------------------
__global__ void __launch_bounds__(256,2)
fused_attn(const bf16* __restrict__ qh_, const bf16* __restrict__ ql_,
           const bf16* __restrict__ kh_, const bf16* __restrict__ kl_,
           const bf16* __restrict__ vh_, const bf16* __restrict__ vl_,
           float* __restrict__ attn_, bf16* __restrict__ ch, bf16* __restrict__ cl)
{
  constexpr int PK=72, NBT=64, NB=SS/NBT;
  extern __shared__ bf16 sm[];
  bf16* sQh = sm;
  bf16* sQl = sQh + 128*PK;
  bf16* sKh = sQl + 128*PK;
  bf16* sKl = sKh + 2*64*PK;
  bf16* sVh = sKl + 2*64*PK;
  bf16* sVl = sVh + 2*64*PK;
  float* sInv = (float*)(sVl + 2*64*PK);

  const int tid=threadIdx.x, lane=tid&31;
  const int g=lane>>2, tg=lane&3;
  const int wm = (tid>>5)*16;
  const int m0 = blockIdx.x*128;
  const int bh = blockIdx.y;

  const int aRowF = (lane&7) + ((lane>>3)&1)*8;
  const int aColF = ((lane>>4)&1)*8;
  const int bRowF = (lane&7) + ((lane>>4)&1)*8;
  const int bColF = ((lane>>3)&1)*8;

  const bf16* qh = qh_ + (size_t)(bh*SS+m0)*DK;
  const bf16* ql = ql_ + (size_t)(bh*SS+m0)*DK;
  const bf16* kh = kh_ + (size_t)bh*SS*DK;
  const bf16* kl = kl_ + (size_t)bh*SS*DK;
  const bf16* vh = vh_ + (size_t)bh*DK*SS;
  const bf16* vl = vl_ + (size_t)bh*DK*SS;
  float* attn = attn_ + (size_t)bh*SS*SS;

  auto issueQ = [&](){
    const int row=tid>>1, s0=(tid&1)*4;
    const bf16* sh = qh + (size_t)row*DK;
    const bf16* sl = ql + (size_t)row*DK;
    unsigned dh = sptr(sQh + row*PK);
    unsigned dl = sptr(sQl + row*PK);
#pragma unroll
    for (int s=s0;s<s0+4;s++){ CP16(dh+s*16, sh+s*8); CP16(dl+s*16, sl+s*8); }
  };
  auto issueK1 = [&](int nb,int st){
    const int row=tid>>2, s=tid&3;
    const bf16* sh = kh + (size_t)(nb*NBT+row)*DK;
    unsigned dh = sptr(sKh + (st*64+row)*PK);
    CP16(dh+s*16, sh+s*8);  CP16(dh+(s+4)*16, sh+(s+4)*8);
  };
  auto issueK = [&](int nb,int st){
    const int row=tid>>2, s=tid&3;
    const bf16* sh = kh + (size_t)(nb*NBT+row)*DK;
    const bf16* sl = kl + (size_t)(nb*NBT+row)*DK;
    unsigned dh = sptr(sKh + (st*64+row)*PK);
    unsigned dl = sptr(sKl + (st*64+row)*PK);
    CP16(dh+s*16, sh+s*8);  CP16(dh+(s+4)*16, sh+(s+4)*8);
    CP16(dl+s*16, sl+s*8);  CP16(dl+(s+4)*16, sl+(s+4)*8);
  };
  auto issueV = [&](int nb,int st){
    const int row=tid>>2, s=tid&3;
    const bf16* sh = vh + (size_t)row*SS + nb*NBT;
    const bf16* sl = vl + (size_t)row*SS + nb*NBT;
    unsigned dh = sptr(sVh + (st*64+row)*PK);
    unsigned dl = sptr(sVl + (st*64+row)*PK);
    CP16(dh+s*16, sh+s*8);  CP16(dh+(s+4)*16, sh+(s+4)*8);
    CP16(dl+s*16, sl+s*8);  CP16(dl+(s+4)*16, sl+(s+4)*8);
  };

  // Q fragments cached for the whole kernel
  unsigned qfh[4][4], qfl[4][4];

  // split-3 S
  auto computeS = [&](int st, float sacc[8][4]){
#pragma unroll
    for (int ni=0;ni<8;ni++)
#pragma unroll
      for (int q=0;q<4;q++) sacc[ni][q]=0.f;
#pragma unroll
    for (int kk=0;kk<4;kk++){
#pragma unroll
      for (int np=0;np<4;np++){
        unsigned bd = sptr(sKh + ((size_t)st*64 + np*16 + bRowF)*PK + kk*16 + bColF);
        unsigned b0,b1,b2,b3; ldsm4(b0,b1,b2,b3,bd);
        unsigned ld = sptr(sKl + ((size_t)st*64 + np*16 + bRowF)*PK + kk*16 + bColF);
        unsigned l0,l1,l2,l3; ldsm4(l0,l1,l2,l3,ld);
        unsigned bp0[2]={b0,b1}, bp1[2]={b2,b3};
        unsigned lp0[2]={l0,l1}, lp1[2]={l2,l3};
        mma16(sacc[2*np],   qfh[kk], bp0);
        mma16(sacc[2*np],   qfl[kk], bp0);
        mma16(sacc[2*np],   qfh[kk], lp0);
        mma16(sacc[2*np+1], qfh[kk], bp1);
        mma16(sacc[2*np+1], qfl[kk], bp1);
        mma16(sacc[2*np+1], qfh[kk], lp1);
      }
    }
  };
  // hi-only S (rowsums)
  auto computeS1 = [&](int st, float sacc[8][4]){
#pragma unroll
    for (int ni=0;ni<8;ni++)
#pragma unroll
      for (int q=0;q<4;q++) sacc[ni][q]=0.f;
#pragma unroll
    for (int kk=0;kk<4;kk++){
#pragma unroll
      for (int np=0;np<4;np++){
        unsigned bd = sptr(sKh + ((size_t)st*64 + np*16 + bRowF)*PK + kk*16 + bColF);
        unsigned b0,b1,b2,b3; ldsm4(b0,b1,b2,b3,bd);
        unsigned bp0[2]={b0,b1}, bp1[2]={b2,b3};
        mma16(sacc[2*np],   qfh[kk], bp0);
        mma16(sacc[2*np+1], qfh[kk], bp1);
      }
    }
  };

  // ================= Sweep 1: row sums (hi-only) =================
  issueQ(); CPCOMMIT();
  issueK1(0,0); CPCOMMIT();
  CPWAIT(1);                 // Q group retired
  __syncthreads();
#pragma unroll
  for (int kk=0;kk<4;kk++){
    unsigned ad = sptr(sQh + (size_t)(wm + aRowF)*PK + kk*16 + aColF);
    ldsm4(qfh[kk][0],qfh[kk][1],qfh[kk][2],qfh[kk][3], ad);
    unsigned ad2 = sptr(sQl + (size_t)(wm + aRowF)*PK + kk*16 + aColF);
    ldsm4(qfl[kk][0],qfl[kk][1],qfl[kk][2],qfl[kk][3], ad2);
  }

  float rs0=0.f, rs1=0.f;
  for (int nb=0;nb<NB;nb++){
    if (nb+1<NB){ issueK1(nb+1,(nb+1)&1); CPCOMMIT(); CPWAIT(1); }
    else        { CPWAIT(0); }
    __syncthreads();
    float sacc[8][4];
    computeS1(nb&1, sacc);
#pragma unroll
    for (int ni=0;ni<8;ni++){
      rs0 += __expf(sacc[ni][0]*0.125f) + __expf(sacc[ni][1]*0.125f);
      rs1 += __expf(sacc[ni][2]*0.125f) + __expf(sacc[ni][3]*0.125f);
    }
    __syncthreads();
  }
  rs0 += __shfl_xor_sync(0xffffffffu, rs0, 1);
  rs0 += __shfl_xor_sync(0xffffffffu, rs0, 2);
  rs1 += __shfl_xor_sync(0xffffffffu, rs1, 1);
  rs1 += __shfl_xor_sync(0xffffffffu, rs1, 2);
  if (tg==0){ sInv[wm+g] = 1.0f/rs0; sInv[wm+g+8] = 1.0f/rs1; }
  __syncthreads();
  const float inv0 = sInv[wm+g];
  const float inv1 = sInv[wm+g+8];

  // ================= Sweep 2: normalized attn + P@V =================
  float cacc[8][4];
#pragma unroll
  for (int ci=0;ci<8;ci++)
#pragma unroll
    for (int q=0;q<4;q++) cacc[ci][q]=0.f;

  issueK(0,0); issueV(0,0); CPCOMMIT();
  for (int nb=0;nb<NB;nb++){
    if (nb+1<NB){ issueK(nb+1,(nb+1)&1); issueV(nb+1,(nb+1)&1); CPCOMMIT(); CPWAIT(1); }
    else        { CPWAIT(0); }
    __syncthreads();
    const int st = nb&1;
    float sacc[8][4];
    computeS(st, sacc);

    float* arow0 = attn + (size_t)(m0+wm+g)*SS + nb*NBT;
    float* arow1 = arow0 + 8*SS;
#pragma unroll
    for (int ni=0;ni<8;ni++){
      float e0 = __expf(sacc[ni][0]*0.125f)*inv0;
      float e1 = __expf(sacc[ni][1]*0.125f)*inv0;
      float e2 = __expf(sacc[ni][2]*0.125f)*inv1;
      float e3 = __expf(sacc[ni][3]*0.125f)*inv1;
      sacc[ni][0]=e0; sacc[ni][1]=e1; sacc[ni][2]=e2; sacc[ni][3]=e3;
      float2 lo2; lo2.x=e0; lo2.y=e1;
      float2 hi2; hi2.x=e2; hi2.y=e3;
      __stcs((float2*)(arow0 + ni*8 + tg*2), lo2);
      __stcs((float2*)(arow1 + ni*8 + tg*2), hi2);
    }

#pragma unroll
    for (int kk=0;kk<4;kk++){
      const int f0=2*kk, f1=2*kk+1;
      unsigned pah[4], pal[4];
      pah[0]=pack2(hi_bf16(sacc[f0][0]), hi_bf16(sacc[f0][1]));
      pah[1]=pack2(hi_bf16(sacc[f0][2]), hi_bf16(sacc[f0][3]));
      pah[2]=pack2(hi_bf16(sacc[f1][0]), hi_bf16(sacc[f1][1]));
      pah[3]=pack2(hi_bf16(sacc[f1][2]), hi_bf16(sacc[f1][3]));
      pal[0]=pack2(lo_bf16(sacc[f0][0]), lo_bf16(sacc[f0][1]));
      pal[1]=pack2(lo_bf16(sacc[f0][2]), lo_bf16(sacc[f0][3]));
      pal[2]=pack2(lo_bf16(sacc[f1][0]), lo_bf16(sacc[f1][1]));
      pal[3]=pack2(lo_bf16(sacc[f1][2]), lo_bf16(sacc[f1][3]));
#pragma unroll
      for (int cp=0;cp<4;cp++){
        unsigned vd = sptr(sVh + ((size_t)st*64 + cp*16 + bRowF)*PK + kk*16 + bColF);
        unsigned v0,v1,v2,v3; ldsm4(v0,v1,v2,v3,vd);
        unsigned vld = sptr(sVl + ((size_t)st*64 + cp*16 + bRowF)*PK + kk*16 + bColF);
        unsigned w0,w1,w2,w3; ldsm4(w0,w1,w2,w3,vld);
        unsigned vp0[2]={v0,v1}, vp1[2]={v2,v3};
        unsigned wp0[2]={w0,w1}, wp1[2]={w2,w3};
        mma16(cacc[2*cp],   pah, vp0);
        mma16(cacc[2*cp],   pal, vp0);
        mma16(cacc[2*cp],   pah, wp0);
        mma16(cacc[2*cp+1], pah, vp1);
        mma16(cacc[2*cp+1], pal, vp1);
        mma16(cacc[2*cp+1], pah, wp1);
      }
    }
    __syncthreads();
  }

  const int b = bh>>4, h = bh&(NH-1);
#pragma unroll
  for (int ci=0;ci<8;ci++){
    const int d = h*DK + ci*8 + tg*2;
    const size_t o0 = ((size_t)(b*SS + m0+wm+g))*DM + d;
    const size_t o1 = o0 + (size_t)8*DM;
    *(unsigned*)(ch+o0) = pack2(hi_bf16(cacc[ci][0]), hi_bf16(cacc[ci][1]));
    *(unsigned*)(cl+o0) = pack2(lo_bf16(cacc[ci][0]), lo_bf16(cacc[ci][1]));
    *(unsigned*)(ch+o1) = pack2(hi_bf16(cacc[ci][2]), hi_bf16(cacc[ci][3]));
    *(unsigned*)(cl+o1) = pack2(lo_bf16(cacc[ci][2]), lo_bf16(cacc[ci][3]));
  }
}

extern "C" void kernel_launch(void* const* d_in, const int* in_sizes, int n_in,
                              void* d_out, int out_size){
  const float* Q   = (const float*)d_in[0];
  const float* K   = (const float*)d_in[1];
  const float* V   = (const float*)d_in[2];
  const float* Wq  = (const float*)d_in[3];
  const float* bq  = (const float*)d_in[4];
  const float* Wk  = (const float*)d_in[5];
  const float* bk  = (const float*)d_in[6];
  const float* Wv  = (const float*)d_in[7];
  const float* bv  = (const float*)d_in[8];
  const float* Wfc = (const float*)d_in[9];
  const float* bfc = (const float*)d_in[10];
  float* out_f = (float*)d_out;

  bf16 *Xh,*Xl,*Wth,*Wtl,*qkvh,*qkvl,*ch,*cl;
  float *bias3,*afb;
  cudaGetSymbolAddress((void**)&Xh, g_Xh);     cudaGetSymbolAddress((void**)&Xl, g_Xl);
  cudaGetSymbolAddress((void**)&Wth, g_Wth);   cudaGetSymbolAddress((void**)&Wtl, g_Wtl);
  cudaGetSymbolAddress((void**)&qkvh, g_qkvh); cudaGetSymbolAddress((void**)&qkvl, g_qkvl);
  cudaGetSymbolAddress((void**)&ch, g_ch);     cudaGetSymbolAddress((void**)&cl, g_cl);
  cudaGetSymbolAddress((void**)&bias3, g_bias3);
  cudaGetSymbolAddress((void**)&afb,  g_attn_fb);

  const size_t ATTN = (size_t)HEADS*SS*SS;
  float* attn = ((size_t)out_size >= ATTN) ? (out_f + ((size_t)out_size - ATTN)) : afb;

  const int SM_GEMMW = 2*(128*40 + 128*40)*2*2;                   // 81920
  const int SM_FUSED = (2*128*72 + 4*64*72 + 4*64*72)*2 + 128*4;  // 111104

  cudaFuncSetAttribute(gemmW<0>, cudaFuncAttributeMaxDynamicSharedMemorySize, SM_GEMMW);
  cudaFuncSetAttribute(gemmW<3>, cudaFuncAttributeMaxDynamicSharedMemorySize, SM_GEMMW);
  cudaFuncSetAttribute(fused_attn, cudaFuncAttributeMaxDynamicSharedMemorySize, SM_FUSED);

  dim3 blk(256);

  cudaMemcpyAsync(bias3,        bq, DM*sizeof(float), cudaMemcpyDeviceToDevice);
  cudaMemcpyAsync(bias3 + DM,   bk, DM*sizeof(float), cudaMemcpyDeviceToDevice);
  cudaMemcpyAsync(bias3 + 2*DM, bv, DM*sizeof(float), cudaMemcpyDeviceToDevice);

  cvtX<<<dim3(NXE/4/256,1,3), blk>>>(Q,K,V, Xh,Xl);
  cvtWt<<<dim3(32,32,4), dim3(32,8)>>>(Wq,Wk,Wv,Wfc, Wth,Wtl);

  gemmW<0><<<dim3(8,32,3), blk, SM_GEMMW>>>(
      Xh, Xl, Wth, Wtl, bias3, nullptr, qkvh, qkvl);

  fused_attn<<<dim3(SS/128, HEADS), blk, SM_FUSED>>>(
      qkvh, qkvl,
      qkvh + (size_t)QKVE, qkvl + (size_t)QKVE,
      qkvh + 2*(size_t)QKVE, qkvl + 2*(size_t)QKVE,
      attn, ch, cl);

  gemmW<3><<<dim3(8,32), blk, SM_GEMMW>>>(
      ch, cl, Wth + 3*(size_t)NWE, Wtl + 3*(size_t)NWE, bfc, out_f, nullptr, nullptr);
}

// round 11
// speedup vs baseline: 3.0039x; 1.0110x over previous
#include <cuda_runtime.h>
#include <cuda_bf16.h>
#include <cstdint>

using bf16 = __nv_bfloat16;

#define BB 2
#define SS 2048
#define DM 1024
#define NH 16
#define DK 64
#define MROWS (BB*SS)       // 4096
#define HEADS (BB*NH)       // 32
#define NXE (MROWS*DM)      // 4194304
#define NWE (DM*DM)         // 1048576
#define QKVE (HEADS*SS*DK)  // 4194304

// ---------------- scratch ----------------
__device__ bf16 g_Xh[3*NXE], g_Xl[3*NXE];
__device__ bf16 g_Wth[4*NWE], g_Wtl[4*NWE];        // transposed weights [N][K]
__device__ bf16 g_qkvh[3*QKVE], g_qkvl[3*QKVE];    // q,k head-split; v transposed [bh][dk][seq]
__device__ bf16 g_ch[MROWS*DM], g_cl[MROWS*DM];
__device__ float g_bias3[3*DM];
__device__ float g_attn_fb[(size_t)HEADS*SS*SS];

// ---------------- helpers ----------------
__device__ __forceinline__ unsigned sptr(const void* p){
  return (unsigned)__cvta_generic_to_shared(p);
}
#define CP16(d,s) asm volatile("cp.async.cg.shared.global [%0], [%1], 16;\n" :: "r"(d), "l"(s))
#define CPCOMMIT() asm volatile("cp.async.commit_group;\n")
#define CPWAIT(N)  asm volatile("cp.async.wait_group %0;\n" :: "n"(N))

__device__ __forceinline__ void ldsm4(unsigned& r0, unsigned& r1, unsigned& r2, unsigned& r3,
                                      unsigned saddr){
  asm volatile("ldmatrix.sync.aligned.m8n8.x4.shared.b16 {%0,%1,%2,%3}, [%4];"
    : "=r"(r0), "=r"(r1), "=r"(r2), "=r"(r3) : "r"(saddr));
}

__device__ __forceinline__ unsigned pack2(bf16 x, bf16 y){
  __nv_bfloat162 t = __halves2bfloat162(x, y);
  return *reinterpret_cast<unsigned*>(&t);
}
__device__ __forceinline__ void split_bf16(float v, bf16& h, bf16& l){
  h = __float2bfloat16(v);
  l = __float2bfloat16(v - __bfloat162float(h));
}
__device__ __forceinline__ bf16 hi_bf16(float v){ return __float2bfloat16(v); }
__device__ __forceinline__ bf16 lo_bf16(float v){
  bf16 h = __float2bfloat16(v);
  return __float2bfloat16(v - __bfloat162float(h));
}
__device__ __forceinline__ void mma16(float c[4], const unsigned a[4], const unsigned b[2]){
  asm volatile(
    "mma.sync.aligned.m16n8k16.row.col.f32.bf16.bf16.f32 "
    "{%0,%1,%2,%3},{%4,%5,%6,%7},{%8,%9},{%0,%1,%2,%3};\n"
    : "+f"(c[0]), "+f"(c[1]), "+f"(c[2]), "+f"(c[3])
    : "r"(a[0]), "r"(a[1]), "r"(a[2]), "r"(a[3]), "r"(b[0]), "r"(b[1]));
}

// fp32 -> bf16 hi/lo for the 3 input tensors (z selects)
__global__ void cvtX(const float* p0, const float* p1, const float* p2,
                     bf16* __restrict__ Xh, bf16* __restrict__ Xl){
  const int z = blockIdx.z;
  const float* in = (z==0)?p0:(z==1)?p1:p2;
  bf16* hi = Xh + (size_t)z*NXE;
  bf16* lo = Xl + (size_t)z*NXE;
  const int i = blockIdx.x*blockDim.x + threadIdx.x;
  float4 v = ((const float4*)in)[i];
  bf16 h0,l0,h1,l1,h2,l2,h3,l3;
  split_bf16(v.x,h0,l0); split_bf16(v.y,h1,l1);
  split_bf16(v.z,h2,l2); split_bf16(v.w,h3,l3);
  uint2 uh, ul;
  uh.x = pack2(h0,h1); uh.y = pack2(h2,h3);
  ul.x = pack2(l0,l1); ul.y = pack2(l2,l3);
  ((uint2*)hi)[i] = uh;
  ((uint2*)lo)[i] = ul;
}

// fp32 W[K][N] -> transposed bf16 hi/lo Wt[N][K]
__global__ void cvtWt(const float* p0, const float* p1, const float* p2, const float* p3,
                      bf16* __restrict__ Wth, bf16* __restrict__ Wtl){
  __shared__ float t[32][33];
  const int z = blockIdx.z;
  const float* in = (z==0)?p0:(z==1)?p1:(z==2)?p2:p3;
  bf16* hi = Wth + (size_t)z*NWE;
  bf16* lo = Wtl + (size_t)z*NWE;
  const int tx = threadIdx.x, ty = threadIdx.y;
  const int n0 = blockIdx.x*32, k0 = blockIdx.y*32;
#pragma unroll
  for (int i=0;i<4;i++){
    const int k = ty + 8*i;
    t[k][tx] = in[(size_t)(k0+k)*DM + n0 + tx];
  }
  __syncthreads();
#pragma unroll
  for (int i=0;i<4;i++){
    const int n = ty + 8*i;
    const float v = t[tx][n];
    const size_t o = (size_t)(n0+n)*DM + k0 + tx;
    hi[o] = hi_bf16(v);
    lo[o] = lo_bf16(v);
  }
}

// ---------------------------------------------------------------------------
// bf16 split-3 GEMM: C = A @ Wt^T, LDSM fragments, term-major MMA order.
// ---------------------------------------------------------------------------
template<int EPI>
__global__ void __launch_bounds__(256,2)
gemmW(const bf16* __restrict__ Ahp, const bf16* __restrict__ Alp,
      const bf16* __restrict__ Bhp, const bf16* __restrict__ Blp,
      const float* __restrict__ biasp,
      float* __restrict__ outf, bf16* __restrict__ outhp, bf16* __restrict__ outlp)
{
  constexpr int BM=128, BN=128, BK=32, STAGES=2, PK=40;
  constexpr int WM=64, WN=32, MF=4, NF=4;

  extern __shared__ bf16 smx[];
  bf16* sAh = smx;
  bf16* sAl = sAh + STAGES*BM*PK;
  bf16* sBh = sAl + STAGES*BM*PK;
  bf16* sBl = sBh + STAGES*BN*PK;

  const int tid=threadIdx.x, lane=tid&31, wid=tid>>5;
  const int g=lane>>2, tg=lane&3;
  const int warp_m=wid>>2, warp_n=wid&3;
  const int wm=warp_m*WM, wn=warp_n*WN;
  const int m0=blockIdx.y*BM, n0=blockIdx.x*BN, bh_=blockIdx.z;

  const int aRowF = (lane&7) + ((lane>>3)&1)*8;
  const int aColF = ((lane>>4)&1)*8;
  const int bRowF = (lane&7) + ((lane>>4)&1)*8;
  const int bColF = ((lane>>3)&1)*8;

  const bf16 *Ah=Ahp, *Al=Alp, *Bh=Bhp, *Bl=Blp;
  const float* bias = biasp;
  bf16 *outh=outhp, *outl=outlp;
  if constexpr (EPI==0){
    Ah += (size_t)bh_*NXE;  Al += (size_t)bh_*NXE;
    Bh += (size_t)bh_*NWE;  Bl += (size_t)bh_*NWE;
    bias += bh_*DM;
    outh += (size_t)bh_*QKVE; outl += (size_t)bh_*QKVE;
  }

  const int ar=tid>>1, ac=(tid&1)*16;

  float acc[MF][NF][4];
#pragma unroll
  for (int mi=0;mi<MF;mi++)
#pragma unroll
    for (int ni=0;ni<NF;ni++)
#pragma unroll
      for (int q=0;q<4;q++) acc[mi][ni][q]=0.f;

  const int T = DM/BK;

  auto issue = [&](int t){
    const int st = t & 1;
    const int k0 = t*BK;
    const bf16* s = Ah + (size_t)(m0+ar)*DM + k0 + ac;
    unsigned d = sptr(sAh + ((size_t)st*BM+ar)*PK + ac);
    CP16(d, s); CP16(d+16, s+8);
    const bf16* s2 = Al + (size_t)(m0+ar)*DM + k0 + ac;
    unsigned d2 = sptr(sAl + ((size_t)st*BM+ar)*PK + ac);
    CP16(d2, s2); CP16(d2+16, s2+8);
    const bf16* s3 = Bh + (size_t)(n0+ar)*DM + k0 + ac;
    unsigned d3 = sptr(sBh + ((size_t)st*BN+ar)*PK + ac);
    CP16(d3, s3); CP16(d3+16, s3+8);
    const bf16* s4 = Bl + (size_t)(n0+ar)*DM + k0 + ac;
    unsigned d4 = sptr(sBl + ((size_t)st*BN+ar)*PK + ac);
    CP16(d4, s4); CP16(d4+16, s4+8);
    CPCOMMIT();
  };

  auto compute = [&](int st){
#pragma unroll
    for (int s16=0; s16<2; s16++){
      const int kc = s16*16;
      unsigned ah[MF][4], al[MF][4], bh[NF][2], bl[NF][2];
#pragma unroll
      for (int mi=0;mi<MF;mi++){
        unsigned ad = sptr(sAh + ((size_t)st*BM + wm + mi*16 + aRowF)*PK + kc + aColF);
        ldsm4(ah[mi][0],ah[mi][1],ah[mi][2],ah[mi][3], ad);
        unsigned ad2 = sptr(sAl + ((size_t)st*BM + wm + mi*16 + aRowF)*PK + kc + aColF);
        ldsm4(al[mi][0],al[mi][1],al[mi][2],al[mi][3], ad2);
      }
#pragma unroll
      for (int np=0;np<2;np++){
        unsigned bd = sptr(sBh + ((size_t)st*BN + wn + np*16 + bRowF)*PK + kc + bColF);
        ldsm4(bh[2*np][0], bh[2*np][1], bh[2*np+1][0], bh[2*np+1][1], bd);
        unsigned bd2 = sptr(sBl + ((size_t)st*BN + wn + np*16 + bRowF)*PK + kc + bColF);
        ldsm4(bl[2*np][0], bl[2*np][1], bl[2*np+1][0], bl[2*np+1][1], bd2);
      }
      // term-major: 16 independent accumulator chains per pass
#pragma unroll
      for (int mi=0;mi<MF;mi++)
#pragma unroll
        for (int ni=0;ni<NF;ni++) mma16(acc[mi][ni], ah[mi], bh[ni]);
#pragma unroll
      for (int mi=0;mi<MF;mi++)
#pragma unroll
        for (int ni=0;ni<NF;ni++) mma16(acc[mi][ni], al[mi], bh[ni]);
#pragma unroll
      for (int mi=0;mi<MF;mi++)
#pragma unroll
        for (int ni=0;ni<NF;ni++) mma16(acc[mi][ni], ah[mi], bl[ni]);
    }
  };

  issue(0);
  for (int t=0;t<T;t++){
    if (t+1<T){ issue(t+1); CPWAIT(1); } else { CPWAIT(0); }
    __syncthreads();
    compute(t & 1);
    __syncthreads();
  }

  if constexpr (EPI==0){
    const bool vdst = (bh_==2);
#pragma unroll
    for (int mi=0;mi<MF;mi++)
#pragma unroll
      for (int hf=0;hf<2;hf++){
        const int m = m0 + wm + mi*16 + g + hf*8;
        const int b = m >> 11, s = m & (SS-1);
#pragma unroll
        for (int ni=0;ni<NF;ni++){
          const int n = n0 + wn + ni*8 + tg*2;
          const int h = n >> 6, d = n & 63;
          float y0 = acc[mi][ni][hf*2+0] + bias[n];
          float y1 = acc[mi][ni][hf*2+1] + bias[n+1];
          if (!vdst){
            const size_t o = (((size_t)b*NH + h)*SS + s)*DK + d;
            *(unsigned*)(outh+o) = pack2(hi_bf16(y0), hi_bf16(y1));
            *(unsigned*)(outl+o) = pack2(lo_bf16(y0), lo_bf16(y1));
          } else {
            const size_t o0 = (((size_t)b*NH + h)*DK + d)*SS + s;
            const size_t o1 = o0 + SS;
            outh[o0]=hi_bf16(y0); outl[o0]=lo_bf16(y0);
            outh[o1]=hi_bf16(y1); outl[o1]=lo_bf16(y1);
          }
        }
      }
  } else {
#pragma unroll
    for (int mi=0;mi<MF;mi++)
#pragma unroll
      for (int hf=0;hf<2;hf++){
        const int m = m0 + wm + mi*16 + g + hf*8;
#pragma unroll
        for (int ni=0;ni<NF;ni++){
          const int n = n0 + wn + ni*8 + tg*2;
          float2 y;
          y.x = acc[mi][ni][hf*2+0] + bias[n];
          y.y = acc[mi][ni][hf*2+1] + bias[n+1];
          *(float2*)(outf + (size_t)m*DM + n) = y;
        }
      }
  }
}

// ---------------------------------------------------------------------------
// Fused attention: Q fragments from gmem (no Q smem), 3-stage K/V pipeline,
// one __syncthreads per kv-block, term-major MMA ordering.
// ---------------------------------------------------------------------------
__global__ void __launch_bounds__(256,2)
fused_attn(const bf16* __restrict__ qh_, const bf16* __restrict__ ql_,
           const bf16* __restrict__ kh_, const bf16* __restrict__ kl_,
           const bf16* __restrict__ vh_, const bf16* __restrict__ vl_,
           float* __restrict__ attn_, bf16* __restrict__ ch, bf16* __restrict__ cl)
{
  constexpr int PK=72, NBT=64, NB=SS/NBT, STG=3;
  extern __shared__ bf16 sm[];
  bf16* sKh = sm;                    // 3 * 64*72
  bf16* sKl = sKh + STG*64*PK;
  bf16* sVh = sKl + STG*64*PK;
  bf16* sVl = sVh + STG*64*PK;
  float* sInv = (float*)(sVl + STG*64*PK);

  const int tid=threadIdx.x, lane=tid&31;
  const int g=lane>>2, tg=lane&3;
  const int wm = (tid>>5)*16;
  const int m0 = blockIdx.x*128;
  const int bh = blockIdx.y;

  const int bRowF = (lane&7) + ((lane>>4)&1)*8;
  const int bColF = ((lane>>3)&1)*8;

  const bf16* qh = qh_ + (size_t)(bh*SS+m0)*DK;
  const bf16* ql = ql_ + (size_t)(bh*SS+m0)*DK;
  const bf16* kh = kh_ + (size_t)bh*SS*DK;
  const bf16* kl = kl_ + (size_t)bh*SS*DK;
  const bf16* vh = vh_ + (size_t)bh*DK*SS;
  const bf16* vl = vl_ + (size_t)bh*DK*SS;
  float* attn = attn_ + (size_t)bh*SS*SS;

  auto issueK1 = [&](int nb,int st){
    const int row=tid>>2, s=tid&3;
    const bf16* sh = kh + (size_t)(nb*NBT+row)*DK;
    unsigned dh = sptr(sKh + (st*64+row)*PK);
    CP16(dh+s*16, sh+s*8);  CP16(dh+(s+4)*16, sh+(s+4)*8);
  };
  auto issueKV = [&](int nb,int st){
    const int row=tid>>2, s=tid&3;
    const bf16* skh = kh + (size_t)(nb*NBT+row)*DK;
    const bf16* skl = kl + (size_t)(nb*NBT+row)*DK;
    unsigned dkh = sptr(sKh + (st*64+row)*PK);
    unsigned dkl = sptr(sKl + (st*64+row)*PK);
    CP16(dkh+s*16, skh+s*8);  CP16(dkh+(s+4)*16, skh+(s+4)*8);
    CP16(dkl+s*16, skl+s*8);  CP16(dkl+(s+4)*16, skl+(s+4)*8);
    const bf16* svh = vh + (size_t)row*SS + nb*NBT;
    const bf16* svl = vl + (size_t)row*SS + nb*NBT;
    unsigned dvh = sptr(sVh + (st*64+row)*PK);
    unsigned dvl = sptr(sVl + (st*64+row)*PK);
    CP16(dvh+s*16, svh+s*8);  CP16(dvh+(s+4)*16, svh+(s+4)*8);
    CP16(dvl+s*16, svl+s*8);  CP16(dvl+(s+4)*16, svl+(s+4)*8);
  };

  // Q fragments straight from gmem (ldmatrix-equivalent distribution)
  unsigned qfh[4][4], qfl[4][4];
#pragma unroll
  for (int kk=0;kk<4;kk++){
    const int c = kk*16 + tg*2;
    qfh[kk][0] = *(const unsigned*)(qh + (size_t)(wm+g  )*DK + c);
    qfh[kk][1] = *(const unsigned*)(qh + (size_t)(wm+g+8)*DK + c);
    qfh[kk][2] = *(const unsigned*)(qh + (size_t)(wm+g  )*DK + c+8);
    qfh[kk][3] = *(const unsigned*)(qh + (size_t)(wm+g+8)*DK + c+8);
    qfl[kk][0] = *(const unsigned*)(ql + (size_t)(wm+g  )*DK + c);
    qfl[kk][1] = *(const unsigned*)(ql + (size_t)(wm+g+8)*DK + c);
    qfl[kk][2] = *(const unsigned*)(ql + (size_t)(wm+g  )*DK + c+8);
    qfl[kk][3] = *(const unsigned*)(ql + (size_t)(wm+g+8)*DK + c+8);
  }

  // split-3 S, term-major
  auto computeS = [&](int st, float sacc[8][4]){
#pragma unroll
    for (int ni=0;ni<8;ni++)
#pragma unroll
      for (int q=0;q<4;q++) sacc[ni][q]=0.f;
#pragma unroll
    for (int kk=0;kk<4;kk++){
      unsigned bh2[8][2];
#pragma unroll
      for (int np=0;np<4;np++){
        unsigned bd = sptr(sKh + ((size_t)st*64 + np*16 + bRowF)*PK + kk*16 + bColF);
        ldsm4(bh2[2*np][0],bh2[2*np][1],bh2[2*np+1][0],bh2[2*np+1][1], bd);
      }
#pragma unroll
      for (int j=0;j<8;j++) mma16(sacc[j], qfh[kk], bh2[j]);
#pragma unroll
      for (int j=0;j<8;j++) mma16(sacc[j], qfl[kk], bh2[j]);
#pragma unroll
      for (int np=0;np<4;np++){
        unsigned ld = sptr(sKl + ((size_t)st*64 + np*16 + bRowF)*PK + kk*16 + bColF);
        ldsm4(bh2[2*np][0],bh2[2*np][1],bh2[2*np+1][0],bh2[2*np+1][1], ld);
      }
#pragma unroll
      for (int j=0;j<8;j++) mma16(sacc[j], qfh[kk], bh2[j]);
    }
  };
  // hi-only S (rowsums), term-major
  auto computeS1 = [&](int st, float sacc[8][4]){
#pragma unroll
    for (int ni=0;ni<8;ni++)
#pragma unroll
      for (int q=0;q<4;q++) sacc[ni][q]=0.f;
#pragma unroll
    for (int kk=0;kk<4;kk++){
      unsigned bh2[8][2];
#pragma unroll
      for (int np=0;np<4;np++){
        unsigned bd = sptr(sKh + ((size_t)st*64 + np*16 + bRowF)*PK + kk*16 + bColF);
        ldsm4(bh2[2*np][0],bh2[2*np][1],bh2[2*np+1][0],bh2[2*np+1][1], bd);
      }
#pragma unroll
      for (int j=0;j<8;j++) mma16(sacc[j], qfh[kk], bh2[j]);
    }
  };

  // ================= Sweep 1: row sums (hi-only) =================
  issueK1(0,0); CPCOMMIT();
  issueK1(1,1); CPCOMMIT();
  float rs0=0.f, rs1=0.f;
  for (int nb=0;nb<NB;nb++){
    if (nb < NB-1) { CPWAIT(1); } else { CPWAIT(0); }
    __syncthreads();
    if (nb+2 < NB){ issueK1(nb+2,(nb+2)%STG); CPCOMMIT(); }
    float sacc[8][4];
    computeS1(nb%STG, sacc);
#pragma unroll
    for (int ni=0;ni<8;ni++){
      rs0 += __expf(sacc[ni][0]*0.125f) + __expf(sacc[ni][1]*0.125f);
      rs1 += __expf(sacc[ni][2]*0.125f) + __expf(sacc[ni][3]*0.125f);
    }
  }
  rs0 += __shfl_xor_sync(0xffffffffu, rs0, 1);
  rs0 += __shfl_xor_sync(0xffffffffu, rs0, 2);
  rs1 += __shfl_xor_sync(0xffffffffu, rs1, 1);
  rs1 += __shfl_xor_sync(0xffffffffu, rs1, 2);
  __syncthreads();                 // all sweep-1 reads done before restage
  if (tg==0){ sInv[wm+g] = 1.0f/rs0; sInv[wm+g+8] = 1.0f/rs1; }
  __syncthreads();
  const float inv0 = sInv[wm+g];
  const float inv1 = sInv[wm+g+8];

  // ================= Sweep 2: normalized attn + P@V =================
  float cacc[8][4];
#pragma unroll
  for (int ci=0;ci<8;ci++)
#pragma unroll
    for (int q=0;q<4;q++) cacc[ci][q]=0.f;

  issueKV(0,0); CPCOMMIT();
  issueKV(1,1); CPCOMMIT();
  for (int nb=0;nb<NB;nb++){
    if (nb < NB-1) { CPWAIT(1); } else { CPWAIT(0); }
    __syncthreads();
    if (nb+2 < NB){ issueKV(nb+2,(nb+2)%STG); CPCOMMIT(); }
    const int st = nb%STG;
    float sacc[8][4];
    computeS(st, sacc);

    float* arow0 = attn + (size_t)(m0+wm+g)*SS + nb*NBT;
    float* arow1 = arow0 + 8*SS;
#pragma unroll
    for (int ni=0;ni<8;ni++){
      float e0 = __expf(sacc[ni][0]*0.125f)*inv0;
      float e1 = __expf(sacc[ni][1]*0.125f)*inv0;
      float e2 = __expf(sacc[ni][2]*0.125f)*inv1;
      float e3 = __expf(sacc[ni][3]*0.125f)*inv1;
      sacc[ni][0]=e0; sacc[ni][1]=e1; sacc[ni][2]=e2; sacc[ni][3]=e3;
      float2 lo2; lo2.x=e0; lo2.y=e1;
      float2 hi2; hi2.x=e2; hi2.y=e3;
      __stcs((float2*)(arow0 + ni*8 + tg*2), lo2);
      __stcs((float2*)(arow1 + ni*8 + tg*2), hi2);
    }

#pragma unroll
    for (int kk=0;kk<4;kk++){
      const int f0=2*kk, f1=2*kk+1;
      unsigned pah[4], pal[4];
      pah[0]=pack2(hi_bf16(sacc[f0][0]), hi_bf16(sacc[f0][1]));
      pah[1]=pack2(hi_bf16(sacc[f0][2]), hi_bf16(sacc[f0][3]));
      pah[2]=pack2(hi_bf16(sacc[f1][0]), hi_bf16(sacc[f1][1]));
      pah[3]=pack2(hi_bf16(sacc[f1][2]), hi_bf16(sacc[f1][3]));
      pal[0]=pack2(lo_bf16(sacc[f0][0]), lo_bf16(sacc[f0][1]));
      pal[1]=pack2(lo_bf16(sacc[f0][2]), lo_bf16(sacc[f0][3]));
      pal[2]=pack2(lo_bf16(sacc[f1][0]), lo_bf16(sacc[f1][1]));
      pal[3]=pack2(lo_bf16(sacc[f1][2]), lo_bf16(sacc[f1][3]));
      unsigned vf[8][2];
#pragma unroll
      for (int cp=0;cp<4;cp++){
        unsigned vd = sptr(sVh + ((size_t)st*64 + cp*16 + bRowF)*PK + kk*16 + bColF);
        ldsm4(vf[2*cp][0],vf[2*cp][1],vf[2*cp+1][0],vf[2*cp+1][1], vd);
      }
#pragma unroll
      for (int j=0;j<8;j++) mma16(cacc[j], pah, vf[j]);
#pragma unroll
      for (int j=0;j<8;j++) mma16(cacc[j], pal, vf[j]);
#pragma unroll
      for (int cp=0;cp<4;cp++){
        unsigned vld = sptr(sVl + ((size_t)st*64 + cp*16 + bRowF)*PK + kk*16 + bColF);
        ldsm4(vf[2*cp][0],vf[2*cp][1],vf[2*cp+1][0],vf[2*cp+1][1], vld);
      }
#pragma unroll
      for (int j=0;j<8;j++) mma16(cacc[j], pah, vf[j]);
    }
  }

  const int b = bh>>4, h = bh&(NH-1);
#pragma unroll
  for (int ci=0;ci<8;ci++){
    const int d = h*DK + ci*8 + tg*2;
    const size_t o0 = ((size_t)(b*SS + m0+wm+g))*DM + d;
    const size_t o1 = o0 + (size_t)8*DM;
    *(unsigned*)(ch+o0) = pack2(hi_bf16(cacc[ci][0]), hi_bf16(cacc[ci][1]));
    *(unsigned*)(cl+o0) = pack2(lo_bf16(cacc[ci][0]), lo_bf16(cacc[ci][1]));
    *(unsigned*)(ch+o1) = pack2(hi_bf16(cacc[ci][2]), hi_bf16(cacc[ci][3]));
    *(unsigned*)(cl+o1) = pack2(lo_bf16(cacc[ci][2]), lo_bf16(cacc[ci][3]));
  }
}

extern "C" void kernel_launch(void* const* d_in, const int* in_sizes, int n_in,
                              void* d_out, int out_size){
  const float* Q   = (const float*)d_in[0];
  const float* K   = (const float*)d_in[1];
  const float* V   = (const float*)d_in[2];
  const float* Wq  = (const float*)d_in[3];
  const float* bq  = (const float*)d_in[4];
  const float* Wk  = (const float*)d_in[5];
  const float* bk  = (const float*)d_in[6];
  const float* Wv  = (const float*)d_in[7];
  const float* bv  = (const float*)d_in[8];
  const float* Wfc = (const float*)d_in[9];
  const float* bfc = (const float*)d_in[10];
  float* out_f = (float*)d_out;

  bf16 *Xh,*Xl,*Wth,*Wtl,*qkvh,*qkvl,*ch,*cl;
  float *bias3,*afb;
  cudaGetSymbolAddress((void**)&Xh, g_Xh);     cudaGetSymbolAddress((void**)&Xl, g_Xl);
  cudaGetSymbolAddress((void**)&Wth, g_Wth);   cudaGetSymbolAddress((void**)&Wtl, g_Wtl);
  cudaGetSymbolAddress((void**)&qkvh, g_qkvh); cudaGetSymbolAddress((void**)&qkvl, g_qkvl);
  cudaGetSymbolAddress((void**)&ch, g_ch);     cudaGetSymbolAddress((void**)&cl, g_cl);
  cudaGetSymbolAddress((void**)&bias3, g_bias3);
  cudaGetSymbolAddress((void**)&afb,  g_attn_fb);

  const size_t ATTN = (size_t)HEADS*SS*SS;
  float* attn = ((size_t)out_size >= ATTN) ? (out_f + ((size_t)out_size - ATTN)) : afb;

  const int SM_GEMMW = 2*(128*40 + 128*40)*2*2;      // 81920
  const int SM_FUSED = 12*64*72*2 + 512;             // 111104 (3-stage KV, no Q smem)

  cudaFuncSetAttribute(gemmW<0>, cudaFuncAttributeMaxDynamicSharedMemorySize, SM_GEMMW);
  cudaFuncSetAttribute(gemmW<3>, cudaFuncAttributeMaxDynamicSharedMemorySize, SM_GEMMW);
  cudaFuncSetAttribute(fused_attn, cudaFuncAttributeMaxDynamicSharedMemorySize, SM_FUSED);

  dim3 blk(256);

  cudaMemcpyAsync(bias3,        bq, DM*sizeof(float), cudaMemcpyDeviceToDevice);
  cudaMemcpyAsync(bias3 + DM,   bk, DM*sizeof(float), cudaMemcpyDeviceToDevice);
  cudaMemcpyAsync(bias3 + 2*DM, bv, DM*sizeof(float), cudaMemcpyDeviceToDevice);

  cvtX<<<dim3(NXE/4/256,1,3), blk>>>(Q,K,V, Xh,Xl);
  cvtWt<<<dim3(32,32,4), dim3(32,8)>>>(Wq,Wk,Wv,Wfc, Wth,Wtl);

  gemmW<0><<<dim3(8,32,3), blk, SM_GEMMW>>>(
      Xh, Xl, Wth, Wtl, bias3, nullptr, qkvh, qkvl);

  fused_attn<<<dim3(SS/128, HEADS), blk, SM_FUSED>>>(
      qkvh, qkvl,
      qkvh + (size_t)QKVE, qkvl + (size_t)QKVE,
      qkvh + 2*(size_t)QKVE, qkvl + 2*(size_t)QKVE,
      attn, ch, cl);

  gemmW<3><<<dim3(8,32), blk, SM_GEMMW>>>(
      ch, cl, Wth + 3*(size_t)NWE, Wtl + 3*(size_t)NWE, bfc, out_f, nullptr, nullptr);
}

// round 13
// speedup vs baseline: 4.0581x; 1.3510x over previous
#include <cuda_runtime.h>
#include <cuda_fp16.h>
#include <cstdint>

using fp16 = __half;

#define BB 2
#define SS 2048
#define DM 1024
#define NH 16
#define DK 64
#define MROWS (BB*SS)       // 4096
#define HEADS (BB*NH)       // 32
#define NXE (MROWS*DM)      // 4194304
#define NWE (DM*DM)         // 1048576
#define QKVE (HEADS*SS*DK)  // 4194304

// ---------------- scratch ----------------
__device__ fp16 g_Xh[3*NXE], g_Xl[3*NXE];     // converted Q,K,V inputs (hi+lo)
__device__ fp16 g_Wth[4*NWE];                 // transposed weights [N][K], hi only
__device__ fp16 g_qh[QKVE], g_ql[QKVE];       // q head-split (hi+lo)
__device__ fp16 g_kh[QKVE];                   // k head-split (hi only)
__device__ fp16 g_vh[QKVE];                   // v transposed [bh][dk][seq] (hi only)
__device__ fp16 g_ch[MROWS*DM], g_cl[MROWS*DM];
__device__ float g_bias3[3*DM];
__device__ float g_attn_fb[(size_t)HEADS*SS*SS];

// ---------------- helpers ----------------
__device__ __forceinline__ unsigned sptr(const void* p){
  return (unsigned)__cvta_generic_to_shared(p);
}
#define CP16(d,s) asm volatile("cp.async.cg.shared.global [%0], [%1], 16;\n" :: "r"(d), "l"(s))
#define CPCOMMIT() asm volatile("cp.async.commit_group;\n")
#define CPWAIT(N)  asm volatile("cp.async.wait_group %0;\n" :: "n"(N))

__device__ __forceinline__ void ldsm4(unsigned& r0, unsigned& r1, unsigned& r2, unsigned& r3,
                                      unsigned saddr){
  asm volatile("ldmatrix.sync.aligned.m8n8.x4.shared.b16 {%0,%1,%2,%3}, [%4];"
    : "=r"(r0), "=r"(r1), "=r"(r2), "=r"(r3) : "r"(saddr));
}

__device__ __forceinline__ unsigned pack2h(fp16 x, fp16 y){
  __half2 t = __halves2half2(x, y);
  return *reinterpret_cast<unsigned*>(&t);
}
__device__ __forceinline__ fp16 hi_f16(float v){ return __float2half_rn(v); }
__device__ __forceinline__ fp16 lo_f16(float v){
  fp16 h = __float2half_rn(v);
  return __float2half_rn(v - __half2float(h));
}
__device__ __forceinline__ void mma16(float c[4], const unsigned a[4], const unsigned b[2]){
  asm volatile(
    "mma.sync.aligned.m16n8k16.row.col.f32.f16.f16.f32 "
    "{%0,%1,%2,%3},{%4,%5,%6,%7},{%8,%9},{%0,%1,%2,%3};\n"
    : "+f"(c[0]), "+f"(c[1]), "+f"(c[2]), "+f"(c[3])
    : "r"(a[0]), "r"(a[1]), "r"(a[2]), "r"(a[3]), "r"(b[0]), "r"(b[1]));
}

// fp32 -> fp16 hi/lo for the 3 input tensors (z selects)
__global__ void cvtX(const float* p0, const float* p1, const float* p2,
                     fp16* __restrict__ Xh, fp16* __restrict__ Xl){
  const int z = blockIdx.z;
  const float* in = (z==0)?p0:(z==1)?p1:p2;
  fp16* hi = Xh + (size_t)z*NXE;
  fp16* lo = Xl + (size_t)z*NXE;
  const int i = blockIdx.x*blockDim.x + threadIdx.x;
  float4 v = ((const float4*)in)[i];
  uint2 uh, ul;
  uh.x = pack2h(hi_f16(v.x), hi_f16(v.y));
  uh.y = pack2h(hi_f16(v.z), hi_f16(v.w));
  ul.x = pack2h(lo_f16(v.x), lo_f16(v.y));
  ul.y = pack2h(lo_f16(v.z), lo_f16(v.w));
  ((uint2*)hi)[i] = uh;
  ((uint2*)lo)[i] = ul;
}

// fp32 W[K][N] -> transposed fp16 Wt[N][K] (hi only)
__global__ void cvtWt(const float* p0, const float* p1, const float* p2, const float* p3,
                      fp16* __restrict__ Wth){
  __shared__ float t[32][33];
  const int z = blockIdx.z;
  const float* in = (z==0)?p0:(z==1)?p1:(z==2)?p2:p3;
  fp16* hi = Wth + (size_t)z*NWE;
  const int tx = threadIdx.x, ty = threadIdx.y;
  const int n0 = blockIdx.x*32, k0 = blockIdx.y*32;
#pragma unroll
  for (int i=0;i<4;i++){
    const int k = ty + 8*i;
    t[k][tx] = in[(size_t)(k0+k)*DM + n0 + tx];
  }
  __syncthreads();
#pragma unroll
  for (int i=0;i<4;i++){
    const int n = ty + 8*i;
    hi[(size_t)(n0+n)*DM + k0 + tx] = hi_f16(t[tx][n]);
  }
}

// ---------------------------------------------------------------------------
// fp16 2-term GEMM: C = (Ah+Al) @ Wth^T. 3-stage single-sync ring, 2 CTAs/SM.
// EPI 0: proj (z: 0=q hi+lo head-split, 1=k hi head-split, 2=v hi transposed)
// EPI 3: out-proj (bias, fp32 out)
// ---------------------------------------------------------------------------
template<int EPI>
__global__ void __launch_bounds__(256,2)
gemmW(const fp16* __restrict__ Ahp, const fp16* __restrict__ Alp,
      const fp16* __restrict__ Bhp,
      const float* __restrict__ biasp, float* __restrict__ outf,
      fp16* __restrict__ oqh, fp16* __restrict__ oql,
      fp16* __restrict__ okh, fp16* __restrict__ ovh)
{
  constexpr int BM=128, BN=128, BK=32, STG=3, PK=40;
  constexpr int WM=64, WN=32, MF=4, NF=4;

  extern __shared__ fp16 smx[];
  fp16* sAh = smx;
  fp16* sAl = sAh + STG*BM*PK;
  fp16* sBh = sAl + STG*BM*PK;

  const int tid=threadIdx.x, lane=tid&31, wid=tid>>5;
  const int g=lane>>2, tg=lane&3;
  const int warp_m=wid>>2, warp_n=wid&3;
  const int wm=warp_m*WM, wn=warp_n*WN;
  const int m0=blockIdx.y*BM, n0=blockIdx.x*BN, z=blockIdx.z;

  const int aRowF = (lane&7) + ((lane>>3)&1)*8;
  const int aColF = ((lane>>4)&1)*8;
  const int bRowF = (lane&7) + ((lane>>4)&1)*8;
  const int bColF = ((lane>>3)&1)*8;

  const fp16 *Ah=Ahp, *Al=Alp, *Bh=Bhp;
  const float* bias = biasp;
  if constexpr (EPI==0){
    Ah += (size_t)z*NXE;  Al += (size_t)z*NXE;
    Bh += (size_t)z*NWE;
    bias += z*DM;
  }

  const int ar=tid>>1, ac=(tid&1)*16;

  float acc[MF][NF][4];
#pragma unroll
  for (int mi=0;mi<MF;mi++)
#pragma unroll
    for (int ni=0;ni<NF;ni++)
#pragma unroll
      for (int q=0;q<4;q++) acc[mi][ni][q]=0.f;

  const int T = DM/BK;   // 32

  auto issue = [&](int t){
    const int st = t % STG;
    const int k0 = t*BK;
    const fp16* s = Ah + (size_t)(m0+ar)*DM + k0 + ac;
    unsigned d = sptr(sAh + ((size_t)st*BM+ar)*PK + ac);
    CP16(d, s); CP16(d+16, s+8);
    const fp16* s2 = Al + (size_t)(m0+ar)*DM + k0 + ac;
    unsigned d2 = sptr(sAl + ((size_t)st*BM+ar)*PK + ac);
    CP16(d2, s2); CP16(d2+16, s2+8);
    const fp16* s3 = Bh + (size_t)(n0+ar)*DM + k0 + ac;
    unsigned d3 = sptr(sBh + ((size_t)st*BN+ar)*PK + ac);
    CP16(d3, s3); CP16(d3+16, s3+8);
    CPCOMMIT();
  };

  auto compute = [&](int st){
#pragma unroll
    for (int s16=0; s16<2; s16++){
      const int kc = s16*16;
      unsigned ah[MF][4], al[MF][4], bh[NF][2];
#pragma unroll
      for (int mi=0;mi<MF;mi++){
        unsigned ad = sptr(sAh + ((size_t)st*BM + wm + mi*16 + aRowF)*PK + kc + aColF);
        ldsm4(ah[mi][0],ah[mi][1],ah[mi][2],ah[mi][3], ad);
        unsigned ad2 = sptr(sAl + ((size_t)st*BM + wm + mi*16 + aRowF)*PK + kc + aColF);
        ldsm4(al[mi][0],al[mi][1],al[mi][2],al[mi][3], ad2);
      }
#pragma unroll
      for (int np=0;np<2;np++){
        unsigned bd = sptr(sBh + ((size_t)st*BN + wn + np*16 + bRowF)*PK + kc + bColF);
        ldsm4(bh[2*np][0], bh[2*np][1], bh[2*np+1][0], bh[2*np+1][1], bd);
      }
#pragma unroll
      for (int mi=0;mi<MF;mi++)
#pragma unroll
        for (int ni=0;ni<NF;ni++) mma16(acc[mi][ni], ah[mi], bh[ni]);
#pragma unroll
      for (int mi=0;mi<MF;mi++)
#pragma unroll
        for (int ni=0;ni<NF;ni++) mma16(acc[mi][ni], al[mi], bh[ni]);
    }
  };

  issue(0); issue(1);
  for (int t=0;t<T;t++){
    CPWAIT(1);
    __syncthreads();
    if (t+2<T) issue(t+2); else CPCOMMIT();   // uniform commit accounting
    compute(t % STG);
  }

  if constexpr (EPI==0){
#pragma unroll
    for (int mi=0;mi<MF;mi++)
#pragma unroll
      for (int hf=0;hf<2;hf++){
        const int m = m0 + wm + mi*16 + g + hf*8;
        const int b = m >> 11, s = m & (SS-1);
#pragma unroll
        for (int ni=0;ni<NF;ni++){
          const int n = n0 + wn + ni*8 + tg*2;
          const int h = n >> 6, d = n & 63;
          float y0 = acc[mi][ni][hf*2+0] + bias[n];
          float y1 = acc[mi][ni][hf*2+1] + bias[n+1];
          if (z==0){
            const size_t o = (((size_t)b*NH + h)*SS + s)*DK + d;
            *(unsigned*)(oqh+o) = pack2h(hi_f16(y0), hi_f16(y1));
            *(unsigned*)(oql+o) = pack2h(lo_f16(y0), lo_f16(y1));
          } else if (z==1){
            const size_t o = (((size_t)b*NH + h)*SS + s)*DK + d;
            *(unsigned*)(okh+o) = pack2h(hi_f16(y0), hi_f16(y1));
          } else {
            const size_t o0 = (((size_t)b*NH + h)*DK + d)*SS + s;
            ovh[o0]      = hi_f16(y0);
            ovh[o0 + SS] = hi_f16(y1);
          }
        }
      }
  } else {
#pragma unroll
    for (int mi=0;mi<MF;mi++)
#pragma unroll
      for (int hf=0;hf<2;hf++){
        const int m = m0 + wm + mi*16 + g + hf*8;
#pragma unroll
        for (int ni=0;ni<NF;ni++){
          const int n = n0 + wn + ni*8 + tg*2;
          float2 y;
          y.x = acc[mi][ni][hf*2+0] + bias[n];
          y.y = acc[mi][ni][hf*2+1] + bias[n+1];
          *(float2*)(outf + (size_t)m*DM + n) = y;
        }
      }
  }
}

// ---------------------------------------------------------------------------
// Fused attention, fp16. K/V hi-only in smem, 4-stage pipeline, uniform commit.
// Sweep 1: qh*kh rowsums. Sweep 2: (qh+ql)*kh scores -> exp -> normalized attn
// write + (Ph+Pl)*vh in registers.
// ---------------------------------------------------------------------------
__global__ void __launch_bounds__(256,2)
fused_attn(const fp16* __restrict__ qh_, const fp16* __restrict__ ql_,
           const fp16* __restrict__ kh_, const fp16* __restrict__ vh_,
           float* __restrict__ attn_, fp16* __restrict__ ch, fp16* __restrict__ cl)
{
  constexpr int PK=72, NBT=64, NB=SS/NBT, STG=4;
  extern __shared__ fp16 sm[];
  fp16* sKh = sm;                    // 4 * 64*72
  fp16* sVh = sKh + STG*64*PK;       // 4 * 64*72
  float* sInv = (float*)(sVh + STG*64*PK);

  const int tid=threadIdx.x, lane=tid&31;
  const int g=lane>>2, tg=lane&3;
  const int wm = (tid>>5)*16;
  const int m0 = blockIdx.x*128;
  const int bh = blockIdx.y;

  const int bRowF = (lane&7) + ((lane>>4)&1)*8;
  const int bColF = ((lane>>3)&1)*8;

  const fp16* qh = qh_ + (size_t)(bh*SS+m0)*DK;
  const fp16* ql = ql_ + (size_t)(bh*SS+m0)*DK;
  const fp16* kh = kh_ + (size_t)bh*SS*DK;
  const fp16* vh = vh_ + (size_t)bh*DK*SS;
  float* attn = attn_ + (size_t)bh*SS*SS;

  auto issueK = [&](int nb,int st){
    const int row=tid>>2, s=tid&3;
    const fp16* sh = kh + (size_t)(nb*NBT+row)*DK;
    unsigned dh = sptr(sKh + (st*64+row)*PK);
    CP16(dh+s*16, sh+s*8);  CP16(dh+(s+4)*16, sh+(s+4)*8);
  };
  auto issueKV = [&](int nb,int st){
    const int row=tid>>2, s=tid&3;
    const fp16* skh = kh + (size_t)(nb*NBT+row)*DK;
    unsigned dkh = sptr(sKh + (st*64+row)*PK);
    CP16(dkh+s*16, skh+s*8);  CP16(dkh+(s+4)*16, skh+(s+4)*8);
    const fp16* svh = vh + (size_t)row*SS + nb*NBT;
    unsigned dvh = sptr(sVh + (st*64+row)*PK);
    CP16(dvh+s*16, svh+s*8);  CP16(dvh+(s+4)*16, svh+(s+4)*8);
  };

  // Q fragments from gmem (ldmatrix-equivalent distribution)
  unsigned qfh[4][4], qfl[4][4];
#pragma unroll
  for (int kk=0;kk<4;kk++){
    const int c = kk*16 + tg*2;
    qfh[kk][0] = *(const unsigned*)(qh + (size_t)(wm+g  )*DK + c);
    qfh[kk][1] = *(const unsigned*)(qh + (size_t)(wm+g+8)*DK + c);
    qfh[kk][2] = *(const unsigned*)(qh + (size_t)(wm+g  )*DK + c+8);
    qfh[kk][3] = *(const unsigned*)(qh + (size_t)(wm+g+8)*DK + c+8);
    qfl[kk][0] = *(const unsigned*)(ql + (size_t)(wm+g  )*DK + c);
    qfl[kk][1] = *(const unsigned*)(ql + (size_t)(wm+g+8)*DK + c);
    qfl[kk][2] = *(const unsigned*)(ql + (size_t)(wm+g  )*DK + c+8);
    qfl[kk][3] = *(const unsigned*)(ql + (size_t)(wm+g+8)*DK + c+8);
  }

  // 2-term S: (qh+ql)*kh
  auto computeS = [&](int st, float sacc[8][4]){
#pragma unroll
    for (int ni=0;ni<8;ni++)
#pragma unroll
      for (int q=0;q<4;q++) sacc[ni][q]=0.f;
#pragma unroll
    for (int kk=0;kk<4;kk++){
      unsigned bh2[8][2];
#pragma unroll
      for (int np=0;np<4;np++){
        unsigned bd = sptr(sKh + ((size_t)st*64 + np*16 + bRowF)*PK + kk*16 + bColF);
        ldsm4(bh2[2*np][0],bh2[2*np][1],bh2[2*np+1][0],bh2[2*np+1][1], bd);
      }
#pragma unroll
      for (int j=0;j<8;j++) mma16(sacc[j], qfh[kk], bh2[j]);
#pragma unroll
      for (int j=0;j<8;j++) mma16(sacc[j], qfl[kk], bh2[j]);
    }
  };
  // 1-term S (rowsums)
  auto computeS1 = [&](int st, float sacc[8][4]){
#pragma unroll
    for (int ni=0;ni<8;ni++)
#pragma unroll
      for (int q=0;q<4;q++) sacc[ni][q]=0.f;
#pragma unroll
    for (int kk=0;kk<4;kk++){
      unsigned bh2[8][2];
#pragma unroll
      for (int np=0;np<4;np++){
        unsigned bd = sptr(sKh + ((size_t)st*64 + np*16 + bRowF)*PK + kk*16 + bColF);
        ldsm4(bh2[2*np][0],bh2[2*np][1],bh2[2*np+1][0],bh2[2*np+1][1], bd);
      }
#pragma unroll
      for (int j=0;j<8;j++) mma16(sacc[j], qfh[kk], bh2[j]);
    }
  };

  // ================= Sweep 1: row sums =================
  issueK(0,0); CPCOMMIT();
  issueK(1,1); CPCOMMIT();
  issueK(2,2); CPCOMMIT();
  float rs0=0.f, rs1=0.f;
  for (int nb=0;nb<NB;nb++){
    CPWAIT(2);
    __syncthreads();
    if (nb+3 < NB){ issueK(nb+3,(nb+3)%STG); CPCOMMIT(); } else { CPCOMMIT(); }
    float sacc[8][4];
    computeS1(nb%STG, sacc);
#pragma unroll
    for (int ni=0;ni<8;ni++){
      rs0 += __expf(sacc[ni][0]*0.125f) + __expf(sacc[ni][1]*0.125f);
      rs1 += __expf(sacc[ni][2]*0.125f) + __expf(sacc[ni][3]*0.125f);
    }
  }
  rs0 += __shfl_xor_sync(0xffffffffu, rs0, 1);
  rs0 += __shfl_xor_sync(0xffffffffu, rs0, 2);
  rs1 += __shfl_xor_sync(0xffffffffu, rs1, 1);
  rs1 += __shfl_xor_sync(0xffffffffu, rs1, 2);
  __syncthreads();                 // all sweep-1 smem reads done before restage
  if (tg==0){ sInv[wm+g] = 1.0f/rs0; sInv[wm+g+8] = 1.0f/rs1; }
  __syncthreads();
  const float inv0 = sInv[wm+g];
  const float inv1 = sInv[wm+g+8];

  // ================= Sweep 2: normalized attn + P@V =================
  float cacc[8][4];
#pragma unroll
  for (int ci=0;ci<8;ci++)
#pragma unroll
    for (int q=0;q<4;q++) cacc[ci][q]=0.f;

  issueKV(0,0); CPCOMMIT();
  issueKV(1,1); CPCOMMIT();
  issueKV(2,2); CPCOMMIT();
  for (int nb=0;nb<NB;nb++){
    CPWAIT(2);
    __syncthreads();
    if (nb+3 < NB){ issueKV(nb+3,(nb+3)%STG); CPCOMMIT(); } else { CPCOMMIT(); }
    const int st = nb%STG;
    float sacc[8][4];
    computeS(st, sacc);

    float* arow0 = attn + (size_t)(m0+wm+g)*SS + nb*NBT;
    float* arow1 = arow0 + 8*SS;
#pragma unroll
    for (int ni=0;ni<8;ni++){
      float e0 = __expf(sacc[ni][0]*0.125f)*inv0;
      float e1 = __expf(sacc[ni][1]*0.125f)*inv0;
      float e2 = __expf(sacc[ni][2]*0.125f)*inv1;
      float e3 = __expf(sacc[ni][3]*0.125f)*inv1;
      sacc[ni][0]=e0; sacc[ni][1]=e1; sacc[ni][2]=e2; sacc[ni][3]=e3;
      float2 lo2; lo2.x=e0; lo2.y=e1;
      float2 hi2; hi2.x=e2; hi2.y=e3;
      __stcs((float2*)(arow0 + ni*8 + tg*2), lo2);
      __stcs((float2*)(arow1 + ni*8 + tg*2), hi2);
    }

#pragma unroll
    for (int kk=0;kk<4;kk++){
      const int f0=2*kk, f1=2*kk+1;
      unsigned pah[4], pal[4];
      pah[0]=pack2h(hi_f16(sacc[f0][0]), hi_f16(sacc[f0][1]));
      pah[1]=pack2h(hi_f16(sacc[f0][2]), hi_f16(sacc[f0][3]));
      pah[2]=pack2h(hi_f16(sacc[f1][0]), hi_f16(sacc[f1][1]));
      pah[3]=pack2h(hi_f16(sacc[f1][2]), hi_f16(sacc[f1][3]));
      pal[0]=pack2h(lo_f16(sacc[f0][0]), lo_f16(sacc[f0][1]));
      pal[1]=pack2h(lo_f16(sacc[f0][2]), lo_f16(sacc[f0][3]));
      pal[2]=pack2h(lo_f16(sacc[f1][0]), lo_f16(sacc[f1][1]));
      pal[3]=pack2h(lo_f16(sacc[f1][2]), lo_f16(sacc[f1][3]));
      unsigned vf[8][2];
#pragma unroll
      for (int cp=0;cp<4;cp++){
        unsigned vd = sptr(sVh + ((size_t)st*64 + cp*16 + bRowF)*PK + kk*16 + bColF);
        ldsm4(vf[2*cp][0],vf[2*cp][1],vf[2*cp+1][0],vf[2*cp+1][1], vd);
      }
#pragma unroll
      for (int j=0;j<8;j++) mma16(cacc[j], pah, vf[j]);
#pragma unroll
      for (int j=0;j<8;j++) mma16(cacc[j], pal, vf[j]);
    }
  }

  const int b = bh>>4, h = bh&(NH-1);
#pragma unroll
  for (int ci=0;ci<8;ci++){
    const int d = h*DK + ci*8 + tg*2;
    const size_t o0 = ((size_t)(b*SS + m0+wm+g))*DM + d;
    const size_t o1 = o0 + (size_t)8*DM;
    *(unsigned*)(ch+o0) = pack2h(hi_f16(cacc[ci][0]), hi_f16(cacc[ci][1]));
    *(unsigned*)(cl+o0) = pack2h(lo_f16(cacc[ci][0]), lo_f16(cacc[ci][1]));
    *(unsigned*)(ch+o1) = pack2h(hi_f16(cacc[ci][2]), hi_f16(cacc[ci][3]));
    *(unsigned*)(cl+o1) = pack2h(lo_f16(cacc[ci][2]), lo_f16(cacc[ci][3]));
  }
}

extern "C" void kernel_launch(void* const* d_in, const int* in_sizes, int n_in,
                              void* d_out, int out_size){
  const float* Q   = (const float*)d_in[0];
  const float* K   = (const float*)d_in[1];
  const float* V   = (const float*)d_in[2];
  const float* Wq  = (const float*)d_in[3];
  const float* bq  = (const float*)d_in[4];
  const float* Wk  = (const float*)d_in[5];
  const float* bk  = (const float*)d_in[6];
  const float* Wv  = (const float*)d_in[7];
  const float* bv  = (const float*)d_in[8];
  const float* Wfc = (const float*)d_in[9];
  const float* bfc = (const float*)d_in[10];
  float* out_f = (float*)d_out;

  fp16 *Xh,*Xl,*Wth,*qh,*ql,*kh,*vh,*ch,*cl;
  float *bias3,*afb;
  cudaGetSymbolAddress((void**)&Xh, g_Xh);   cudaGetSymbolAddress((void**)&Xl, g_Xl);
  cudaGetSymbolAddress((void**)&Wth, g_Wth);
  cudaGetSymbolAddress((void**)&qh, g_qh);   cudaGetSymbolAddress((void**)&ql, g_ql);
  cudaGetSymbolAddress((void**)&kh, g_kh);   cudaGetSymbolAddress((void**)&vh, g_vh);
  cudaGetSymbolAddress((void**)&ch, g_ch);   cudaGetSymbolAddress((void**)&cl, g_cl);
  cudaGetSymbolAddress((void**)&bias3, g_bias3);
  cudaGetSymbolAddress((void**)&afb,  g_attn_fb);

  const size_t ATTN = (size_t)HEADS*SS*SS;
  float* attn = ((size_t)out_size >= ATTN) ? (out_f + ((size_t)out_size - ATTN)) : afb;

  const int SM_GEMMW = 3*3*128*40*2;                 // 92160 (3 stages x {Ah,Al,Bh})
  const int SM_FUSED = 2*4*64*72*2 + 512;            // 74240 (4-stage K + 4-stage V)

  cudaFuncSetAttribute(gemmW<0>, cudaFuncAttributeMaxDynamicSharedMemorySize, SM_GEMMW);
  cudaFuncSetAttribute(gemmW<3>, cudaFuncAttributeMaxDynamicSharedMemorySize, SM_GEMMW);
  cudaFuncSetAttribute(fused_attn, cudaFuncAttributeMaxDynamicSharedMemorySize, SM_FUSED);

  dim3 blk(256);

  cudaMemcpyAsync(bias3,        bq, DM*sizeof(float), cudaMemcpyDeviceToDevice);
  cudaMemcpyAsync(bias3 + DM,   bk, DM*sizeof(float), cudaMemcpyDeviceToDevice);
  cudaMemcpyAsync(bias3 + 2*DM, bv, DM*sizeof(float), cudaMemcpyDeviceToDevice);

  cvtX<<<dim3(NXE/4/256,1,3), blk>>>(Q,K,V, Xh,Xl);
  cvtWt<<<dim3(32,32,4), dim3(32,8)>>>(Wq,Wk,Wv,Wfc, Wth);

  // Q/K/V projections (z: 0=q hi+lo, 1=k hi, 2=v hi transposed)
  gemmW<0><<<dim3(8,32,3), blk, SM_GEMMW>>>(
      Xh, Xl, Wth, bias3, nullptr, qh, ql, kh, vh);

  fused_attn<<<dim3(SS/128, HEADS), blk, SM_FUSED>>>(
      qh, ql, kh, vh, attn, ch, cl);

  // output projection: ctx(hi+lo) @ Wfc(hi)
  gemmW<3><<<dim3(8,32), blk, SM_GEMMW>>>(
      ch, cl, Wth + 3*(size_t)NWE, bfc, out_f, nullptr, nullptr, nullptr, nullptr);
}

// round 14
// speedup vs baseline: 4.9049x; 1.2087x over previous
#include <cuda_runtime.h>
#include <cuda_fp16.h>
#include <cstdint>

using fp16 = __half;

#define BB 2
#define SS 2048
#define DM 1024
#define NH 16
#define DK 64
#define MROWS (BB*SS)       // 4096
#define HEADS (BB*NH)       // 32
#define NXE (MROWS*DM)      // 4194304
#define NWE (DM*DM)         // 1048576
#define QKVE (HEADS*SS*DK)  // 4194304

// ---------------- scratch ----------------
__device__ fp16 g_Xh[3*NXE], g_Xl[3*NXE];     // converted Q,K,V inputs (hi+lo)
__device__ fp16 g_Wth[4*NWE];                 // transposed weights [N][K], hi only
__device__ fp16 g_qh[QKVE];                   // q head-split (hi)
__device__ fp16 g_kh[QKVE];                   // k head-split (hi)
__device__ fp16 g_vh[QKVE];                   // v transposed [bh][dk][seq] (hi)
__device__ fp16 g_ch[MROWS*DM];               // ctx merged heads (hi)
__device__ float g_bias3[3*DM];
__device__ float g_attn_fb[(size_t)HEADS*SS*SS];

// ---------------- helpers ----------------
__device__ __forceinline__ unsigned sptr(const void* p){
  return (unsigned)__cvta_generic_to_shared(p);
}
#define CP16(d,s) asm volatile("cp.async.cg.shared.global [%0], [%1], 16;\n" :: "r"(d), "l"(s))
#define CPCOMMIT() asm volatile("cp.async.commit_group;\n")
#define CPWAIT(N)  asm volatile("cp.async.wait_group %0;\n" :: "n"(N))

__device__ __forceinline__ void ldsm4(unsigned& r0, unsigned& r1, unsigned& r2, unsigned& r3,
                                      unsigned saddr){
  asm volatile("ldmatrix.sync.aligned.m8n8.x4.shared.b16 {%0,%1,%2,%3}, [%4];"
    : "=r"(r0), "=r"(r1), "=r"(r2), "=r"(r3) : "r"(saddr));
}

__device__ __forceinline__ unsigned pack2h(fp16 x, fp16 y){
  __half2 t = __halves2half2(x, y);
  return *reinterpret_cast<unsigned*>(&t);
}
__device__ __forceinline__ fp16 hi_f16(float v){ return __float2half_rn(v); }
__device__ __forceinline__ fp16 lo_f16(float v){
  fp16 h = __float2half_rn(v);
  return __float2half_rn(v - __half2float(h));
}
__device__ __forceinline__ void mma16(float c[4], const unsigned a[4], const unsigned b[2]){
  asm volatile(
    "mma.sync.aligned.m16n8k16.row.col.f32.f16.f16.f32 "
    "{%0,%1,%2,%3},{%4,%5,%6,%7},{%8,%9},{%0,%1,%2,%3};\n"
    : "+f"(c[0]), "+f"(c[1]), "+f"(c[2]), "+f"(c[3])
    : "r"(a[0]), "r"(a[1]), "r"(a[2]), "r"(a[3]), "r"(b[0]), "r"(b[1]));
}

// fp32 -> fp16 hi/lo for the 3 input tensors (z selects)
__global__ void cvtX(const float* p0, const float* p1, const float* p2,
                     fp16* __restrict__ Xh, fp16* __restrict__ Xl){
  const int z = blockIdx.z;
  const float* in = (z==0)?p0:(z==1)?p1:p2;
  fp16* hi = Xh + (size_t)z*NXE;
  fp16* lo = Xl + (size_t)z*NXE;
  const int i = blockIdx.x*blockDim.x + threadIdx.x;
  float4 v = ((const float4*)in)[i];
  uint2 uh, ul;
  uh.x = pack2h(hi_f16(v.x), hi_f16(v.y));
  uh.y = pack2h(hi_f16(v.z), hi_f16(v.w));
  ul.x = pack2h(lo_f16(v.x), lo_f16(v.y));
  ul.y = pack2h(lo_f16(v.z), lo_f16(v.w));
  ((uint2*)hi)[i] = uh;
  ((uint2*)lo)[i] = ul;
}

// fp32 W[K][N] -> transposed fp16 Wt[N][K] (hi only)
__global__ void cvtWt(const float* p0, const float* p1, const float* p2, const float* p3,
                      fp16* __restrict__ Wth){
  __shared__ float t[32][33];
  const int z = blockIdx.z;
  const float* in = (z==0)?p0:(z==1)?p1:(z==2)?p2:p3;
  fp16* hi = Wth + (size_t)z*NWE;
  const int tx = threadIdx.x, ty = threadIdx.y;
  const int n0 = blockIdx.x*32, k0 = blockIdx.y*32;
#pragma unroll
  for (int i=0;i<4;i++){
    const int k = ty + 8*i;
    t[k][tx] = in[(size_t)(k0+k)*DM + n0 + tx];
  }
  __syncthreads();
#pragma unroll
  for (int i=0;i<4;i++){
    const int n = ty + 8*i;
    hi[(size_t)(n0+n)*DM + k0 + tx] = hi_f16(t[tx][n]);
  }
}

// ---------------------------------------------------------------------------
// fp16 GEMM: C = A @ Wth^T. TERMS=2: A = Ah+Al (proj). TERMS=1: A = Ah (outproj).
// 3-stage single-sync ring, 2 CTAs/SM.
// EPI 0: proj (z: 0=q hi head-split, 1=k hi head-split, 2=v hi transposed)
// EPI 3: out-proj (bias, fp32 out)
// ---------------------------------------------------------------------------
template<int EPI, int TERMS>
__global__ void __launch_bounds__(256,2)
gemmW(const fp16* __restrict__ Ahp, const fp16* __restrict__ Alp,
      const fp16* __restrict__ Bhp,
      const float* __restrict__ biasp, float* __restrict__ outf,
      fp16* __restrict__ oqh, fp16* __restrict__ okh, fp16* __restrict__ ovh)
{
  constexpr int BM=128, BN=128, BK=32, STG=3, PK=40;
  constexpr int WM=64, WN=32, MF=4, NF=4;

  extern __shared__ fp16 smx[];
  fp16* sAh = smx;
  fp16* sAl = sAh + STG*BM*PK;                       // only used if TERMS==2
  fp16* sBh = (TERMS==2) ? (sAl + STG*BM*PK) : sAl;

  const int tid=threadIdx.x, lane=tid&31, wid=tid>>5;
  const int g=lane>>2, tg=lane&3;
  const int warp_m=wid>>2, warp_n=wid&3;
  const int wm=warp_m*WM, wn=warp_n*WN;
  const int m0=blockIdx.y*BM, n0=blockIdx.x*BN, z=blockIdx.z;

  const int aRowF = (lane&7) + ((lane>>3)&1)*8;
  const int aColF = ((lane>>4)&1)*8;
  const int bRowF = (lane&7) + ((lane>>4)&1)*8;
  const int bColF = ((lane>>3)&1)*8;

  const fp16 *Ah=Ahp, *Al=Alp, *Bh=Bhp;
  const float* bias = biasp;
  if constexpr (EPI==0){
    Ah += (size_t)z*NXE;  Al += (size_t)z*NXE;
    Bh += (size_t)z*NWE;
    bias += z*DM;
  }

  const int ar=tid>>1, ac=(tid&1)*16;

  float acc[MF][NF][4];
#pragma unroll
  for (int mi=0;mi<MF;mi++)
#pragma unroll
    for (int ni=0;ni<NF;ni++)
#pragma unroll
      for (int q=0;q<4;q++) acc[mi][ni][q]=0.f;

  const int T = DM/BK;   // 32

  auto issue = [&](int t){
    const int st = t % STG;
    const int k0 = t*BK;
    const fp16* s = Ah + (size_t)(m0+ar)*DM + k0 + ac;
    unsigned d = sptr(sAh + ((size_t)st*BM+ar)*PK + ac);
    CP16(d, s); CP16(d+16, s+8);
    if constexpr (TERMS==2){
      const fp16* s2 = Al + (size_t)(m0+ar)*DM + k0 + ac;
      unsigned d2 = sptr(sAl + ((size_t)st*BM+ar)*PK + ac);
      CP16(d2, s2); CP16(d2+16, s2+8);
    }
    const fp16* s3 = Bh + (size_t)(n0+ar)*DM + k0 + ac;
    unsigned d3 = sptr(sBh + ((size_t)st*BN+ar)*PK + ac);
    CP16(d3, s3); CP16(d3+16, s3+8);
    CPCOMMIT();
  };

  auto compute = [&](int st){
#pragma unroll
    for (int s16=0; s16<2; s16++){
      const int kc = s16*16;
      unsigned ah[MF][4], al[MF][4], bh[NF][2];
#pragma unroll
      for (int mi=0;mi<MF;mi++){
        unsigned ad = sptr(sAh + ((size_t)st*BM + wm + mi*16 + aRowF)*PK + kc + aColF);
        ldsm4(ah[mi][0],ah[mi][1],ah[mi][2],ah[mi][3], ad);
        if constexpr (TERMS==2){
          unsigned ad2 = sptr(sAl + ((size_t)st*BM + wm + mi*16 + aRowF)*PK + kc + aColF);
          ldsm4(al[mi][0],al[mi][1],al[mi][2],al[mi][3], ad2);
        }
      }
#pragma unroll
      for (int np=0;np<2;np++){
        unsigned bd = sptr(sBh + ((size_t)st*BN + wn + np*16 + bRowF)*PK + kc + bColF);
        ldsm4(bh[2*np][0], bh[2*np][1], bh[2*np+1][0], bh[2*np+1][1], bd);
      }
#pragma unroll
      for (int mi=0;mi<MF;mi++)
#pragma unroll
        for (int ni=0;ni<NF;ni++) mma16(acc[mi][ni], ah[mi], bh[ni]);
      if constexpr (TERMS==2){
#pragma unroll
        for (int mi=0;mi<MF;mi++)
#pragma unroll
          for (int ni=0;ni<NF;ni++) mma16(acc[mi][ni], al[mi], bh[ni]);
      }
    }
  };

  issue(0); issue(1);
  for (int t=0;t<T;t++){
    CPWAIT(1);
    __syncthreads();
    if (t+2<T) issue(t+2); else CPCOMMIT();   // uniform commit accounting
    compute(t % STG);
  }

  if constexpr (EPI==0){
#pragma unroll
    for (int mi=0;mi<MF;mi++)
#pragma unroll
      for (int hf=0;hf<2;hf++){
        const int m = m0 + wm + mi*16 + g + hf*8;
        const int b = m >> 11, s = m & (SS-1);
#pragma unroll
        for (int ni=0;ni<NF;ni++){
          const int n = n0 + wn + ni*8 + tg*2;
          const int h = n >> 6, d = n & 63;
          float y0 = acc[mi][ni][hf*2+0] + bias[n];
          float y1 = acc[mi][ni][hf*2+1] + bias[n+1];
          if (z==0){
            const size_t o = (((size_t)b*NH + h)*SS + s)*DK + d;
            *(unsigned*)(oqh+o) = pack2h(hi_f16(y0), hi_f16(y1));
          } else if (z==1){
            const size_t o = (((size_t)b*NH + h)*SS + s)*DK + d;
            *(unsigned*)(okh+o) = pack2h(hi_f16(y0), hi_f16(y1));
          } else {
            const size_t o0 = (((size_t)b*NH + h)*DK + d)*SS + s;
            ovh[o0]      = hi_f16(y0);
            ovh[o0 + SS] = hi_f16(y1);
          }
        }
      }
  } else {
#pragma unroll
    for (int mi=0;mi<MF;mi++)
#pragma unroll
      for (int hf=0;hf<2;hf++){
        const int m = m0 + wm + mi*16 + g + hf*8;
#pragma unroll
        for (int ni=0;ni<NF;ni++){
          const int n = n0 + wn + ni*8 + tg*2;
          float2 y;
          y.x = acc[mi][ni][hf*2+0] + bias[n];
          y.y = acc[mi][ni][hf*2+1] + bias[n+1];
          *(float2*)(outf + (size_t)m*DM + n) = y;
        }
      }
  }
}

// ---------------------------------------------------------------------------
// Fused attention, fp16 1-term throughout. S = qh*kh in BOTH sweeps (numerator
// and normalizer perfectly consistent). PV = Ph*vh. K/V hi-only in smem,
// 4-stage pipeline, uniform commit.
// ---------------------------------------------------------------------------
__global__ void __launch_bounds__(256,2)
fused_attn(const fp16* __restrict__ qh_, const fp16* __restrict__ kh_,
           const fp16* __restrict__ vh_,
           float* __restrict__ attn_, fp16* __restrict__ ch)
{
  constexpr int PK=72, NBT=64, NB=SS/NBT, STG=4;
  extern __shared__ fp16 sm[];
  fp16* sKh = sm;                    // 4 * 64*72
  fp16* sVh = sKh + STG*64*PK;       // 4 * 64*72
  float* sInv = (float*)(sVh + STG*64*PK);

  const int tid=threadIdx.x, lane=tid&31;
  const int g=lane>>2, tg=lane&3;
  const int wm = (tid>>5)*16;
  const int m0 = blockIdx.x*128;
  const int bh = blockIdx.y;

  const int bRowF = (lane&7) + ((lane>>4)&1)*8;
  const int bColF = ((lane>>3)&1)*8;

  const fp16* qh = qh_ + (size_t)(bh*SS+m0)*DK;
  const fp16* kh = kh_ + (size_t)bh*SS*DK;
  const fp16* vh = vh_ + (size_t)bh*DK*SS;
  float* attn = attn_ + (size_t)bh*SS*SS;

  auto issueK = [&](int nb,int st){
    const int row=tid>>2, s=tid&3;
    const fp16* sh = kh + (size_t)(nb*NBT+row)*DK;
    unsigned dh = sptr(sKh + (st*64+row)*PK);
    CP16(dh+s*16, sh+s*8);  CP16(dh+(s+4)*16, sh+(s+4)*8);
  };
  auto issueKV = [&](int nb,int st){
    const int row=tid>>2, s=tid&3;
    const fp16* skh = kh + (size_t)(nb*NBT+row)*DK;
    unsigned dkh = sptr(sKh + (st*64+row)*PK);
    CP16(dkh+s*16, skh+s*8);  CP16(dkh+(s+4)*16, skh+(s+4)*8);
    const fp16* svh = vh + (size_t)row*SS + nb*NBT;
    unsigned dvh = sptr(sVh + (st*64+row)*PK);
    CP16(dvh+s*16, svh+s*8);  CP16(dvh+(s+4)*16, svh+(s+4)*8);
  };

  // Q fragments from gmem (ldmatrix-equivalent distribution), hi only
  unsigned qfh[4][4];
#pragma unroll
  for (int kk=0;kk<4;kk++){
    const int c = kk*16 + tg*2;
    qfh[kk][0] = *(const unsigned*)(qh + (size_t)(wm+g  )*DK + c);
    qfh[kk][1] = *(const unsigned*)(qh + (size_t)(wm+g+8)*DK + c);
    qfh[kk][2] = *(const unsigned*)(qh + (size_t)(wm+g  )*DK + c+8);
    qfh[kk][3] = *(const unsigned*)(qh + (size_t)(wm+g+8)*DK + c+8);
  }

  // 1-term S (used by both sweeps)
  auto computeS = [&](int st, float sacc[8][4]){
#pragma unroll
    for (int ni=0;ni<8;ni++)
#pragma unroll
      for (int q=0;q<4;q++) sacc[ni][q]=0.f;
#pragma unroll
    for (int kk=0;kk<4;kk++){
      unsigned bh2[8][2];
#pragma unroll
      for (int np=0;np<4;np++){
        unsigned bd = sptr(sKh + ((size_t)st*64 + np*16 + bRowF)*PK + kk*16 + bColF);
        ldsm4(bh2[2*np][0],bh2[2*np][1],bh2[2*np+1][0],bh2[2*np+1][1], bd);
      }
#pragma unroll
      for (int j=0;j<8;j++) mma16(sacc[j], qfh[kk], bh2[j]);
    }
  };

  // ================= Sweep 1: row sums =================
  issueK(0,0); CPCOMMIT();
  issueK(1,1); CPCOMMIT();
  issueK(2,2); CPCOMMIT();
  float rs0=0.f, rs1=0.f;
  for (int nb=0;nb<NB;nb++){
    CPWAIT(2);
    __syncthreads();
    if (nb+3 < NB){ issueK(nb+3,(nb+3)%STG); CPCOMMIT(); } else { CPCOMMIT(); }
    float sacc[8][4];
    computeS(nb%STG, sacc);
#pragma unroll
    for (int ni=0;ni<8;ni++){
      rs0 += __expf(sacc[ni][0]*0.125f) + __expf(sacc[ni][1]*0.125f);
      rs1 += __expf(sacc[ni][2]*0.125f) + __expf(sacc[ni][3]*0.125f);
    }
  }
  rs0 += __shfl_xor_sync(0xffffffffu, rs0, 1);
  rs0 += __shfl_xor_sync(0xffffffffu, rs0, 2);
  rs1 += __shfl_xor_sync(0xffffffffu, rs1, 1);
  rs1 += __shfl_xor_sync(0xffffffffu, rs1, 2);
  __syncthreads();                 // all sweep-1 smem reads done before restage
  if (tg==0){ sInv[wm+g] = 1.0f/rs0; sInv[wm+g+8] = 1.0f/rs1; }
  __syncthreads();
  const float inv0 = sInv[wm+g];
  const float inv1 = sInv[wm+g+8];

  // ================= Sweep 2: normalized attn + P@V =================
  float cacc[8][4];
#pragma unroll
  for (int ci=0;ci<8;ci++)
#pragma unroll
    for (int q=0;q<4;q++) cacc[ci][q]=0.f;

  issueKV(0,0); CPCOMMIT();
  issueKV(1,1); CPCOMMIT();
  issueKV(2,2); CPCOMMIT();
  for (int nb=0;nb<NB;nb++){
    CPWAIT(2);
    __syncthreads();
    if (nb+3 < NB){ issueKV(nb+3,(nb+3)%STG); CPCOMMIT(); } else { CPCOMMIT(); }
    const int st = nb%STG;
    float sacc[8][4];
    computeS(st, sacc);

    float* arow0 = attn + (size_t)(m0+wm+g)*SS + nb*NBT;
    float* arow1 = arow0 + 8*SS;
#pragma unroll
    for (int ni=0;ni<8;ni++){
      float e0 = __expf(sacc[ni][0]*0.125f)*inv0;
      float e1 = __expf(sacc[ni][1]*0.125f)*inv0;
      float e2 = __expf(sacc[ni][2]*0.125f)*inv1;
      float e3 = __expf(sacc[ni][3]*0.125f)*inv1;
      sacc[ni][0]=e0; sacc[ni][1]=e1; sacc[ni][2]=e2; sacc[ni][3]=e3;
      float2 lo2; lo2.x=e0; lo2.y=e1;
      float2 hi2; hi2.x=e2; hi2.y=e3;
      __stcs((float2*)(arow0 + ni*8 + tg*2), lo2);
      __stcs((float2*)(arow1 + ni*8 + tg*2), hi2);
    }

#pragma unroll
    for (int kk=0;kk<4;kk++){
      const int f0=2*kk, f1=2*kk+1;
      unsigned pah[4];
      pah[0]=pack2h(hi_f16(sacc[f0][0]), hi_f16(sacc[f0][1]));
      pah[1]=pack2h(hi_f16(sacc[f0][2]), hi_f16(sacc[f0][3]));
      pah[2]=pack2h(hi_f16(sacc[f1][0]), hi_f16(sacc[f1][1]));
      pah[3]=pack2h(hi_f16(sacc[f1][2]), hi_f16(sacc[f1][3]));
      unsigned vf[8][2];
#pragma unroll
      for (int cp=0;cp<4;cp++){
        unsigned vd = sptr(sVh + ((size_t)st*64 + cp*16 + bRowF)*PK + kk*16 + bColF);
        ldsm4(vf[2*cp][0],vf[2*cp][1],vf[2*cp+1][0],vf[2*cp+1][1], vd);
      }
#pragma unroll
      for (int j=0;j<8;j++) mma16(cacc[j], pah, vf[j]);
    }
  }

  const int b = bh>>4, h = bh&(NH-1);
#pragma unroll
  for (int ci=0;ci<8;ci++){
    const int d = h*DK + ci*8 + tg*2;
    const size_t o0 = ((size_t)(b*SS + m0+wm+g))*DM + d;
    const size_t o1 = o0 + (size_t)8*DM;
    *(unsigned*)(ch+o0) = pack2h(hi_f16(cacc[ci][0]), hi_f16(cacc[ci][1]));
    *(unsigned*)(ch+o1) = pack2h(hi_f16(cacc[ci][2]), hi_f16(cacc[ci][3]));
  }
}

extern "C" void kernel_launch(void* const* d_in, const int* in_sizes, int n_in,
                              void* d_out, int out_size){
  const float* Q   = (const float*)d_in[0];
  const float* K   = (const float*)d_in[1];
  const float* V   = (const float*)d_in[2];
  const float* Wq  = (const float*)d_in[3];
  const float* bq  = (const float*)d_in[4];
  const float* Wk  = (const float*)d_in[5];
  const float* bk  = (const float*)d_in[6];
  const float* Wv  = (const float*)d_in[7];
  const float* bv  = (const float*)d_in[8];
  const float* Wfc = (const float*)d_in[9];
  const float* bfc = (const float*)d_in[10];
  float* out_f = (float*)d_out;

  fp16 *Xh,*Xl,*Wth,*qh,*kh,*vh,*ch;
  float *bias3,*afb;
  cudaGetSymbolAddress((void**)&Xh, g_Xh);   cudaGetSymbolAddress((void**)&Xl, g_Xl);
  cudaGetSymbolAddress((void**)&Wth, g_Wth);
  cudaGetSymbolAddress((void**)&qh, g_qh);
  cudaGetSymbolAddress((void**)&kh, g_kh);   cudaGetSymbolAddress((void**)&vh, g_vh);
  cudaGetSymbolAddress((void**)&ch, g_ch);
  cudaGetSymbolAddress((void**)&bias3, g_bias3);
  cudaGetSymbolAddress((void**)&afb,  g_attn_fb);

  const size_t ATTN = (size_t)HEADS*SS*SS;
  float* attn = ((size_t)out_size >= ATTN) ? (out_f + ((size_t)out_size - ATTN)) : afb;

  const int SM_PROJ  = 3*3*128*40*2;                 // 92160 (3 stages x {Ah,Al,Bh})
  const int SM_OUTP  = 3*2*128*40*2;                 // 61440 (3 stages x {Ah,Bh})
  const int SM_FUSED = 2*4*64*72*2 + 512;            // 74240

  cudaFuncSetAttribute(gemmW<0,2>, cudaFuncAttributeMaxDynamicSharedMemorySize, SM_PROJ);
  cudaFuncSetAttribute(gemmW<3,1>, cudaFuncAttributeMaxDynamicSharedMemorySize, SM_OUTP);
  cudaFuncSetAttribute(fused_attn, cudaFuncAttributeMaxDynamicSharedMemorySize, SM_FUSED);

  dim3 blk(256);

  cudaMemcpyAsync(bias3,        bq, DM*sizeof(float), cudaMemcpyDeviceToDevice);
  cudaMemcpyAsync(bias3 + DM,   bk, DM*sizeof(float), cudaMemcpyDeviceToDevice);
  cudaMemcpyAsync(bias3 + 2*DM, bv, DM*sizeof(float), cudaMemcpyDeviceToDevice);

  cvtX<<<dim3(NXE/4/256,1,3), blk>>>(Q,K,V, Xh,Xl);
  cvtWt<<<dim3(32,32,4), dim3(32,8)>>>(Wq,Wk,Wv,Wfc, Wth);

  // Q/K/V projections, 2-term A (z: 0=q hi, 1=k hi, 2=v hi transposed)
  gemmW<0,2><<<dim3(8,32,3), blk, SM_PROJ>>>(
      Xh, Xl, Wth, bias3, nullptr, qh, kh, vh);

  fused_attn<<<dim3(SS/128, HEADS), blk, SM_FUSED>>>(
      qh, kh, vh, attn, ch);

  // output projection: ctx(hi) @ Wfc(hi), 1-term
  gemmW<3,1><<<dim3(8,32), blk, SM_OUTP>>>(
      ch, nullptr, Wth + 3*(size_t)NWE, bfc, out_f, nullptr, nullptr, nullptr);
}

// round 15
// speedup vs baseline: 5.8655x; 1.1958x over previous
#include <cuda_runtime.h>
#include <cuda_fp16.h>
#include <cstdint>

using fp16 = __half;

#define BB 2
#define SS 2048
#define DM 1024
#define NH 16
#define DK 64
#define MROWS (BB*SS)       // 4096
#define HEADS (BB*NH)       // 32
#define NXE (MROWS*DM)      // 4194304
#define NWE (DM*DM)         // 1048576
#define QKVE (HEADS*SS*DK)  // 4194304

// ---------------- scratch ----------------
__device__ fp16 g_Xh[3*NXE];                  // converted Q,K,V inputs (hi only)
__device__ fp16 g_Wth[4*NWE];                 // transposed weights [N][K], hi only
__device__ fp16 g_qh[QKVE];                   // q head-split
__device__ fp16 g_kh[QKVE];                   // k head-split
__device__ fp16 g_vh[QKVE];                   // v transposed [bh][dk][seq]
__device__ fp16 g_ch[MROWS*DM];               // ctx merged heads
__device__ float g_bias3[3*DM];
__device__ float g_attn_fb[(size_t)HEADS*SS*SS];

// ---------------- helpers ----------------
__device__ __forceinline__ unsigned sptr(const void* p){
  return (unsigned)__cvta_generic_to_shared(p);
}
#define CP16(d,s) asm volatile("cp.async.cg.shared.global [%0], [%1], 16;\n" :: "r"(d), "l"(s))
#define CPCOMMIT() asm volatile("cp.async.commit_group;\n")
#define CPWAIT(N)  asm volatile("cp.async.wait_group %0;\n" :: "n"(N))

__device__ __forceinline__ void ldsm4(unsigned& r0, unsigned& r1, unsigned& r2, unsigned& r3,
                                      unsigned saddr){
  asm volatile("ldmatrix.sync.aligned.m8n8.x4.shared.b16 {%0,%1,%2,%3}, [%4];"
    : "=r"(r0), "=r"(r1), "=r"(r2), "=r"(r3) : "r"(saddr));
}

__device__ __forceinline__ unsigned pack2h(fp16 x, fp16 y){
  __half2 t = __halves2half2(x, y);
  return *reinterpret_cast<unsigned*>(&t);
}
__device__ __forceinline__ fp16 hi_f16(float v){ return __float2half_rn(v); }
__device__ __forceinline__ void mma16(float c[4], const unsigned a[4], const unsigned b[2]){
  asm volatile(
    "mma.sync.aligned.m16n8k16.row.col.f32.f16.f16.f32 "
    "{%0,%1,%2,%3},{%4,%5,%6,%7},{%8,%9},{%0,%1,%2,%3};\n"
    : "+f"(c[0]), "+f"(c[1]), "+f"(c[2]), "+f"(c[3])
    : "r"(a[0]), "r"(a[1]), "r"(a[2]), "r"(a[3]), "r"(b[0]), "r"(b[1]));
}

// fp32 -> fp16 (hi) for the 3 input tensors (z selects)
__global__ void cvtX(const float* p0, const float* p1, const float* p2,
                     fp16* __restrict__ Xh){
  const int z = blockIdx.z;
  const float* in = (z==0)?p0:(z==1)?p1:p2;
  fp16* hi = Xh + (size_t)z*NXE;
  const int i = blockIdx.x*blockDim.x + threadIdx.x;
  float4 v = ((const float4*)in)[i];
  uint2 uh;
  uh.x = pack2h(hi_f16(v.x), hi_f16(v.y));
  uh.y = pack2h(hi_f16(v.z), hi_f16(v.w));
  ((uint2*)hi)[i] = uh;
}

// fp32 W[K][N] -> transposed fp16 Wt[N][K]
__global__ void cvtWt(const float* p0, const float* p1, const float* p2, const float* p3,
                      fp16* __restrict__ Wth){
  __shared__ float t[32][33];
  const int z = blockIdx.z;
  const float* in = (z==0)?p0:(z==1)?p1:(z==2)?p2:p3;
  fp16* hi = Wth + (size_t)z*NWE;
  const int tx = threadIdx.x, ty = threadIdx.y;
  const int n0 = blockIdx.x*32, k0 = blockIdx.y*32;
#pragma unroll
  for (int i=0;i<4;i++){
    const int k = ty + 8*i;
    t[k][tx] = in[(size_t)(k0+k)*DM + n0 + tx];
  }
  __syncthreads();
#pragma unroll
  for (int i=0;i<4;i++){
    const int n = ty + 8*i;
    hi[(size_t)(n0+n)*DM + k0 + tx] = hi_f16(t[tx][n]);
  }
}

// ---------------------------------------------------------------------------
// fp16 1-term GEMM: C = Ah @ Wth^T. 3-stage single-sync ring, 2 CTAs/SM.
// EPI 0: proj (z: 0=q head-split, 1=k head-split, 2=v transposed)
// EPI 3: out-proj (bias, fp32 out)
// ---------------------------------------------------------------------------
template<int EPI>
__global__ void __launch_bounds__(256,2)
gemmW(const fp16* __restrict__ Ahp, const fp16* __restrict__ Bhp,
      const float* __restrict__ biasp, float* __restrict__ outf,
      fp16* __restrict__ oqh, fp16* __restrict__ okh, fp16* __restrict__ ovh)
{
  constexpr int BM=128, BN=128, BK=32, STG=3, PK=40;
  constexpr int WM=64, WN=32, MF=4, NF=4;

  extern __shared__ fp16 smx[];
  fp16* sAh = smx;
  fp16* sBh = sAh + STG*BM*PK;

  const int tid=threadIdx.x, lane=tid&31, wid=tid>>5;
  const int g=lane>>2, tg=lane&3;
  const int warp_m=wid>>2, warp_n=wid&3;
  const int wm=warp_m*WM, wn=warp_n*WN;
  const int m0=blockIdx.y*BM, n0=blockIdx.x*BN, z=blockIdx.z;

  const int aRowF = (lane&7) + ((lane>>3)&1)*8;
  const int aColF = ((lane>>4)&1)*8;
  const int bRowF = (lane&7) + ((lane>>4)&1)*8;
  const int bColF = ((lane>>3)&1)*8;

  const fp16 *Ah=Ahp, *Bh=Bhp;
  const float* bias = biasp;
  if constexpr (EPI==0){
    Ah += (size_t)z*NXE;
    Bh += (size_t)z*NWE;
    bias += z*DM;
  }

  const int ar=tid>>1, ac=(tid&1)*16;

  float acc[MF][NF][4];
#pragma unroll
  for (int mi=0;mi<MF;mi++)
#pragma unroll
    for (int ni=0;ni<NF;ni++)
#pragma unroll
      for (int q=0;q<4;q++) acc[mi][ni][q]=0.f;

  const int T = DM/BK;   // 32

  auto issue = [&](int t){
    const int st = t % STG;
    const int k0 = t*BK;
    const fp16* s = Ah + (size_t)(m0+ar)*DM + k0 + ac;
    unsigned d = sptr(sAh + ((size_t)st*BM+ar)*PK + ac);
    CP16(d, s); CP16(d+16, s+8);
    const fp16* s3 = Bh + (size_t)(n0+ar)*DM + k0 + ac;
    unsigned d3 = sptr(sBh + ((size_t)st*BN+ar)*PK + ac);
    CP16(d3, s3); CP16(d3+16, s3+8);
    CPCOMMIT();
  };

  auto compute = [&](int st){
#pragma unroll
    for (int s16=0; s16<2; s16++){
      const int kc = s16*16;
      unsigned ah[MF][4], bh[NF][2];
#pragma unroll
      for (int mi=0;mi<MF;mi++){
        unsigned ad = sptr(sAh + ((size_t)st*BM + wm + mi*16 + aRowF)*PK + kc + aColF);
        ldsm4(ah[mi][0],ah[mi][1],ah[mi][2],ah[mi][3], ad);
      }
#pragma unroll
      for (int np=0;np<2;np++){
        unsigned bd = sptr(sBh + ((size_t)st*BN + wn + np*16 + bRowF)*PK + kc + bColF);
        ldsm4(bh[2*np][0], bh[2*np][1], bh[2*np+1][0], bh[2*np+1][1], bd);
      }
#pragma unroll
      for (int mi=0;mi<MF;mi++)
#pragma unroll
        for (int ni=0;ni<NF;ni++) mma16(acc[mi][ni], ah[mi], bh[ni]);
    }
  };

  issue(0); issue(1);
  for (int t=0;t<T;t++){
    CPWAIT(1);
    __syncthreads();
    if (t+2<T) issue(t+2); else CPCOMMIT();   // uniform commit accounting
    compute(t % STG);
  }

  if constexpr (EPI==0){
#pragma unroll
    for (int mi=0;mi<MF;mi++)
#pragma unroll
      for (int hf=0;hf<2;hf++){
        const int m = m0 + wm + mi*16 + g + hf*8;
        const int b = m >> 11, s = m & (SS-1);
#pragma unroll
        for (int ni=0;ni<NF;ni++){
          const int n = n0 + wn + ni*8 + tg*2;
          const int h = n >> 6, d = n & 63;
          float y0 = acc[mi][ni][hf*2+0] + bias[n];
          float y1 = acc[mi][ni][hf*2+1] + bias[n+1];
          if (z==0){
            const size_t o = (((size_t)b*NH + h)*SS + s)*DK + d;
            *(unsigned*)(oqh+o) = pack2h(hi_f16(y0), hi_f16(y1));
          } else if (z==1){
            const size_t o = (((size_t)b*NH + h)*SS + s)*DK + d;
            *(unsigned*)(okh+o) = pack2h(hi_f16(y0), hi_f16(y1));
          } else {
            const size_t o0 = (((size_t)b*NH + h)*DK + d)*SS + s;
            ovh[o0]      = hi_f16(y0);
            ovh[o0 + SS] = hi_f16(y1);
          }
        }
      }
  } else {
#pragma unroll
    for (int mi=0;mi<MF;mi++)
#pragma unroll
      for (int hf=0;hf<2;hf++){
        const int m = m0 + wm + mi*16 + g + hf*8;
#pragma unroll
        for (int ni=0;ni<NF;ni++){
          const int n = n0 + wn + ni*8 + tg*2;
          float2 y;
          y.x = acc[mi][ni][hf*2+0] + bias[n];
          y.y = acc[mi][ni][hf*2+1] + bias[n+1];
          *(float2*)(outf + (size_t)m*DM + n) = y;
        }
      }
  }
}

// ---------------------------------------------------------------------------
// Fused attention, fp16 1-term throughout. S = qh*kh in BOTH sweeps (numerator
// and normalizer perfectly consistent). PV = Ph*vh. K/V hi-only in smem,
// 4-stage pipeline, uniform commit.
// ---------------------------------------------------------------------------
__global__ void __launch_bounds__(256,2)
fused_attn(const fp16* __restrict__ qh_, const fp16* __restrict__ kh_,
           const fp16* __restrict__ vh_,
           float* __restrict__ attn_, fp16* __restrict__ ch)
{
  constexpr int PK=72, NBT=64, NB=SS/NBT, STG=4;
  extern __shared__ fp16 sm[];
  fp16* sKh = sm;                    // 4 * 64*72
  fp16* sVh = sKh + STG*64*PK;       // 4 * 64*72
  float* sInv = (float*)(sVh + STG*64*PK);

  const int tid=threadIdx.x, lane=tid&31;
  const int g=lane>>2, tg=lane&3;
  const int wm = (tid>>5)*16;
  const int m0 = blockIdx.x*128;
  const int bh = blockIdx.y;

  const int bRowF = (lane&7) + ((lane>>4)&1)*8;
  const int bColF = ((lane>>3)&1)*8;

  const fp16* qh = qh_ + (size_t)(bh*SS+m0)*DK;
  const fp16* kh = kh_ + (size_t)bh*SS*DK;
  const fp16* vh = vh_ + (size_t)bh*DK*SS;
  float* attn = attn_ + (size_t)bh*SS*SS;

  auto issueK = [&](int nb,int st){
    const int row=tid>>2, s=tid&3;
    const fp16* sh = kh + (size_t)(nb*NBT+row)*DK;
    unsigned dh = sptr(sKh + (st*64+row)*PK);
    CP16(dh+s*16, sh+s*8);  CP16(dh+(s+4)*16, sh+(s+4)*8);
  };
  auto issueKV = [&](int nb,int st){
    const int row=tid>>2, s=tid&3;
    const fp16* skh = kh + (size_t)(nb*NBT+row)*DK;
    unsigned dkh = sptr(sKh + (st*64+row)*PK);
    CP16(dkh+s*16, skh+s*8);  CP16(dkh+(s+4)*16, skh+(s+4)*8);
    const fp16* svh = vh + (size_t)row*SS + nb*NBT;
    unsigned dvh = sptr(sVh + (st*64+row)*PK);
    CP16(dvh+s*16, svh+s*8);  CP16(dvh+(s+4)*16, svh+(s+4)*8);
  };

  // Q fragments from gmem (ldmatrix-equivalent distribution)
  unsigned qfh[4][4];
#pragma unroll
  for (int kk=0;kk<4;kk++){
    const int c = kk*16 + tg*2;
    qfh[kk][0] = *(const unsigned*)(qh + (size_t)(wm+g  )*DK + c);
    qfh[kk][1] = *(const unsigned*)(qh + (size_t)(wm+g+8)*DK + c);
    qfh[kk][2] = *(const unsigned*)(qh + (size_t)(wm+g  )*DK + c+8);
    qfh[kk][3] = *(const unsigned*)(qh + (size_t)(wm+g+8)*DK + c+8);
  }

  // 1-term S (used by both sweeps)
  auto computeS = [&](int st, float sacc[8][4]){
#pragma unroll
    for (int ni=0;ni<8;ni++)
#pragma unroll
      for (int q=0;q<4;q++) sacc[ni][q]=0.f;
#pragma unroll
    for (int kk=0;kk<4;kk++){
      unsigned bh2[8][2];
#pragma unroll
      for (int np=0;np<4;np++){
        unsigned bd = sptr(sKh + ((size_t)st*64 + np*16 + bRowF)*PK + kk*16 + bColF);
        ldsm4(bh2[2*np][0],bh2[2*np][1],bh2[2*np+1][0],bh2[2*np+1][1], bd);
      }
#pragma unroll
      for (int j=0;j<8;j++) mma16(sacc[j], qfh[kk], bh2[j]);
    }
  };

  // ================= Sweep 1: row sums =================
  issueK(0,0); CPCOMMIT();
  issueK(1,1); CPCOMMIT();
  issueK(2,2); CPCOMMIT();
  float rs0=0.f, rs1=0.f;
  for (int nb=0;nb<NB;nb++){
    CPWAIT(2);
    __syncthreads();
    if (nb+3 < NB){ issueK(nb+3,(nb+3)%STG); CPCOMMIT(); } else { CPCOMMIT(); }
    float sacc[8][4];
    computeS(nb%STG, sacc);
#pragma unroll
    for (int ni=0;ni<8;ni++){
      rs0 += __expf(sacc[ni][0]*0.125f) + __expf(sacc[ni][1]*0.125f);
      rs1 += __expf(sacc[ni][2]*0.125f) + __expf(sacc[ni][3]*0.125f);
    }
  }
  rs0 += __shfl_xor_sync(0xffffffffu, rs0, 1);
  rs0 += __shfl_xor_sync(0xffffffffu, rs0, 2);
  rs1 += __shfl_xor_sync(0xffffffffu, rs1, 1);
  rs1 += __shfl_xor_sync(0xffffffffu, rs1, 2);
  __syncthreads();                 // all sweep-1 smem reads done before restage
  if (tg==0){ sInv[wm+g] = 1.0f/rs0; sInv[wm+g+8] = 1.0f/rs1; }
  __syncthreads();
  const float inv0 = sInv[wm+g];
  const float inv1 = sInv[wm+g+8];

  // ================= Sweep 2: normalized attn + P@V =================
  float cacc[8][4];
#pragma unroll
  for (int ci=0;ci<8;ci++)
#pragma unroll
    for (int q=0;q<4;q++) cacc[ci][q]=0.f;

  issueKV(0,0); CPCOMMIT();
  issueKV(1,1); CPCOMMIT();
  issueKV(2,2); CPCOMMIT();
  for (int nb=0;nb<NB;nb++){
    CPWAIT(2);
    __syncthreads();
    if (nb+3 < NB){ issueKV(nb+3,(nb+3)%STG); CPCOMMIT(); } else { CPCOMMIT(); }
    const int st = nb%STG;
    float sacc[8][4];
    computeS(st, sacc);

    float* arow0 = attn + (size_t)(m0+wm+g)*SS + nb*NBT;
    float* arow1 = arow0 + 8*SS;
#pragma unroll
    for (int ni=0;ni<8;ni++){
      float e0 = __expf(sacc[ni][0]*0.125f)*inv0;
      float e1 = __expf(sacc[ni][1]*0.125f)*inv0;
      float e2 = __expf(sacc[ni][2]*0.125f)*inv1;
      float e3 = __expf(sacc[ni][3]*0.125f)*inv1;
      sacc[ni][0]=e0; sacc[ni][1]=e1; sacc[ni][2]=e2; sacc[ni][3]=e3;
      float2 lo2; lo2.x=e0; lo2.y=e1;
      float2 hi2; hi2.x=e2; hi2.y=e3;
      __stcs((float2*)(arow0 + ni*8 + tg*2), lo2);
      __stcs((float2*)(arow1 + ni*8 + tg*2), hi2);
    }

#pragma unroll
    for (int kk=0;kk<4;kk++){
      const int f0=2*kk, f1=2*kk+1;
      unsigned pah[4];
      pah[0]=pack2h(hi_f16(sacc[f0][0]), hi_f16(sacc[f0][1]));
      pah[1]=pack2h(hi_f16(sacc[f0][2]), hi_f16(sacc[f0][3]));
      pah[2]=pack2h(hi_f16(sacc[f1][0]), hi_f16(sacc[f1][1]));
      pah[3]=pack2h(hi_f16(sacc[f1][2]), hi_f16(sacc[f1][3]));
      unsigned vf[8][2];
#pragma unroll
      for (int cp=0;cp<4;cp++){
        unsigned vd = sptr(sVh + ((size_t)st*64 + cp*16 + bRowF)*PK + kk*16 + bColF);
        ldsm4(vf[2*cp][0],vf[2*cp][1],vf[2*cp+1][0],vf[2*cp+1][1], vd);
      }
#pragma unroll
      for (int j=0;j<8;j++) mma16(cacc[j], pah, vf[j]);
    }
  }

  const int b = bh>>4, h = bh&(NH-1);
#pragma unroll
  for (int ci=0;ci<8;ci++){
    const int d = h*DK + ci*8 + tg*2;
    const size_t o0 = ((size_t)(b*SS + m0+wm+g))*DM + d;
    const size_t o1 = o0 + (size_t)8*DM;
    *(unsigned*)(ch+o0) = pack2h(hi_f16(cacc[ci][0]), hi_f16(cacc[ci][1]));
    *(unsigned*)(ch+o1) = pack2h(hi_f16(cacc[ci][2]), hi_f16(cacc[ci][3]));
  }
}

extern "C" void kernel_launch(void* const* d_in, const int* in_sizes, int n_in,
                              void* d_out, int out_size){
  const float* Q   = (const float*)d_in[0];
  const float* K   = (const float*)d_in[1];
  const float* V   = (const float*)d_in[2];
  const float* Wq  = (const float*)d_in[3];
  const float* bq  = (const float*)d_in[4];
  const float* Wk  = (const float*)d_in[5];
  const float* bk  = (const float*)d_in[6];
  const float* Wv  = (const float*)d_in[7];
  const float* bv  = (const float*)d_in[8];
  const float* Wfc = (const float*)d_in[9];
  const float* bfc = (const float*)d_in[10];
  float* out_f = (float*)d_out;

  fp16 *Xh,*Wth,*qh,*kh,*vh,*ch;
  float *bias3,*afb;
  cudaGetSymbolAddress((void**)&Xh, g_Xh);
  cudaGetSymbolAddress((void**)&Wth, g_Wth);
  cudaGetSymbolAddress((void**)&qh, g_qh);
  cudaGetSymbolAddress((void**)&kh, g_kh);   cudaGetSymbolAddress((void**)&vh, g_vh);
  cudaGetSymbolAddress((void**)&ch, g_ch);
  cudaGetSymbolAddress((void**)&bias3, g_bias3);
  cudaGetSymbolAddress((void**)&afb,  g_attn_fb);

  const size_t ATTN = (size_t)HEADS*SS*SS;
  float* attn = ((size_t)out_size >= ATTN) ? (out_f + ((size_t)out_size - ATTN)) : afb;

  const int SM_GEMMW = 3*2*128*40*2;                 // 61440 (3 stages x {Ah,Bh})
  const int SM_FUSED = 2*4*64*72*2 + 512;            // 74240

  cudaFuncSetAttribute(gemmW<0>, cudaFuncAttributeMaxDynamicSharedMemorySize, SM_GEMMW);
  cudaFuncSetAttribute(gemmW<3>, cudaFuncAttributeMaxDynamicSharedMemorySize, SM_GEMMW);
  cudaFuncSetAttribute(fused_attn, cudaFuncAttributeMaxDynamicSharedMemorySize, SM_FUSED);

  dim3 blk(256);

  cudaMemcpyAsync(bias3,        bq, DM*sizeof(float), cudaMemcpyDeviceToDevice);
  cudaMemcpyAsync(bias3 + DM,   bk, DM*sizeof(float), cudaMemcpyDeviceToDevice);
  cudaMemcpyAsync(bias3 + 2*DM, bv, DM*sizeof(float), cudaMemcpyDeviceToDevice);

  cvtX<<<dim3(NXE/4/256,1,3), blk>>>(Q,K,V, Xh);
  cvtWt<<<dim3(32,32,4), dim3(32,8)>>>(Wq,Wk,Wv,Wfc, Wth);

  // Q/K/V projections, 1-term (z: 0=q, 1=k head-split, 2=v transposed)
  gemmW<0><<<dim3(8,32,3), blk, SM_GEMMW>>>(
      Xh, Wth, bias3, nullptr, qh, kh, vh);

  fused_attn<<<dim3(SS/128, HEADS), blk, SM_FUSED>>>(
      qh, kh, vh, attn, ch);

  // output projection: ctx @ Wfc, 1-term
  gemmW<3><<<dim3(8,32), blk, SM_GEMMW>>>(
      ch, Wth + 3*(size_t)NWE, bfc, out_f, nullptr, nullptr, nullptr);
}

// round 16
// speedup vs baseline: 6.0139x; 1.0253x over previous
#include <cuda_runtime.h>
#include <cuda_fp16.h>
#include <cstdint>

using fp16 = __half;

#define BB 2
#define SS 2048
#define DM 1024
#define NH 16
#define DK 64
#define MROWS (BB*SS)       // 4096
#define HEADS (BB*NH)       // 32
#define NXE (MROWS*DM)      // 4194304
#define NWE (DM*DM)         // 1048576
#define QKVE (HEADS*SS*DK)  // 4194304

// ---------------- scratch ----------------
__device__ fp16 g_Xh[3*NXE];                  // converted Q,K,V inputs
__device__ fp16 g_Wth[4*NWE];                 // transposed weights [N][K]
__device__ fp16 g_qh[QKVE];                   // q head-split, pre-scaled by 0.125*log2(e)
__device__ fp16 g_kh[QKVE];                   // k head-split
__device__ fp16 g_vh[QKVE];                   // v transposed [bh][dk][seq]
__device__ fp16 g_ch[MROWS*DM];               // ctx merged heads
__device__ float g_bias3[3*DM];
__device__ float g_attn_fb[(size_t)HEADS*SS*SS];

// ---------------- helpers ----------------
__device__ __forceinline__ unsigned sptr(const void* p){
  return (unsigned)__cvta_generic_to_shared(p);
}
#define CP16(d,s) asm volatile("cp.async.cg.shared.global [%0], [%1], 16;\n" :: "r"(d), "l"(s))
#define CPCOMMIT() asm volatile("cp.async.commit_group;\n")
#define CPWAIT(N)  asm volatile("cp.async.wait_group %0;\n" :: "n"(N))

__device__ __forceinline__ void ldsm4(unsigned& r0, unsigned& r1, unsigned& r2, unsigned& r3,
                                      unsigned saddr){
  asm volatile("ldmatrix.sync.aligned.m8n8.x4.shared.b16 {%0,%1,%2,%3}, [%4];"
    : "=r"(r0), "=r"(r1), "=r"(r2), "=r"(r3) : "r"(saddr));
}

__device__ __forceinline__ unsigned pack2h(fp16 x, fp16 y){
  __half2 t = __halves2half2(x, y);
  return *reinterpret_cast<unsigned*>(&t);
}
// one-instruction f32x2 -> packed f16x2 (first src -> HIGH half)
__device__ __forceinline__ unsigned pack2f(float lo, float hi){
  unsigned r;
  asm("cvt.rn.f16x2.f32 %0, %1, %2;" : "=r"(r) : "f"(hi), "f"(lo));
  return r;
}
__device__ __forceinline__ float ex2f(float x){
  float y; asm("ex2.approx.f32 %0, %1;" : "=f"(y) : "f"(x)); return y;
}
__device__ __forceinline__ fp16 hi_f16(float v){ return __float2half_rn(v); }
__device__ __forceinline__ void mma16(float c[4], const unsigned a[4], const unsigned b[2]){
  asm volatile(
    "mma.sync.aligned.m16n8k16.row.col.f32.f16.f16.f32 "
    "{%0,%1,%2,%3},{%4,%5,%6,%7},{%8,%9},{%0,%1,%2,%3};\n"
    : "+f"(c[0]), "+f"(c[1]), "+f"(c[2]), "+f"(c[3])
    : "r"(a[0]), "r"(a[1]), "r"(a[2]), "r"(a[3]), "r"(b[0]), "r"(b[1]));
}

#define QSCL 0.1803368801111244f   // 0.125 * log2(e)

// fp32 -> fp16 for the 3 input tensors (z selects)
__global__ void cvtX(const float* p0, const float* p1, const float* p2,
                     fp16* __restrict__ Xh){
  const int z = blockIdx.z;
  const float* in = (z==0)?p0:(z==1)?p1:p2;
  fp16* hi = Xh + (size_t)z*NXE;
  const int i = blockIdx.x*blockDim.x + threadIdx.x;
  float4 v = ((const float4*)in)[i];
  uint2 uh;
  uh.x = pack2f(v.x, v.y);
  uh.y = pack2f(v.z, v.w);
  ((uint2*)hi)[i] = uh;
}

// fp32 W[K][N] -> transposed fp16 Wt[N][K]
__global__ void cvtWt(const float* p0, const float* p1, const float* p2, const float* p3,
                      fp16* __restrict__ Wth){
  __shared__ float t[32][33];
  const int z = blockIdx.z;
  const float* in = (z==0)?p0:(z==1)?p1:(z==2)?p2:p3;
  fp16* hi = Wth + (size_t)z*NWE;
  const int tx = threadIdx.x, ty = threadIdx.y;
  const int n0 = blockIdx.x*32, k0 = blockIdx.y*32;
#pragma unroll
  for (int i=0;i<4;i++){
    const int k = ty + 8*i;
    t[k][tx] = in[(size_t)(k0+k)*DM + n0 + tx];
  }
  __syncthreads();
#pragma unroll
  for (int i=0;i<4;i++){
    const int n = ty + 8*i;
    hi[(size_t)(n0+n)*DM + k0 + tx] = hi_f16(t[tx][n]);
  }
}

// ---------------------------------------------------------------------------
// fp16 1-term GEMM: C = Ah @ Wth^T. 3-stage single-sync ring, 2 CTAs/SM.
// EPI 0: proj (z: 0=q*QSCL head-split, 1=k head-split, 2=v transposed)
// EPI 3: out-proj (bias, fp32 out)
// ---------------------------------------------------------------------------
template<int EPI>
__global__ void __launch_bounds__(256,2)
gemmW(const fp16* __restrict__ Ahp, const fp16* __restrict__ Bhp,
      const float* __restrict__ biasp, float* __restrict__ outf,
      fp16* __restrict__ oqh, fp16* __restrict__ okh, fp16* __restrict__ ovh)
{
  constexpr int BM=128, BN=128, BK=32, STG=3, PK=40;
  constexpr int WM=64, WN=32, MF=4, NF=4;

  extern __shared__ fp16 smx[];
  fp16* sAh = smx;
  fp16* sBh = sAh + STG*BM*PK;

  const int tid=threadIdx.x, lane=tid&31, wid=tid>>5;
  const int g=lane>>2, tg=lane&3;
  const int warp_m=wid>>2, warp_n=wid&3;
  const int wm=warp_m*WM, wn=warp_n*WN;
  const int m0=blockIdx.y*BM, n0=blockIdx.x*BN, z=blockIdx.z;

  const int aRowF = (lane&7) + ((lane>>3)&1)*8;
  const int aColF = ((lane>>4)&1)*8;
  const int bRowF = (lane&7) + ((lane>>4)&1)*8;
  const int bColF = ((lane>>3)&1)*8;

  const fp16 *Ah=Ahp, *Bh=Bhp;
  const float* bias = biasp;
  if constexpr (EPI==0){
    Ah += (size_t)z*NXE;
    Bh += (size_t)z*NWE;
    bias += z*DM;
  }

  const int ar=tid>>1, ac=(tid&1)*16;

  float acc[MF][NF][4];
#pragma unroll
  for (int mi=0;mi<MF;mi++)
#pragma unroll
    for (int ni=0;ni<NF;ni++)
#pragma unroll
      for (int q=0;q<4;q++) acc[mi][ni][q]=0.f;

  const int T = DM/BK;   // 32

  auto issue = [&](int t){
    const int st = t % STG;
    const int k0 = t*BK;
    const fp16* s = Ah + (size_t)(m0+ar)*DM + k0 + ac;
    unsigned d = sptr(sAh + ((size_t)st*BM+ar)*PK + ac);
    CP16(d, s); CP16(d+16, s+8);
    const fp16* s3 = Bh + (size_t)(n0+ar)*DM + k0 + ac;
    unsigned d3 = sptr(sBh + ((size_t)st*BN+ar)*PK + ac);
    CP16(d3, s3); CP16(d3+16, s3+8);
    CPCOMMIT();
  };

  auto compute = [&](int st){
#pragma unroll
    for (int s16=0; s16<2; s16++){
      const int kc = s16*16;
      unsigned ah[MF][4], bh[NF][2];
#pragma unroll
      for (int mi=0;mi<MF;mi++){
        unsigned ad = sptr(sAh + ((size_t)st*BM + wm + mi*16 + aRowF)*PK + kc + aColF);
        ldsm4(ah[mi][0],ah[mi][1],ah[mi][2],ah[mi][3], ad);
      }
#pragma unroll
      for (int np=0;np<2;np++){
        unsigned bd = sptr(sBh + ((size_t)st*BN + wn + np*16 + bRowF)*PK + kc + bColF);
        ldsm4(bh[2*np][0], bh[2*np][1], bh[2*np+1][0], bh[2*np+1][1], bd);
      }
#pragma unroll
      for (int mi=0;mi<MF;mi++)
#pragma unroll
        for (int ni=0;ni<NF;ni++) mma16(acc[mi][ni], ah[mi], bh[ni]);
    }
  };

  issue(0); issue(1);
  for (int t=0;t<T;t++){
    CPWAIT(1);
    __syncthreads();
    if (t+2<T) issue(t+2); else CPCOMMIT();   // uniform commit accounting
    compute(t % STG);
  }

  if constexpr (EPI==0){
#pragma unroll
    for (int mi=0;mi<MF;mi++)
#pragma unroll
      for (int hf=0;hf<2;hf++){
        const int m = m0 + wm + mi*16 + g + hf*8;
        const int b = m >> 11, s = m & (SS-1);
#pragma unroll
        for (int ni=0;ni<NF;ni++){
          const int n = n0 + wn + ni*8 + tg*2;
          const int h = n >> 6, d = n & 63;
          float y0 = acc[mi][ni][hf*2+0] + bias[n];
          float y1 = acc[mi][ni][hf*2+1] + bias[n+1];
          if (z==0){
            // fold softmax scale * log2(e) into q
            y0 *= QSCL; y1 *= QSCL;
            const size_t o = (((size_t)b*NH + h)*SS + s)*DK + d;
            *(unsigned*)(oqh+o) = pack2f(y0, y1);
          } else if (z==1){
            const size_t o = (((size_t)b*NH + h)*SS + s)*DK + d;
            *(unsigned*)(okh+o) = pack2f(y0, y1);
          } else {
            const size_t o0 = (((size_t)b*NH + h)*DK + d)*SS + s;
            ovh[o0]      = hi_f16(y0);
            ovh[o0 + SS] = hi_f16(y1);
          }
        }
      }
  } else {
#pragma unroll
    for (int mi=0;mi<MF;mi++)
#pragma unroll
      for (int hf=0;hf<2;hf++){
        const int m = m0 + wm + mi*16 + g + hf*8;
#pragma unroll
        for (int ni=0;ni<NF;ni++){
          const int n = n0 + wn + ni*8 + tg*2;
          float2 y;
          y.x = acc[mi][ni][hf*2+0] + bias[n];
          y.y = acc[mi][ni][hf*2+1] + bias[n+1];
          *(float2*)(outf + (size_t)m*DM + n) = y;
        }
      }
  }
}

// ---------------------------------------------------------------------------
// Fused attention, fp16. q pre-scaled so exp(S/8) = ex2(S'). 5-stage K/V
// pipeline, uniform commit, 1 sync per kv-block.
// ---------------------------------------------------------------------------
__global__ void __launch_bounds__(256,2)
fused_attn(const fp16* __restrict__ qh_, const fp16* __restrict__ kh_,
           const fp16* __restrict__ vh_,
           float* __restrict__ attn_, fp16* __restrict__ ch)
{
  constexpr int PK=72, NBT=64, NB=SS/NBT, STG=5;
  extern __shared__ fp16 sm[];
  fp16* sKh = sm;                    // 5 * 64*72
  fp16* sVh = sKh + STG*64*PK;       // 5 * 64*72
  float* sInv = (float*)(sVh + STG*64*PK);

  const int tid=threadIdx.x, lane=tid&31;
  const int g=lane>>2, tg=lane&3;
  const int wm = (tid>>5)*16;
  const int m0 = blockIdx.x*128;
  const int bh = blockIdx.y;

  const int bRowF = (lane&7) + ((lane>>4)&1)*8;
  const int bColF = ((lane>>3)&1)*8;

  const fp16* qh = qh_ + (size_t)(bh*SS+m0)*DK;
  const fp16* kh = kh_ + (size_t)bh*SS*DK;
  const fp16* vh = vh_ + (size_t)bh*DK*SS;
  float* attn = attn_ + (size_t)bh*SS*SS;

  auto issueK = [&](int nb,int st){
    const int row=tid>>2, s=tid&3;
    const fp16* sh = kh + (size_t)(nb*NBT+row)*DK;
    unsigned dh = sptr(sKh + (st*64+row)*PK);
    CP16(dh+s*16, sh+s*8);  CP16(dh+(s+4)*16, sh+(s+4)*8);
  };
  auto issueKV = [&](int nb,int st){
    const int row=tid>>2, s=tid&3;
    const fp16* skh = kh + (size_t)(nb*NBT+row)*DK;
    unsigned dkh = sptr(sKh + (st*64+row)*PK);
    CP16(dkh+s*16, skh+s*8);  CP16(dkh+(s+4)*16, skh+(s+4)*8);
    const fp16* svh = vh + (size_t)row*SS + nb*NBT;
    unsigned dvh = sptr(sVh + (st*64+row)*PK);
    CP16(dvh+s*16, svh+s*8);  CP16(dvh+(s+4)*16, svh+(s+4)*8);
  };

  // Q fragments from gmem (ldmatrix-equivalent distribution)
  unsigned qfh[4][4];
#pragma unroll
  for (int kk=0;kk<4;kk++){
    const int c = kk*16 + tg*2;
    qfh[kk][0] = *(const unsigned*)(qh + (size_t)(wm+g  )*DK + c);
    qfh[kk][1] = *(const unsigned*)(qh + (size_t)(wm+g+8)*DK + c);
    qfh[kk][2] = *(const unsigned*)(qh + (size_t)(wm+g  )*DK + c+8);
    qfh[kk][3] = *(const unsigned*)(qh + (size_t)(wm+g+8)*DK + c+8);
  }

  // 1-term S (used by both sweeps)
  auto computeS = [&](int st, float sacc[8][4]){
#pragma unroll
    for (int ni=0;ni<8;ni++)
#pragma unroll
      for (int q=0;q<4;q++) sacc[ni][q]=0.f;
#pragma unroll
    for (int kk=0;kk<4;kk++){
      unsigned bh2[8][2];
#pragma unroll
      for (int np=0;np<4;np++){
        unsigned bd = sptr(sKh + ((size_t)st*64 + np*16 + bRowF)*PK + kk*16 + bColF);
        ldsm4(bh2[2*np][0],bh2[2*np][1],bh2[2*np+1][0],bh2[2*np+1][1], bd);
      }
#pragma unroll
      for (int j=0;j<8;j++) mma16(sacc[j], qfh[kk], bh2[j]);
    }
  };

  // ================= Sweep 1: row sums =================
  issueK(0,0); CPCOMMIT();
  issueK(1,1); CPCOMMIT();
  issueK(2,2); CPCOMMIT();
  issueK(3,3); CPCOMMIT();
  float rs0=0.f, rs1=0.f;
  for (int nb=0;nb<NB;nb++){
    CPWAIT(3);
    __syncthreads();
    if (nb+4 < NB){ issueK(nb+4,(nb+4)%STG); CPCOMMIT(); } else { CPCOMMIT(); }
    float sacc[8][4];
    computeS(nb%STG, sacc);
#pragma unroll
    for (int ni=0;ni<8;ni++){
      rs0 += ex2f(sacc[ni][0]) + ex2f(sacc[ni][1]);
      rs1 += ex2f(sacc[ni][2]) + ex2f(sacc[ni][3]);
    }
  }
  rs0 += __shfl_xor_sync(0xffffffffu, rs0, 1);
  rs0 += __shfl_xor_sync(0xffffffffu, rs0, 2);
  rs1 += __shfl_xor_sync(0xffffffffu, rs1, 1);
  rs1 += __shfl_xor_sync(0xffffffffu, rs1, 2);
  __syncthreads();                 // all sweep-1 smem reads done before restage
  if (tg==0){ sInv[wm+g] = 1.0f/rs0; sInv[wm+g+8] = 1.0f/rs1; }
  __syncthreads();
  const float inv0 = sInv[wm+g];
  const float inv1 = sInv[wm+g+8];

  // ================= Sweep 2: normalized attn + P@V =================
  float cacc[8][4];
#pragma unroll
  for (int ci=0;ci<8;ci++)
#pragma unroll
    for (int q=0;q<4;q++) cacc[ci][q]=0.f;

  issueKV(0,0); CPCOMMIT();
  issueKV(1,1); CPCOMMIT();
  issueKV(2,2); CPCOMMIT();
  issueKV(3,3); CPCOMMIT();
  for (int nb=0;nb<NB;nb++){
    CPWAIT(3);
    __syncthreads();
    if (nb+4 < NB){ issueKV(nb+4,(nb+4)%STG); CPCOMMIT(); } else { CPCOMMIT(); }
    const int st = nb%STG;
    float sacc[8][4];
    computeS(st, sacc);

    float* arow0 = attn + (size_t)(m0+wm+g)*SS + nb*NBT;
    float* arow1 = arow0 + 8*SS;
#pragma unroll
    for (int ni=0;ni<8;ni++){
      float e0 = ex2f(sacc[ni][0])*inv0;
      float e1 = ex2f(sacc[ni][1])*inv0;
      float e2 = ex2f(sacc[ni][2])*inv1;
      float e3 = ex2f(sacc[ni][3])*inv1;
      sacc[ni][0]=e0; sacc[ni][1]=e1; sacc[ni][2]=e2; sacc[ni][3]=e3;
      float2 lo2; lo2.x=e0; lo2.y=e1;
      float2 hi2; hi2.x=e2; hi2.y=e3;
      __stcs((float2*)(arow0 + ni*8 + tg*2), lo2);
      __stcs((float2*)(arow1 + ni*8 + tg*2), hi2);
    }

#pragma unroll
    for (int kk=0;kk<4;kk++){
      const int f0=2*kk, f1=2*kk+1;
      unsigned pah[4];
      pah[0]=pack2f(sacc[f0][0], sacc[f0][1]);
      pah[1]=pack2f(sacc[f0][2], sacc[f0][3]);
      pah[2]=pack2f(sacc[f1][0], sacc[f1][1]);
      pah[3]=pack2f(sacc[f1][2], sacc[f1][3]);
      unsigned vf[8][2];
#pragma unroll
      for (int cp=0;cp<4;cp++){
        unsigned vd = sptr(sVh + ((size_t)st*64 + cp*16 + bRowF)*PK + kk*16 + bColF);
        ldsm4(vf[2*cp][0],vf[2*cp][1],vf[2*cp+1][0],vf[2*cp+1][1], vd);
      }
#pragma unroll
      for (int j=0;j<8;j++) mma16(cacc[j], pah, vf[j]);
    }
  }

  const int b = bh>>4, h = bh&(NH-1);
#pragma unroll
  for (int ci=0;ci<8;ci++){
    const int d = h*DK + ci*8 + tg*2;
    const size_t o0 = ((size_t)(b*SS + m0+wm+g))*DM + d;
    const size_t o1 = o0 + (size_t)8*DM;
    *(unsigned*)(ch+o0) = pack2f(cacc[ci][0], cacc[ci][1]);
    *(unsigned*)(ch+o1) = pack2f(cacc[ci][2], cacc[ci][3]);
  }
}

extern "C" void kernel_launch(void* const* d_in, const int* in_sizes, int n_in,
                              void* d_out, int out_size){
  const float* Q   = (const float*)d_in[0];
  const float* K   = (const float*)d_in[1];
  const float* V   = (const float*)d_in[2];
  const float* Wq  = (const float*)d_in[3];
  const float* bq  = (const float*)d_in[4];
  const float* Wk  = (const float*)d_in[5];
  const float* bk  = (const float*)d_in[6];
  const float* Wv  = (const float*)d_in[7];
  const float* bv  = (const float*)d_in[8];
  const float* Wfc = (const float*)d_in[9];
  const float* bfc = (const float*)d_in[10];
  float* out_f = (float*)d_out;

  fp16 *Xh,*Wth,*qh,*kh,*vh,*ch;
  float *bias3,*afb;
  cudaGetSymbolAddress((void**)&Xh, g_Xh);
  cudaGetSymbolAddress((void**)&Wth, g_Wth);
  cudaGetSymbolAddress((void**)&qh, g_qh);
  cudaGetSymbolAddress((void**)&kh, g_kh);   cudaGetSymbolAddress((void**)&vh, g_vh);
  cudaGetSymbolAddress((void**)&ch, g_ch);
  cudaGetSymbolAddress((void**)&bias3, g_bias3);
  cudaGetSymbolAddress((void**)&afb,  g_attn_fb);

  const size_t ATTN = (size_t)HEADS*SS*SS;
  float* attn = ((size_t)out_size >= ATTN) ? (out_f + ((size_t)out_size - ATTN)) : afb;

  const int SM_GEMMW = 3*2*128*40*2;                 // 61440
  const int SM_FUSED = 2*5*64*72*2 + 512;            // 92672 (5-stage K + 5-stage V)

  cudaFuncSetAttribute(gemmW<0>, cudaFuncAttributeMaxDynamicSharedMemorySize, SM_GEMMW);
  cudaFuncSetAttribute(gemmW<3>, cudaFuncAttributeMaxDynamicSharedMemorySize, SM_GEMMW);
  cudaFuncSetAttribute(fused_attn, cudaFuncAttributeMaxDynamicSharedMemorySize, SM_FUSED);

  dim3 blk(256);

  cudaMemcpyAsync(bias3,        bq, DM*sizeof(float), cudaMemcpyDeviceToDevice);
  cudaMemcpyAsync(bias3 + DM,   bk, DM*sizeof(float), cudaMemcpyDeviceToDevice);
  cudaMemcpyAsync(bias3 + 2*DM, bv, DM*sizeof(float), cudaMemcpyDeviceToDevice);

  cvtX<<<dim3(NXE/4/256,1,3), blk>>>(Q,K,V, Xh);
  cvtWt<<<dim3(32,32,4), dim3(32,8)>>>(Wq,Wk,Wv,Wfc, Wth);

  // Q/K/V projections (z: 0=q pre-scaled, 1=k head-split, 2=v transposed)
  gemmW<0><<<dim3(8,32,3), blk, SM_GEMMW>>>(
      Xh, Wth, bias3, nullptr, qh, kh, vh);

  fused_attn<<<dim3(SS/128, HEADS), blk, SM_FUSED>>>(
      qh, kh, vh, attn, ch);

  // output projection: ctx @ Wfc
  gemmW<3><<<dim3(8,32), blk, SM_GEMMW>>>(
      ch, Wth + 3*(size_t)NWE, bfc, out_f, nullptr, nullptr, nullptr);
}